// round 1
// baseline (speedup 1.0000x reference)
#include <cuda_runtime.h>
#include <cuda_bf16.h>
#include <math.h>

#define BDIM   32
#define TIN    1000
#define TA     400
#define FDIM   256
#define HDIM   256
#define FRAME  320
#define SHIFT  160
#define LSIG   160000
#define LAUX   64000
#define NCLS   101

// ---------------- scratch (static device globals; no allocation) ----------------
__device__ float g_out   [BDIM * TIN * FDIM];
__device__ float g_out2  [BDIM * TIN * FDIM];
__device__ float g_aux   [BDIM * TA  * FDIM];
__device__ float g_h     [BDIM * TA  * HDIM];
__device__ float g_a     [BDIM * TA  * HDIM];
__device__ float g_logits[BDIM * TA  * HDIM];
__device__ float g_y     [BDIM * TIN * FRAME];
__device__ float g_mean  [BDIM];
__device__ float g_inv   [BDIM];
__device__ float g_mt    [BDIM * HDIM];
__device__ float g_st    [BDIM * HDIM];
__device__ float g_bias2 [BDIM * HDIM];
__device__ float g_pool  [BDIM * 2 * HDIM];
__device__ float g_emb   [BDIM * FDIM];
__device__ float g_evec  [4 * BDIM * FDIM];

// ---------------- generic 64x64 tiled fp32 GEMM ----------------
// MODE 0: A = gathered frames from raw signal (L = signal len). epi: + e0[col]
// MODE 1: A = GLN-transform(g_aux) masked by aux_len. epi: relu(+e2[col]) masked
// MODE 2: A plain. epi: a=relu(acc + g_bias2[b,col]); tanh(a*e0[col]+e1[col])
// MODE 3: A plain. epi: + e0[col]
// MODE 4: A plain. epi: C = A[t,col] + tanh(acc + g_evec[i,b,col] + e0[col])
template<int MODE>
__global__ __launch_bounds__(256) void k_gemm(
    const float* __restrict__ A, const float* __restrict__ W, float* __restrict__ C,
    const float* __restrict__ e0, const float* __restrict__ e1, const float* __restrict__ e2,
    const int* __restrict__ aux_len, int M, int K, int N, int L, int arn_i)
{
    __shared__ float As[16][64];
    __shared__ float Bs[16][64];
    const int b  = blockIdx.z;
    const int t0 = blockIdx.y * 64;
    const int n0 = blockIdx.x * 64;
    const int tid = threadIdx.x;
    const int ty = tid >> 4, tx = tid & 15;
    const int ar = tid >> 2, akq = (tid & 3) * 4;

    int   len  = 0;
    float mean = 0.f, inv = 0.f;
    if (MODE == 1) { len = aux_len[b]; mean = g_mean[b]; inv = g_inv[b]; }

    const float* Ab = (MODE == 0) ? (A + (size_t)b * L)
                                  : (A + (size_t)b * M * K);
    float acc[4][4];
    #pragma unroll
    for (int i = 0; i < 4; i++)
        #pragma unroll
        for (int j = 0; j < 4; j++) acc[i][j] = 0.f;

    for (int k0 = 0; k0 < K; k0 += 16) {
        // ---- load A tile (transposed into As[k][row]) ----
        const int t = t0 + ar;
        float4 av = make_float4(0.f, 0.f, 0.f, 0.f);
        if (MODE == 0) {
            if (t < M) {
                const int base = t * SHIFT + k0 + akq;
                if (base + 3 < L) {
                    av = *(const float4*)(Ab + base);
                } else {
                    av.x = (base     < L) ? Ab[base]     : 0.f;
                    av.y = (base + 1 < L) ? Ab[base + 1] : 0.f;
                    av.z = (base + 2 < L) ? Ab[base + 2] : 0.f;
                    av.w = (base + 3 < L) ? Ab[base + 3] : 0.f;
                }
            }
        } else if (MODE == 1) {
            if (t < len) {
                float4 x  = *(const float4*)(Ab + (size_t)t * K + k0 + akq);
                float4 gg = *(const float4*)(e0 + k0 + akq);
                float4 gb = *(const float4*)(e1 + k0 + akq);
                av.x = gg.x * inv * (x.x - mean) + gb.x;
                av.y = gg.y * inv * (x.y - mean) + gb.y;
                av.z = gg.z * inv * (x.z - mean) + gb.z;
                av.w = gg.w * inv * (x.w - mean) + gb.w;
            }
        } else {
            if (t < M) av = *(const float4*)(Ab + (size_t)t * K + k0 + akq);
        }
        As[akq + 0][ar] = av.x;
        As[akq + 1][ar] = av.y;
        As[akq + 2][ar] = av.z;
        As[akq + 3][ar] = av.w;

        // ---- load B tile ----
        {
            const int kk = tid >> 4, c4 = (tid & 15) * 4;
            *(float4*)&Bs[kk][c4] = *(const float4*)(W + (size_t)(k0 + kk) * N + n0 + c4);
        }
        __syncthreads();

        // ---- MMA ----
        #pragma unroll
        for (int kk = 0; kk < 16; kk++) {
            float4 a4 = *(const float4*)&As[kk][ty * 4];
            float4 b4 = *(const float4*)&Bs[kk][tx * 4];
            float ax[4] = {a4.x, a4.y, a4.z, a4.w};
            float bx[4] = {b4.x, b4.y, b4.z, b4.w};
            #pragma unroll
            for (int i = 0; i < 4; i++)
                #pragma unroll
                for (int j = 0; j < 4; j++)
                    acc[i][j] += ax[i] * bx[j];
        }
        __syncthreads();
    }

    // ---- epilogue ----
    #pragma unroll
    for (int i = 0; i < 4; i++) {
        const int t = t0 + ty * 4 + i;
        if (t >= M) continue;
        float* cp = C + ((size_t)b * M + t) * N + n0 + tx * 4;
        float4 r;
        float rr[4];
        #pragma unroll
        for (int j = 0; j < 4; j++) {
            const int col = n0 + tx * 4 + j;
            float v = acc[i][j];
            if (MODE == 0) {
                rr[j] = v + e0[col];
            } else if (MODE == 1) {
                rr[j] = (t < len) ? fmaxf(v + e2[col], 0.f) : 0.f;
            } else if (MODE == 2) {
                float a = fmaxf(v + g_bias2[b * HDIM + col], 0.f);
                rr[j] = tanhf(a * e0[col] + e1[col]);
            } else if (MODE == 3) {
                rr[j] = v + e0[col];
            } else { // MODE 4
                rr[j] = Ab[(size_t)t * K + col] +
                        tanhf(v + g_evec[((size_t)arn_i * BDIM + b) * FDIM + col] + e0[col]);
            }
        }
        r.x = rr[0]; r.y = rr[1]; r.z = rr[2]; r.w = rr[3];
        *(float4*)cp = r;
    }
}

// ---------------- GLN reduction: per-sample mean / inv-std over valid frames ----------------
__global__ __launch_bounds__(256) void k_gln_reduce(const int* __restrict__ aux_len)
{
    const int b = blockIdx.x;
    const int len = aux_len[b];
    const int n = len * FDIM;
    const float* p = g_aux + (size_t)b * TA * FDIM;
    double s = 0.0, q = 0.0;
    for (int i = threadIdx.x; i < n; i += blockDim.x) {
        float v = p[i];
        s += (double)v;
        q += (double)v * (double)v;
    }
    __shared__ double ss[256], qq[256];
    ss[threadIdx.x] = s; qq[threadIdx.x] = q;
    __syncthreads();
    for (int st = 128; st > 0; st >>= 1) {
        if (threadIdx.x < st) {
            ss[threadIdx.x] += ss[threadIdx.x + st];
            qq[threadIdx.x] += qq[threadIdx.x + st];
        }
        __syncthreads();
    }
    if (threadIdx.x == 0) {
        double m   = ss[0] / (double)n;
        double var = qq[0] / (double)n - m * m;
        g_mean[b] = (float)m;
        g_inv[b]  = (float)(1.0 / sqrt(var + 1e-5));
    }
}

// ---------------- per-sample per-channel h statistics (mean / unbiased std) ----------------
__global__ __launch_bounds__(256) void k_hstats(const int* __restrict__ aux_len)
{
    const int b = blockIdx.x, ch = threadIdx.x;
    const int len = aux_len[b];
    const float* p = g_h + (size_t)b * TA * HDIM + ch;
    float s = 0.f, q = 0.f;
    for (int t = 0; t < len; t++) {
        float v = p[(size_t)t * HDIM];
        s += v; q += v * v;
    }
    const float n = (float)len;
    const float m = s / n;
    const float var = (q - n * m * m) / (n - 1.f);
    g_mt[b * HDIM + ch] = m;
    g_st[b * HDIM + ch] = sqrtf(fmaxf(var, 1e-4f));
}

// ---------------- bias2[b,j] = att_b1[j] + m.W1[256:512] + s.W1[512:768] ----------------
__global__ __launch_bounds__(256) void k_bias2(const float* __restrict__ att_w1,
                                               const float* __restrict__ att_b1)
{
    const int b = blockIdx.x, j = threadIdx.x;
    float acc = att_b1[j];
    for (int k = 0; k < HDIM; k++) {
        acc += g_mt[b * HDIM + k] * att_w1[(size_t)(256 + k) * HDIM + j]
             + g_st[b * HDIM + k] * att_w1[(size_t)(512 + k) * HDIM + j];
    }
    g_bias2[b * HDIM + j] = acc;
}

// ---------------- masked softmax over time + attentive pooling + bn5 affine ----------------
__global__ __launch_bounds__(256) void k_softpool(const int* __restrict__ aux_len,
                                                  const float* __restrict__ bn5g,
                                                  const float* __restrict__ bn5b)
{
    const int b = blockIdx.x, ch = threadIdx.x;
    const int len = aux_len[b];
    const float* lp = g_logits + (size_t)b * TA * HDIM + ch;
    const float* hp = g_h      + (size_t)b * TA * HDIM + ch;
    float mx = -1e30f;
    for (int t = 0; t < len; t++) mx = fmaxf(mx, lp[(size_t)t * HDIM]);
    float se = 0.f, s1 = 0.f, s2 = 0.f;
    for (int t = 0; t < len; t++) {
        float e  = expf(lp[(size_t)t * HDIM] - mx);
        float hv = hp[(size_t)t * HDIM];
        se += e; s1 += hv * e; s2 += hv * hv * e;
    }
    float mu = s1 / se;
    float sg = sqrtf(fmaxf(s2 / se - mu * mu, 1e-4f));
    g_pool[b * 2 * HDIM + ch]        = mu * bn5g[ch]        + bn5b[ch];
    g_pool[b * 2 * HDIM + HDIM + ch] = sg * bn5g[HDIM + ch] + bn5b[HDIM + ch];
}

// ---------------- fc6 -> bn6 -> emb ; normalize -> classifier ----------------
__global__ __launch_bounds__(256) void k_emb(const float* __restrict__ fc6_w,
                                             const float* __restrict__ fc6_b,
                                             const float* __restrict__ bn6g,
                                             const float* __restrict__ bn6b,
                                             const float* __restrict__ cls_w,
                                             const float* __restrict__ cls_b,
                                             float* __restrict__ out_cls, int write_cls)
{
    const int b = blockIdx.x, j = threadIdx.x;
    __shared__ float e[2 * HDIM];
    e[j]        = g_pool[b * 2 * HDIM + j];
    e[j + HDIM] = g_pool[b * 2 * HDIM + HDIM + j];
    __syncthreads();
    float acc = fc6_b[j];
    for (int k = 0; k < 2 * HDIM; k++) acc += e[k] * fc6_w[(size_t)k * FDIM + j];
    const float em = acc * bn6g[j] + bn6b[j];
    g_emb[b * FDIM + j] = em;

    __shared__ float red[256];
    red[j] = em * em;
    __syncthreads();
    for (int st = 128; st > 0; st >>= 1) {
        if (j < st) red[j] += red[j + st];
        __syncthreads();
    }
    const float nrmv = fmaxf(sqrtf(red[0]), 1e-12f);
    __shared__ float ne[256];
    ne[j] = em / nrmv;
    __syncthreads();
    if (write_cls && j < NCLS) {
        float c = cls_b[j];
        for (int k = 0; k < FDIM; k++) c += ne[k] * cls_w[(size_t)k * NCLS + j];
        out_cls[b * NCLS + j] = c;
    }
}

// ---------------- evec[i,b,:] = emb[b] @ arn_w2[i] ----------------
__global__ __launch_bounds__(256) void k_evec(const float* __restrict__ arn_w2)
{
    const int b = blockIdx.x, i = blockIdx.y, j = threadIdx.x;
    const float* W = arn_w2 + (size_t)i * FDIM * FDIM;
    float acc = 0.f;
    for (int k = 0; k < FDIM; k++) acc += g_emb[b * FDIM + k] * W[(size_t)k * FDIM + j];
    g_evec[((size_t)i * BDIM + b) * FDIM + j] = acc;
}

// ---------------- overlap-add (FRAME = 2*SHIFT -> exactly 2 taps, den = 1 or 2) ----------------
__global__ __launch_bounds__(256) void k_ola(float* __restrict__ out)
{
    const int idx = blockIdx.x * blockDim.x + threadIdx.x;
    if (idx >= BDIM * LSIG) return;
    const int b = idx / LSIG;
    const int i = idx - b * LSIG;
    const int t = i / SHIFT;
    const int j = i - t * SHIFT;
    const float* yb = g_y + (size_t)b * TIN * FRAME;
    float v = yb[(size_t)t * FRAME + j];
    if (t > 0) {
        v += yb[(size_t)(t - 1) * FRAME + j + SHIFT];
        v *= 0.5f;
    }
    out[idx] = v;
}

// ---------------- launch ----------------
extern "C" void kernel_launch(void* const* d_in, const int* in_sizes, int n_in,
                              void* d_out, int out_size)
{
    const float* input   = (const float*)d_in[0];
    const float* anchor  = (const float*)d_in[1];
    const int*   aux_len = (const int*)  d_in[2];
    /* d_in[3] = input_len : unused by the reference forward */
    const float* in_w    = (const float*)d_in[4];
    const float* in_b    = (const float*)d_in[5];
    const float* out_w   = (const float*)d_in[6];
    const float* out_b   = (const float*)d_in[7];
    const float* gln_g   = (const float*)d_in[8];
    const float* gln_b   = (const float*)d_in[9];
    const float* ecapa_w = (const float*)d_in[10];
    const float* ecapa_b = (const float*)d_in[11];
    const float* att_w1  = (const float*)d_in[12];
    const float* att_b1  = (const float*)d_in[13];
    const float* attbn_g = (const float*)d_in[14];
    const float* attbn_b = (const float*)d_in[15];
    const float* att_w2  = (const float*)d_in[16];
    const float* att_b2  = (const float*)d_in[17];
    const float* bn5_g   = (const float*)d_in[18];
    const float* bn5_b   = (const float*)d_in[19];
    const float* fc6_w   = (const float*)d_in[20];
    const float* fc6_b   = (const float*)d_in[21];
    const float* bn6_g   = (const float*)d_in[22];
    const float* bn6_b   = (const float*)d_in[23];
    const float* cls_w   = (const float*)d_in[24];
    const float* cls_b   = (const float*)d_in[25];
    const float* arn_w1  = (const float*)d_in[26];
    const float* arn_w2  = (const float*)d_in[27];
    const float* arn_b   = (const float*)d_in[28];

    float *p_out, *p_out2, *p_aux, *p_h, *p_a, *p_logits, *p_y;
    cudaGetSymbolAddress((void**)&p_out,    g_out);
    cudaGetSymbolAddress((void**)&p_out2,   g_out2);
    cudaGetSymbolAddress((void**)&p_aux,    g_aux);
    cudaGetSymbolAddress((void**)&p_h,      g_h);
    cudaGetSymbolAddress((void**)&p_a,      g_a);
    cudaGetSymbolAddress((void**)&p_logits, g_logits);
    cudaGetSymbolAddress((void**)&p_y,      g_y);

    const dim3 blk(256);

    // 1. encoder on input frames -> g_out  [B, 1000, 256]
    k_gemm<0><<<dim3(4, 16, 32), blk>>>(input, in_w, p_out, in_b, nullptr, nullptr,
                                        nullptr, TIN, FRAME, FDIM, LSIG, 0);
    // 2. encoder on anchor frames -> g_aux [B, 400, 256]
    k_gemm<0><<<dim3(4, 7, 32), blk>>>(anchor, in_w, p_aux, in_b, nullptr, nullptr,
                                       nullptr, TA, FRAME, FDIM, LAUX, 0);
    // 3. GLN stats
    k_gln_reduce<<<32, 256>>>(aux_len);
    // 4. GLN-normalized aux @ ecapa_w -> relu -> mask -> g_h
    k_gemm<1><<<dim3(4, 7, 32), blk>>>(p_aux, ecapa_w, p_h, gln_g, gln_b, ecapa_b,
                                       aux_len, TA, FDIM, HDIM, 0, 0);
    // 5. h time statistics (mean / unbiased std)
    k_hstats<<<32, 256>>>(aux_len);
    // 6. time-constant part of attention conv1
    k_bias2<<<32, 256>>>(att_w1, att_b1);
    // 7. attention conv1 (h part) + relu + bn + tanh -> g_a
    k_gemm<2><<<dim3(4, 7, 32), blk>>>(p_h, att_w1, p_a, attbn_g, attbn_b, nullptr,
                                       nullptr, TA, HDIM, HDIM, 0, 0);
    // 8. attention conv2 -> logits
    k_gemm<3><<<dim3(4, 7, 32), blk>>>(p_a, att_w2, p_logits, att_b2, nullptr, nullptr,
                                       nullptr, TA, HDIM, HDIM, 0, 0);
    // 9. masked softmax + attentive pooling + bn5 affine
    k_softpool<<<32, 256>>>(aux_len, bn5_g, bn5_b);
    // 10. fc6/bn6/emb + classifier head
    const int write_cls = (out_size >= BDIM * LSIG + BDIM * NCLS) ? 1 : 0;
    k_emb<<<32, 256>>>(fc6_w, fc6_b, bn6_g, bn6_b, cls_w, cls_b,
                       (float*)d_out + (size_t)BDIM * LSIG, write_cls);
    // 11. per-block speaker-embedding projections
    k_evec<<<dim3(32, 4), 256>>>(arn_w2);
    // 12. 4 ARN residual blocks (ping-pong)
    const float* src = p_out;
    float*       dst = p_out2;
    for (int i = 0; i < 4; i++) {
        k_gemm<4><<<dim3(4, 16, 32), blk>>>(src, arn_w1 + (size_t)i * FDIM * FDIM, dst,
                                            arn_b + i * FDIM, nullptr, nullptr,
                                            nullptr, TIN, FDIM, FDIM, 0, i);
        const float* tmp = dst;
        dst = (float*)src;
        src = tmp;
    }
    // after 4 swaps the latest result lives in g_out (src)
    // 13. decoder -> g_y [B, 1000, 320]
    k_gemm<3><<<dim3(5, 16, 32), blk>>>(src, out_w, p_y, out_b, nullptr, nullptr,
                                        nullptr, TIN, FDIM, FRAME, 0, 0);
    // 14. overlap-add -> d_out
    k_ola<<<(BDIM * LSIG + 255) / 256, 256>>>((float*)d_out);
}

// round 3
// speedup vs baseline: 1.3913x; 1.3913x over previous
#include <cuda_runtime.h>
#include <cuda_bf16.h>
#include <math.h>
#include <stdint.h>

#define BDIM   32
#define TIN    1000
#define TA     400
#define FDIM   256
#define HDIM   256
#define FRAME  320
#define SHIFT  160
#define LSIG   160000
#define LAUX   64000
#define NCLS   101

// ---------------- scratch (static device globals; no allocation) ----------------
__device__ float g_out   [BDIM * TIN * FDIM];
__device__ float g_out2  [BDIM * TIN * FDIM];
__device__ float g_aux   [BDIM * TA  * FDIM];
__device__ float g_h     [BDIM * TA  * HDIM];
__device__ float g_a     [BDIM * TA  * HDIM];
__device__ float g_logits[BDIM * TA  * HDIM];
__device__ float g_y     [BDIM * TIN * FRAME];
__device__ float g_mean  [BDIM];
__device__ float g_inv   [BDIM];
__device__ float g_mt    [BDIM * HDIM];
__device__ float g_st    [BDIM * HDIM];
__device__ float g_bias2 [BDIM * HDIM];
__device__ float g_pool  [BDIM * 2 * HDIM];
__device__ float g_emb   [BDIM * FDIM];
__device__ float g_evec  [4 * BDIM * FDIM];

// bf16 split weight planes, layout [N][K] (K contiguous)
__device__ __nv_bfloat16 w_in_hi [256 * 320];
__device__ __nv_bfloat16 w_in_lo [256 * 320];
__device__ __nv_bfloat16 w_ec_hi [256 * 256];
__device__ __nv_bfloat16 w_ec_lo [256 * 256];
__device__ __nv_bfloat16 w_a1_hi [256 * 256];
__device__ __nv_bfloat16 w_a1_lo [256 * 256];
__device__ __nv_bfloat16 w_a2_hi [256 * 256];
__device__ __nv_bfloat16 w_a2_lo [256 * 256];
__device__ __nv_bfloat16 w_arn_hi[4 * 256 * 256];
__device__ __nv_bfloat16 w_arn_lo[4 * 256 * 256];
__device__ __nv_bfloat16 w_out_hi[320 * 256];
__device__ __nv_bfloat16 w_out_lo[320 * 256];

// ---------------- helpers ----------------
__device__ __forceinline__ uint32_t smem_u32(const void* p) {
    uint32_t a;
    asm("{ .reg .u64 t; cvta.to.shared.u64 t, %1; cvt.u32.u64 %0, t; }" : "=r"(a) : "l"(p));
    return a;
}
__device__ __forceinline__ void ldmx4(uint32_t* r, uint32_t addr) {
    asm volatile("ldmatrix.sync.aligned.m8n8.x4.shared.b16 {%0,%1,%2,%3}, [%4];"
                 : "=r"(r[0]), "=r"(r[1]), "=r"(r[2]), "=r"(r[3]) : "r"(addr));
}
__device__ __forceinline__ void ldmx2(uint32_t* r, uint32_t addr) {
    asm volatile("ldmatrix.sync.aligned.m8n8.x2.shared.b16 {%0,%1}, [%2];"
                 : "=r"(r[0]), "=r"(r[1]) : "r"(addr));
}
__device__ __forceinline__ void mma_bf16(float* c, const uint32_t* a, const uint32_t* b) {
    asm volatile("mma.sync.aligned.m16n8k16.row.col.f32.bf16.bf16.f32 "
                 "{%0,%1,%2,%3}, {%4,%5,%6,%7}, {%8,%9}, {%0,%1,%2,%3};"
                 : "+f"(c[0]), "+f"(c[1]), "+f"(c[2]), "+f"(c[3])
                 : "r"(a[0]), "r"(a[1]), "r"(a[2]), "r"(a[3]), "r"(b[0]), "r"(b[1]));
}

// ---------------- weight split/transpose prep: W[k][n] fp32 -> [n][k] bf16 hi/lo ----------------
__global__ __launch_bounds__(256) void k_prep_w(const float* __restrict__ W, int K, int N,
                                                __nv_bfloat16* __restrict__ hi,
                                                __nv_bfloat16* __restrict__ lo)
{
    int i = blockIdx.x * blockDim.x + threadIdx.x;
    if (i >= K * N) return;
    int n = i / K, k = i - n * K;
    float x = W[(size_t)k * N + n];
    __nv_bfloat16 h = __float2bfloat16(x);
    hi[i] = h;
    lo[i] = __float2bfloat16(x - __bfloat162float(h));
}

// ---------------- tensor-core GEMM (mma.sync bf16, 3-term split) ----------------
// CTA: 256 threads = 8 warps. Tile: 64 rows x N cols. Warp w owns cols [w*N/8, (w+1)*N/8).
// K staged 64 at a time into padded SMEM (stride 72 bf16 per row, conflict-free ldmatrix).
// MODE 0: A = framed signal (row t -> signal[t*SHIFT+k], bound L). epi: + e0[col]
// MODE 1: A = GLN(g_aux) masked by aux_len. epi: relu(acc + e2[col]) masked
// MODE 2: A plain. epi: a = relu(acc + g_bias2[b,col]); tanh(a*e0[col]+e1[col])
// MODE 3: A plain. epi: + e0[col]
// MODE 4: A plain. epi: C = A[t,col] + tanh(acc + g_evec[arn_i,b,col] + e0[col])
template<int N, int MODE>
__global__ void __launch_bounds__(256, 2) k_tgemm(
    const float* __restrict__ A,
    const __nv_bfloat16* __restrict__ Bhi, const __nv_bfloat16* __restrict__ Blo,
    float* __restrict__ C,
    const float* __restrict__ e0, const float* __restrict__ e1, const float* __restrict__ e2,
    const int* __restrict__ aux_len, int M, int K, int L, int arn_i)
{
    constexpr int WN   = N / 8;      // cols per warp (32 or 40)
    constexpr int NF   = WN / 8;     // 8-wide n-frags per warp (4 or 5)
    constexpr int KS   = 72;         // padded smem row stride (bf16 elems)
    constexpr int ASZ  = 64 * KS * 2;            // bytes per A plane
    constexpr int BSZ  = N  * KS * 2;            // bytes per B plane

    extern __shared__ char smem[];
    const uint32_t sb  = smem_u32(smem);
    const uint32_t aHi = sb;
    const uint32_t aLo = sb + ASZ;
    const uint32_t bHi = sb + 2 * ASZ;
    const uint32_t bLo = sb + 2 * ASZ + BSZ;

    const int tid  = threadIdx.x;
    const int w    = tid >> 5;
    const int lane = tid & 31;
    const int b    = blockIdx.y;
    const int t0   = blockIdx.x * 64;
    const int NB   = K / 64;
    const int wn0  = w * WN;

    int   len  = 0;
    float mean = 0.f, inv = 0.f;
    if (MODE == 1) { len = aux_len[b]; mean = g_mean[b]; inv = g_inv[b]; }

    // A-load mapping: 4 threads per row, 16 fp32 cols each
    const int arow = tid >> 2;
    const int ac0  = (tid & 3) * 16;

    float acc[4][NF][4];
    #pragma unroll
    for (int mi = 0; mi < 4; mi++)
        #pragma unroll
        for (int nj = 0; nj < NF; nj++)
            #pragma unroll
            for (int q = 0; q < 4; q++) acc[mi][nj][q] = 0.f;

    for (int kb = 0; kb < NB; kb++) {
        // ---- stage A tile: 64 rows x 64 fp32 -> bf16 hi/lo (padded rows) ----
        {
            const int t = t0 + arow;
            float va[16];
            if (MODE == 0) {
                if (t < M) {
                    const float* src = A + (size_t)b * L;
                    const int base = t * SHIFT + kb * 64 + ac0;
                    #pragma unroll
                    for (int q = 0; q < 4; q++) {
                        const int p = base + q * 4;
                        if (p + 3 < L) {
                            float4 f = *(const float4*)(src + p);
                            va[q*4+0]=f.x; va[q*4+1]=f.y; va[q*4+2]=f.z; va[q*4+3]=f.w;
                        } else {
                            #pragma unroll
                            for (int j = 0; j < 4; j++) va[q*4+j] = (p + j < L) ? src[p + j] : 0.f;
                        }
                    }
                } else {
                    #pragma unroll
                    for (int j = 0; j < 16; j++) va[j] = 0.f;
                }
            } else {
                const bool valid = (MODE == 1) ? (t < len) : (t < M);
                if (valid) {
                    const float* src = A + ((size_t)b * M + t) * K + kb * 64 + ac0;
                    #pragma unroll
                    for (int q = 0; q < 4; q++) {
                        float4 f = *(const float4*)(src + q * 4);
                        va[q*4+0]=f.x; va[q*4+1]=f.y; va[q*4+2]=f.z; va[q*4+3]=f.w;
                    }
                    if (MODE == 1) {
                        const int c0 = kb * 64 + ac0;
                        #pragma unroll
                        for (int q = 0; q < 4; q++) {
                            float4 gg = *(const float4*)(e0 + c0 + q * 4);
                            float4 gb = *(const float4*)(e1 + c0 + q * 4);
                            va[q*4+0] = gg.x * inv * (va[q*4+0] - mean) + gb.x;
                            va[q*4+1] = gg.y * inv * (va[q*4+1] - mean) + gb.y;
                            va[q*4+2] = gg.z * inv * (va[q*4+2] - mean) + gb.z;
                            va[q*4+3] = gg.w * inv * (va[q*4+3] - mean) + gb.w;
                        }
                    }
                } else {
                    #pragma unroll
                    for (int j = 0; j < 16; j++) va[j] = 0.f;
                }
            }
            union { __nv_bfloat16 x[8]; uint4 v; } H0, H1, L0, L1;
            #pragma unroll
            for (int j = 0; j < 8; j++) {
                __nv_bfloat16 h0 = __float2bfloat16(va[j]);
                __nv_bfloat16 h1 = __float2bfloat16(va[j + 8]);
                H0.x[j] = h0; L0.x[j] = __float2bfloat16(va[j]     - __bfloat162float(h0));
                H1.x[j] = h1; L1.x[j] = __float2bfloat16(va[j + 8] - __bfloat162float(h1));
            }
            const uint32_t bo = (uint32_t)(arow * KS + ac0) * 2;
            *(uint4*)(smem + (aHi - sb) + bo)      = H0.v;
            *(uint4*)(smem + (aHi - sb) + bo + 16) = H1.v;
            *(uint4*)(smem + (aLo - sb) + bo)      = L0.v;
            *(uint4*)(smem + (aLo - sb) + bo + 16) = L1.v;
        }
        // ---- stage B tile: N rows x 64 bf16 (hi/lo) ----
        for (int n = tid; n < N; n += 256) {
            const __nv_bfloat16* sh = Bhi + (size_t)n * K + kb * 64;
            const __nv_bfloat16* sl = Blo + (size_t)n * K + kb * 64;
            char* dh = smem + (bHi - sb) + (size_t)n * KS * 2;
            char* dl = smem + (bLo - sb) + (size_t)n * KS * 2;
            #pragma unroll
            for (int j = 0; j < 4; j++) {
                *(uint4*)(dh + j * 16) = *(const uint4*)(sh + j * 8);
                *(uint4*)(dl + j * 16) = *(const uint4*)(sl + j * 8);
            }
            #pragma unroll
            for (int j = 4; j < 8; j++) {
                *(uint4*)(dh + j * 16) = *(const uint4*)(sh + j * 8);
                *(uint4*)(dl + j * 16) = *(const uint4*)(sl + j * 8);
            }
        }
        __syncthreads();

        // ---- compute: 4 k-frags of 16 ----
        #pragma unroll
        for (int ki = 0; ki < 4; ki++) {
            // B fragments for this warp's WN cols
            uint32_t bh[NF][2], bl[NF][2];
            const int brow = wn0 + (lane & 7);
            const int bcol = ki * 16 + (((lane & 15) >> 3) << 3);
            #pragma unroll
            for (int nj = 0; nj < NF; nj++) {
                const uint32_t ba = ((uint32_t)((brow + nj * 8) * KS + bcol)) * 2;
                ldmx2(bh[nj], bHi + ba);
                ldmx2(bl[nj], bLo + ba);
            }
            const int am = lane & 15;
            const int acol = ki * 16 + ((lane >> 4) << 3);
            #pragma unroll
            for (int mi = 0; mi < 4; mi++) {
                uint32_t ah[4], al[4];
                const uint32_t aa = ((uint32_t)((mi * 16 + am) * KS + acol)) * 2;
                ldmx4(ah, aHi + aa);
                ldmx4(al, aLo + aa);
                #pragma unroll
                for (int nj = 0; nj < NF; nj++) {
                    mma_bf16(acc[mi][nj], ah, bh[nj]);
                    mma_bf16(acc[mi][nj], ah, bl[nj]);
                    mma_bf16(acc[mi][nj], al, bh[nj]);
                }
            }
        }
        __syncthreads();
    }

    // ---- epilogue ----
    #pragma unroll
    for (int mi = 0; mi < 4; mi++) {
        #pragma unroll
        for (int half = 0; half < 2; half++) {
            const int r = mi * 16 + (lane >> 2) + half * 8;
            const int t = t0 + r;
            if (t >= M) continue;
            #pragma unroll
            for (int nj = 0; nj < NF; nj++) {
                const int col = wn0 + nj * 8 + (lane & 3) * 2;
                float v0 = acc[mi][nj][half * 2 + 0];
                float v1 = acc[mi][nj][half * 2 + 1];
                float r0, r1;
                if (MODE == 0) {
                    r0 = v0 + e0[col]; r1 = v1 + e0[col + 1];
                } else if (MODE == 1) {
                    if (t < len) { r0 = fmaxf(v0 + e2[col], 0.f); r1 = fmaxf(v1 + e2[col + 1], 0.f); }
                    else         { r0 = 0.f; r1 = 0.f; }
                } else if (MODE == 2) {
                    float a0 = fmaxf(v0 + g_bias2[b * HDIM + col],     0.f);
                    float a1 = fmaxf(v1 + g_bias2[b * HDIM + col + 1], 0.f);
                    r0 = tanhf(a0 * e0[col]     + e1[col]);
                    r1 = tanhf(a1 * e0[col + 1] + e1[col + 1]);
                } else if (MODE == 3) {
                    r0 = v0 + e0[col]; r1 = v1 + e0[col + 1];
                } else {
                    const float* ares = A + ((size_t)b * M + t) * K + col;
                    const float* ev = g_evec + ((size_t)arn_i * BDIM + b) * FDIM + col;
                    r0 = ares[0] + tanhf(v0 + ev[0] + e0[col]);
                    r1 = ares[1] + tanhf(v1 + ev[1] + e0[col + 1]);
                }
                *(float2*)(C + ((size_t)b * M + t) * N + col) = make_float2(r0, r1);
            }
        }
    }
}

// ---------------- GLN reduction ----------------
__global__ __launch_bounds__(256) void k_gln_reduce(const int* __restrict__ aux_len)
{
    const int b = blockIdx.x;
    const int len = aux_len[b];
    const int n = len * FDIM;
    const float* p = g_aux + (size_t)b * TA * FDIM;
    double s = 0.0, q = 0.0;
    for (int i = threadIdx.x; i < n; i += blockDim.x) {
        float v = p[i];
        s += (double)v; q += (double)v * (double)v;
    }
    __shared__ double ss[256], qq[256];
    ss[threadIdx.x] = s; qq[threadIdx.x] = q;
    __syncthreads();
    for (int st = 128; st > 0; st >>= 1) {
        if (threadIdx.x < st) { ss[threadIdx.x] += ss[threadIdx.x + st]; qq[threadIdx.x] += qq[threadIdx.x + st]; }
        __syncthreads();
    }
    if (threadIdx.x == 0) {
        double m = ss[0] / (double)n;
        double var = qq[0] / (double)n - m * m;
        g_mean[b] = (float)m;
        g_inv[b]  = (float)(1.0 / sqrt(var + 1e-5));
    }
}

// ---------------- h statistics ----------------
__global__ __launch_bounds__(256) void k_hstats(const int* __restrict__ aux_len)
{
    const int b = blockIdx.x, ch = threadIdx.x;
    const int len = aux_len[b];
    const float* p = g_h + (size_t)b * TA * HDIM + ch;
    float s = 0.f, q = 0.f;
    for (int t = 0; t < len; t++) { float v = p[(size_t)t * HDIM]; s += v; q += v * v; }
    const float n = (float)len;
    const float m = s / n;
    const float var = (q - n * m * m) / (n - 1.f);
    g_mt[b * HDIM + ch] = m;
    g_st[b * HDIM + ch] = sqrtf(fmaxf(var, 1e-4f));
}

__global__ __launch_bounds__(256) void k_bias2(const float* __restrict__ att_w1,
                                               const float* __restrict__ att_b1)
{
    const int b = blockIdx.x, j = threadIdx.x;
    float acc = att_b1[j];
    for (int k = 0; k < HDIM; k++) {
        acc += g_mt[b * HDIM + k] * att_w1[(size_t)(256 + k) * HDIM + j]
             + g_st[b * HDIM + k] * att_w1[(size_t)(512 + k) * HDIM + j];
    }
    g_bias2[b * HDIM + j] = acc;
}

__global__ __launch_bounds__(256) void k_softpool(const int* __restrict__ aux_len,
                                                  const float* __restrict__ bn5g,
                                                  const float* __restrict__ bn5b)
{
    const int b = blockIdx.x, ch = threadIdx.x;
    const int len = aux_len[b];
    const float* lp = g_logits + (size_t)b * TA * HDIM + ch;
    const float* hp = g_h      + (size_t)b * TA * HDIM + ch;
    float mx = -1e30f;
    for (int t = 0; t < len; t++) mx = fmaxf(mx, lp[(size_t)t * HDIM]);
    float se = 0.f, s1 = 0.f, s2 = 0.f;
    for (int t = 0; t < len; t++) {
        float e = expf(lp[(size_t)t * HDIM] - mx);
        float hv = hp[(size_t)t * HDIM];
        se += e; s1 += hv * e; s2 += hv * hv * e;
    }
    float mu = s1 / se;
    float sg = sqrtf(fmaxf(s2 / se - mu * mu, 1e-4f));
    g_pool[b * 2 * HDIM + ch]        = mu * bn5g[ch]        + bn5b[ch];
    g_pool[b * 2 * HDIM + HDIM + ch] = sg * bn5g[HDIM + ch] + bn5b[HDIM + ch];
}

__global__ __launch_bounds__(256) void k_emb(const float* __restrict__ fc6_w,
                                             const float* __restrict__ fc6_b,
                                             const float* __restrict__ bn6g,
                                             const float* __restrict__ bn6b,
                                             const float* __restrict__ cls_w,
                                             const float* __restrict__ cls_b,
                                             float* __restrict__ out_cls, int write_cls)
{
    const int b = blockIdx.x, j = threadIdx.x;
    __shared__ float e[2 * HDIM];
    e[j]        = g_pool[b * 2 * HDIM + j];
    e[j + HDIM] = g_pool[b * 2 * HDIM + HDIM + j];
    __syncthreads();
    float acc = fc6_b[j];
    for (int k = 0; k < 2 * HDIM; k++) acc += e[k] * fc6_w[(size_t)k * FDIM + j];
    const float em = acc * bn6g[j] + bn6b[j];
    g_emb[b * FDIM + j] = em;

    __shared__ float red[256];
    red[j] = em * em;
    __syncthreads();
    for (int st = 128; st > 0; st >>= 1) { if (j < st) red[j] += red[j + st]; __syncthreads(); }
    const float nrmv = fmaxf(sqrtf(red[0]), 1e-12f);
    __shared__ float ne[256];
    ne[j] = em / nrmv;
    __syncthreads();
    if (write_cls && j < NCLS) {
        float c = cls_b[j];
        for (int k = 0; k < FDIM; k++) c += ne[k] * cls_w[(size_t)k * NCLS + j];
        out_cls[b * NCLS + j] = c;
    }
}

__global__ __launch_bounds__(256) void k_evec(const float* __restrict__ arn_w2)
{
    const int b = blockIdx.x, i = blockIdx.y, j = threadIdx.x;
    const float* W = arn_w2 + (size_t)i * FDIM * FDIM;
    float acc = 0.f;
    for (int k = 0; k < FDIM; k++) acc += g_emb[b * FDIM + k] * W[(size_t)k * FDIM + j];
    g_evec[((size_t)i * BDIM + b) * FDIM + j] = acc;
}

__global__ __launch_bounds__(256) void k_ola(float* __restrict__ out)
{
    const int idx = blockIdx.x * blockDim.x + threadIdx.x;
    if (idx >= BDIM * LSIG) return;
    const int b = idx / LSIG;
    const int i = idx - b * LSIG;
    const int t = i / SHIFT;
    const int j = i - t * SHIFT;
    const float* yb = g_y + (size_t)b * TIN * FRAME;
    float v = yb[(size_t)t * FRAME + j];
    if (t > 0) { v += yb[(size_t)(t - 1) * FRAME + j + SHIFT]; v *= 0.5f; }
    out[idx] = v;
}

// ---------------- launch ----------------
extern "C" void kernel_launch(void* const* d_in, const int* in_sizes, int n_in,
                              void* d_out, int out_size)
{
    const float* input   = (const float*)d_in[0];
    const float* anchor  = (const float*)d_in[1];
    const int*   aux_len = (const int*)  d_in[2];
    const float* in_w    = (const float*)d_in[4];
    const float* in_b    = (const float*)d_in[5];
    const float* out_w   = (const float*)d_in[6];
    const float* out_b   = (const float*)d_in[7];
    const float* gln_g   = (const float*)d_in[8];
    const float* gln_b   = (const float*)d_in[9];
    const float* ecapa_w = (const float*)d_in[10];
    const float* ecapa_b = (const float*)d_in[11];
    const float* att_w1  = (const float*)d_in[12];
    const float* att_b1  = (const float*)d_in[13];
    const float* attbn_g = (const float*)d_in[14];
    const float* attbn_b = (const float*)d_in[15];
    const float* att_w2  = (const float*)d_in[16];
    const float* att_b2  = (const float*)d_in[17];
    const float* bn5_g   = (const float*)d_in[18];
    const float* bn5_b   = (const float*)d_in[19];
    const float* fc6_w   = (const float*)d_in[20];
    const float* fc6_b   = (const float*)d_in[21];
    const float* bn6_g   = (const float*)d_in[22];
    const float* bn6_b   = (const float*)d_in[23];
    const float* cls_w   = (const float*)d_in[24];
    const float* cls_b   = (const float*)d_in[25];
    const float* arn_w1  = (const float*)d_in[26];
    const float* arn_w2  = (const float*)d_in[27];
    const float* arn_b   = (const float*)d_in[28];

    float *p_out, *p_out2, *p_aux, *p_h, *p_a, *p_logits, *p_y;
    cudaGetSymbolAddress((void**)&p_out,    g_out);
    cudaGetSymbolAddress((void**)&p_out2,   g_out2);
    cudaGetSymbolAddress((void**)&p_aux,    g_aux);
    cudaGetSymbolAddress((void**)&p_h,      g_h);
    cudaGetSymbolAddress((void**)&p_a,      g_a);
    cudaGetSymbolAddress((void**)&p_logits, g_logits);
    cudaGetSymbolAddress((void**)&p_y,      g_y);

    __nv_bfloat16 *pw_in_h, *pw_in_l, *pw_ec_h, *pw_ec_l, *pw_a1_h, *pw_a1_l,
                  *pw_a2_h, *pw_a2_l, *pw_ar_h, *pw_ar_l, *pw_ou_h, *pw_ou_l;
    cudaGetSymbolAddress((void**)&pw_in_h, w_in_hi);  cudaGetSymbolAddress((void**)&pw_in_l, w_in_lo);
    cudaGetSymbolAddress((void**)&pw_ec_h, w_ec_hi);  cudaGetSymbolAddress((void**)&pw_ec_l, w_ec_lo);
    cudaGetSymbolAddress((void**)&pw_a1_h, w_a1_hi);  cudaGetSymbolAddress((void**)&pw_a1_l, w_a1_lo);
    cudaGetSymbolAddress((void**)&pw_a2_h, w_a2_hi);  cudaGetSymbolAddress((void**)&pw_a2_l, w_a2_lo);
    cudaGetSymbolAddress((void**)&pw_ar_h, w_arn_hi); cudaGetSymbolAddress((void**)&pw_ar_l, w_arn_lo);
    cudaGetSymbolAddress((void**)&pw_ou_h, w_out_hi); cudaGetSymbolAddress((void**)&pw_ou_l, w_out_lo);

    // smem: 2 A planes (64*72*2B) + 2 B planes (N*72*2B)
    const int SM256 = 2 * (64 * 72 * 2) + 2 * (256 * 72 * 2);   // 92160
    const int SM320 = 2 * (64 * 72 * 2) + 2 * (320 * 72 * 2);   // 110592
    cudaFuncSetAttribute(k_tgemm<256,0>, cudaFuncAttributeMaxDynamicSharedMemorySize, SM256);
    cudaFuncSetAttribute(k_tgemm<256,1>, cudaFuncAttributeMaxDynamicSharedMemorySize, SM256);
    cudaFuncSetAttribute(k_tgemm<256,2>, cudaFuncAttributeMaxDynamicSharedMemorySize, SM256);
    cudaFuncSetAttribute(k_tgemm<256,3>, cudaFuncAttributeMaxDynamicSharedMemorySize, SM256);
    cudaFuncSetAttribute(k_tgemm<256,4>, cudaFuncAttributeMaxDynamicSharedMemorySize, SM256);
    cudaFuncSetAttribute(k_tgemm<320,3>, cudaFuncAttributeMaxDynamicSharedMemorySize, SM320);

    // weight prep (split + transpose)
    k_prep_w<<<(320*256+255)/256, 256>>>(in_w,    320, 256, pw_in_h, pw_in_l);
    k_prep_w<<<(256*256+255)/256, 256>>>(ecapa_w, 256, 256, pw_ec_h, pw_ec_l);
    k_prep_w<<<(256*256+255)/256, 256>>>(att_w1,  256, 256, pw_a1_h, pw_a1_l);
    k_prep_w<<<(256*256+255)/256, 256>>>(att_w2,  256, 256, pw_a2_h, pw_a2_l);
    for (int i = 0; i < 4; i++)
        k_prep_w<<<(256*256+255)/256, 256>>>(arn_w1 + (size_t)i*65536, 256, 256,
                                             pw_ar_h + (size_t)i*65536, pw_ar_l + (size_t)i*65536);
    k_prep_w<<<(256*320+255)/256, 256>>>(out_w,   256, 320, pw_ou_h, pw_ou_l);

    // 1-2. encoders
    k_tgemm<256,0><<<dim3(16, 32), 256, SM256>>>(input,  pw_in_h, pw_in_l, p_out, in_b, nullptr, nullptr,
                                                 nullptr, TIN, FRAME, LSIG, 0);
    k_tgemm<256,0><<<dim3(7, 32), 256, SM256>>>(anchor, pw_in_h, pw_in_l, p_aux, in_b, nullptr, nullptr,
                                                nullptr, TA, FRAME, LAUX, 0);
    // 3. GLN stats
    k_gln_reduce<<<32, 256>>>(aux_len);
    // 4. GLN + ecapa + relu
    k_tgemm<256,1><<<dim3(7, 32), 256, SM256>>>(p_aux, pw_ec_h, pw_ec_l, p_h, gln_g, gln_b, ecapa_b,
                                                aux_len, TA, FDIM, 0, 0);
    // 5-6. stats + attention bias
    k_hstats<<<32, 256>>>(aux_len);
    k_bias2<<<32, 256>>>(att_w1, att_b1);
    // 7. attention conv1(+relu+bn+tanh)
    k_tgemm<256,2><<<dim3(7, 32), 256, SM256>>>(p_h, pw_a1_h, pw_a1_l, p_a, attbn_g, attbn_b, nullptr,
                                                nullptr, TA, HDIM, 0, 0);
    // 8. attention conv2
    k_tgemm<256,3><<<dim3(7, 32), 256, SM256>>>(p_a, pw_a2_h, pw_a2_l, p_logits, att_b2, nullptr, nullptr,
                                                nullptr, TA, HDIM, 0, 0);
    // 9-11. pooling, embedding, ARN embedding projections
    k_softpool<<<32, 256>>>(aux_len, bn5_g, bn5_b);
    const int write_cls = (out_size >= BDIM * LSIG + BDIM * NCLS) ? 1 : 0;
    k_emb<<<32, 256>>>(fc6_w, fc6_b, bn6_g, bn6_b, cls_w, cls_b,
                       (float*)d_out + (size_t)BDIM * LSIG, write_cls);
    k_evec<<<dim3(32, 4), 256>>>(arn_w2);
    // 12. 4 ARN residual blocks (ping-pong)
    const float* src = p_out;
    float*       dst = p_out2;
    for (int i = 0; i < 4; i++) {
        k_tgemm<256,4><<<dim3(16, 32), 256, SM256>>>(src, pw_ar_h + (size_t)i*65536, pw_ar_l + (size_t)i*65536,
                                                     dst, arn_b + i * FDIM, nullptr, nullptr,
                                                     nullptr, TIN, FDIM, 0, i);
        const float* tmp = dst; dst = (float*)src; src = tmp;
    }
    // 13. decoder
    k_tgemm<320,3><<<dim3(16, 32), 256, SM320>>>(src, pw_ou_h, pw_ou_l, p_y, out_b, nullptr, nullptr,
                                                 nullptr, TIN, FDIM, 0, 0);
    // 14. OLA
    k_ola<<<(BDIM * LSIG + 255) / 256, 256>>>((float*)d_out);
}

// round 4
// speedup vs baseline: 1.4893x; 1.0705x over previous
#include <cuda_runtime.h>
#include <cuda_bf16.h>
#include <math.h>
#include <stdint.h>

#define BDIM   32
#define TIN    1000
#define TA     400
#define FDIM   256
#define HDIM   256
#define FRAME  320
#define SHIFT  160
#define LSIG   160000
#define LAUX   64000
#define NCLS   101

// ---------------- scratch (static device globals; no allocation) ----------------
__device__ float g_out   [BDIM * TIN * FDIM];
__device__ float g_out2  [BDIM * TIN * FDIM];
__device__ float g_aux   [BDIM * TA  * FDIM];
__device__ float g_h     [BDIM * TA  * HDIM];
__device__ float g_a     [BDIM * TA  * HDIM];
__device__ float g_logits[BDIM * TA  * HDIM];
__device__ float g_y     [BDIM * TIN * FRAME];
__device__ float g_mean  [BDIM];
__device__ float g_inv   [BDIM];
__device__ float g_bias2 [BDIM * HDIM];
__device__ float g_emb   [BDIM * FDIM];
__device__ float g_evec  [4 * BDIM * FDIM];

// bf16 split weight planes, layout [N][K] (K contiguous)
__device__ __nv_bfloat16 w_in_hi [256 * 320];
__device__ __nv_bfloat16 w_in_lo [256 * 320];
__device__ __nv_bfloat16 w_ec_hi [256 * 256];
__device__ __nv_bfloat16 w_ec_lo [256 * 256];
__device__ __nv_bfloat16 w_a1_hi [256 * 256];
__device__ __nv_bfloat16 w_a1_lo [256 * 256];
__device__ __nv_bfloat16 w_a2_hi [256 * 256];
__device__ __nv_bfloat16 w_a2_lo [256 * 256];
__device__ __nv_bfloat16 w_arn_hi[4 * 256 * 256];
__device__ __nv_bfloat16 w_arn_lo[4 * 256 * 256];
__device__ __nv_bfloat16 w_out_hi[320 * 256];
__device__ __nv_bfloat16 w_out_lo[320 * 256];

// ---------------- helpers ----------------
__device__ __forceinline__ uint32_t smem_u32(const void* p) {
    uint32_t a;
    asm("{ .reg .u64 t; cvta.to.shared.u64 t, %1; cvt.u32.u64 %0, t; }" : "=r"(a) : "l"(p));
    return a;
}
__device__ __forceinline__ void ldmx4(uint32_t* r, uint32_t addr) {
    asm volatile("ldmatrix.sync.aligned.m8n8.x4.shared.b16 {%0,%1,%2,%3}, [%4];"
                 : "=r"(r[0]), "=r"(r[1]), "=r"(r[2]), "=r"(r[3]) : "r"(addr));
}
__device__ __forceinline__ void ldmx2(uint32_t* r, uint32_t addr) {
    asm volatile("ldmatrix.sync.aligned.m8n8.x2.shared.b16 {%0,%1}, [%2];"
                 : "=r"(r[0]), "=r"(r[1]) : "r"(addr));
}
__device__ __forceinline__ void mma_bf16(float* c, const uint32_t* a, const uint32_t* b) {
    asm volatile("mma.sync.aligned.m16n8k16.row.col.f32.bf16.bf16.f32 "
                 "{%0,%1,%2,%3}, {%4,%5,%6,%7}, {%8,%9}, {%0,%1,%2,%3};"
                 : "+f"(c[0]), "+f"(c[1]), "+f"(c[2]), "+f"(c[3])
                 : "r"(a[0]), "r"(a[1]), "r"(a[2]), "r"(a[3]), "r"(b[0]), "r"(b[1]));
}
__device__ __forceinline__ void cp16(uint32_t saddr, const void* gaddr) {
    asm volatile("cp.async.ca.shared.global [%0], [%1], 16;" :: "r"(saddr), "l"(gaddr));
}
__device__ __forceinline__ void cp_commit() { asm volatile("cp.async.commit_group;" ::: "memory"); }
template<int W> __device__ __forceinline__ void cp_wait() {
    asm volatile("cp.async.wait_group %0;" :: "n"(W) : "memory");
}

// ---------------- fused weight prep: all W[k][n] fp32 -> [n][k] bf16 hi/lo ----------------
struct PrepArgs {
    const float* src[10];
    __nv_bfloat16* hi[10];
    __nv_bfloat16* lo[10];
    int K[10];
    int off[11];
};
__global__ __launch_bounds__(256) void k_prep_all(PrepArgs a)
{
    int gid = blockIdx.x * blockDim.x + threadIdx.x;
    if (gid >= a.off[10]) return;
    int r = 0;
    while (gid >= a.off[r + 1]) r++;
    int i = gid - a.off[r];
    int K = a.K[r];
    int N = (a.off[r + 1] - a.off[r]) / K;
    int n = i / K, k = i - n * K;
    float x = a.src[r][(size_t)k * N + n];
    __nv_bfloat16 h = __float2bfloat16(x);
    a.hi[r][i] = h;
    a.lo[r][i] = __float2bfloat16(x - __bfloat162float(h));
}

// ---------------- tensor-core GEMM (mma.sync bf16, 3-term split, cp.async pipelined) ----------------
// CTA: 256 threads = 8 warps.  Tile: MT rows x N cols.
// MT=128: warps 2(m) x 4(n).  MT=64: warps 1 x 8.
// MODE 0: A = framed signal (row t -> signal[t*SHIFT+k], bound L). epi: + e0[col]
// MODE 1: A = GLN(g_aux) masked by aux_len. epi: relu(acc + e2[col]) masked
// MODE 2: A plain. epi: a = relu(acc + g_bias2[b,col]); tanh(a*e0[col]+e1[col])
// MODE 3: A plain. epi: + e0[col]
// MODE 4: A plain. epi: C = A[t,col] + tanh(acc + g_evec[arn_i,b,col] + e0[col])
template<int N, int MODE, int MT, bool DB>
__global__ void __launch_bounds__(256, 1) k_tgemm(
    const float* __restrict__ A,
    const __nv_bfloat16* __restrict__ Bhi, const __nv_bfloat16* __restrict__ Blo,
    float* __restrict__ C,
    const float* __restrict__ e0, const float* __restrict__ e1, const float* __restrict__ e2,
    const int* __restrict__ aux_len, int M, int K, int L, int arn_i)
{
    constexpr int WARPS_M = MT / 64;          // 2 or 1
    constexpr int WARPS_N = 8 / WARPS_M;      // 4 or 8
    constexpr int WN   = N / WARPS_N;         // 64 (N=256,MT=128) or 40 (N=320,MT=64)
    constexpr int NF   = WN / 8;              // 8 or 5
    constexpr int KS   = 72;                  // padded smem row stride (bf16 elems)
    constexpr int ASZ  = MT * KS * 2;         // bytes per A plane
    constexpr int BSZ  = N  * KS * 2;         // bytes per B plane
    constexpr int ABASE = 4 * ASZ;            // A: 2 bufs x 2 planes
    constexpr int TPR  = 256 / MT;            // threads per A row
    constexpr int ACOLS = 64 / TPR;           // fp32 cols per thread (32 or 16)

    extern __shared__ char smem[];
    const uint32_t sb = smem_u32(smem);

    const int tid  = threadIdx.x;
    const int w    = tid >> 5;
    const int lane = tid & 31;
    const int b    = blockIdx.y;
    const int t0   = blockIdx.x * MT;
    const int NB   = K / 64;
    const int wm   = w / WARPS_N;
    const int wn   = w % WARPS_N;
    const int wn0  = wn * WN;

    int   len  = 0;
    float mean = 0.f, inv = 0.f;
    if (MODE == 1) { len = aux_len[b]; mean = g_mean[b]; inv = g_inv[b]; }

    const int arow = tid / TPR;
    const int ac0  = (tid % TPR) * ACOLS;

    float acc[4][NF][4];
    #pragma unroll
    for (int mi = 0; mi < 4; mi++)
        #pragma unroll
        for (int nj = 0; nj < NF; nj++)
            #pragma unroll
            for (int q = 0; q < 4; q++) acc[mi][nj][q] = 0.f;

    float va[ACOLS];

    // ---- A prefetch (global -> regs, with MODE transform) ----
    auto prefA = [&](int kb) {
        const int t = t0 + arow;
        if (MODE == 0) {
            if (t < M) {
                const float* src = A + (size_t)b * L;
                const int base = t * SHIFT + kb * 64 + ac0;
                #pragma unroll
                for (int q = 0; q < ACOLS / 4; q++) {
                    const int p = base + q * 4;
                    if (p + 3 < L) {
                        float4 f = *(const float4*)(src + p);
                        va[q*4+0]=f.x; va[q*4+1]=f.y; va[q*4+2]=f.z; va[q*4+3]=f.w;
                    } else {
                        #pragma unroll
                        for (int j = 0; j < 4; j++) va[q*4+j] = (p + j < L) ? src[p + j] : 0.f;
                    }
                }
            } else {
                #pragma unroll
                for (int j = 0; j < ACOLS; j++) va[j] = 0.f;
            }
        } else {
            const bool valid = (MODE == 1) ? (t < len) : (t < M);
            if (valid) {
                const float* src = A + ((size_t)b * M + t) * K + kb * 64 + ac0;
                #pragma unroll
                for (int q = 0; q < ACOLS / 4; q++) {
                    float4 f = *(const float4*)(src + q * 4);
                    va[q*4+0]=f.x; va[q*4+1]=f.y; va[q*4+2]=f.z; va[q*4+3]=f.w;
                }
                if (MODE == 1) {
                    const int c0 = kb * 64 + ac0;
                    #pragma unroll
                    for (int q = 0; q < ACOLS / 4; q++) {
                        float4 gg = *(const float4*)(e0 + c0 + q * 4);
                        float4 gb = *(const float4*)(e1 + c0 + q * 4);
                        va[q*4+0] = gg.x * inv * (va[q*4+0] - mean) + gb.x;
                        va[q*4+1] = gg.y * inv * (va[q*4+1] - mean) + gb.y;
                        va[q*4+2] = gg.z * inv * (va[q*4+2] - mean) + gb.z;
                        va[q*4+3] = gg.w * inv * (va[q*4+3] - mean) + gb.w;
                    }
                }
            } else {
                #pragma unroll
                for (int j = 0; j < ACOLS; j++) va[j] = 0.f;
            }
        }
    };
    // ---- A convert (regs -> smem hi/lo planes of buffer) ----
    auto convA = [&](int buf) {
        char* aH = smem + (size_t)(buf * 2 + 0) * ASZ;
        char* aL = smem + (size_t)(buf * 2 + 1) * ASZ;
        #pragma unroll
        for (int q = 0; q < ACOLS / 8; q++) {
            union { __nv_bfloat16 x[8]; uint4 v; } H, Lo;
            #pragma unroll
            for (int j = 0; j < 8; j++) {
                float f = va[q * 8 + j];
                __nv_bfloat16 hb = __float2bfloat16(f);
                H.x[j]  = hb;
                Lo.x[j] = __float2bfloat16(f - __bfloat162float(hb));
            }
            const uint32_t bo = (uint32_t)(arow * KS + ac0 + q * 8) * 2;
            *(uint4*)(aH + bo) = H.v;
            *(uint4*)(aL + bo) = Lo.v;
        }
    };
    // ---- B stage via cp.async ----
    auto cpB = [&](int kb, int buf) {
        const uint32_t bH = sb + ABASE + (uint32_t)(buf * 2 + 0) * BSZ;
        const uint32_t bL = sb + ABASE + (uint32_t)(buf * 2 + 1) * BSZ;
        for (int idx = tid; idx < N * 8; idx += 256) {
            const int n = idx >> 3, j = idx & 7;
            const uint32_t so = (uint32_t)(n * KS + j * 8) * 2;
            cp16(bH + so, Bhi + (size_t)n * K + kb * 64 + j * 8);
            cp16(bL + so, Blo + (size_t)n * K + kb * 64 + j * 8);
        }
    };
    // ---- compute one staged k-block ----
    auto compute = [&](int buf) {
        const uint32_t aH = sb + (uint32_t)(buf * 2 + 0) * ASZ;
        const uint32_t aL = sb + (uint32_t)(buf * 2 + 1) * ASZ;
        const uint32_t bH = sb + ABASE + (uint32_t)(buf * 2 + 0) * BSZ;
        const uint32_t bL = sb + ABASE + (uint32_t)(buf * 2 + 1) * BSZ;
        #pragma unroll
        for (int ki = 0; ki < 4; ki++) {
            uint32_t bh[NF][2], bl[NF][2];
            // paired ldmatrix.x4: two n-frags per instruction
            #pragma unroll
            for (int p = 0; p < NF / 2; p++) {
                const int g = lane >> 3;
                const int nrow = wn0 + p * 16 + ((g >> 1) << 3) + (lane & 7);
                const int kcol = ki * 16 + ((g & 1) << 3);
                const uint32_t off = (uint32_t)(nrow * KS + kcol) * 2;
                uint32_t r4[4];
                ldmx4(r4, bH + off);
                bh[2*p][0]=r4[0]; bh[2*p][1]=r4[1]; bh[2*p+1][0]=r4[2]; bh[2*p+1][1]=r4[3];
                ldmx4(r4, bL + off);
                bl[2*p][0]=r4[0]; bl[2*p][1]=r4[1]; bl[2*p+1][0]=r4[2]; bl[2*p+1][1]=r4[3];
            }
            if (NF & 1) {
                const int nj = NF - 1;
                const int nrow = wn0 + nj * 8 + (lane & 7);
                const int kcol = ki * 16 + (((lane & 15) >> 3) << 3);
                const uint32_t off = (uint32_t)(nrow * KS + kcol) * 2;
                ldmx2(bh[nj], bH + off);
                ldmx2(bl[nj], bL + off);
            }
            #pragma unroll
            for (int mi = 0; mi < 4; mi++) {
                uint32_t ah[4], al[4];
                const int row = wm * 64 + mi * 16 + (lane & 15);
                const int col = ki * 16 + ((lane >> 4) << 3);
                const uint32_t off = (uint32_t)(row * KS + col) * 2;
                ldmx4(ah, aH + off);
                ldmx4(al, aL + off);
                #pragma unroll
                for (int nj = 0; nj < NF; nj++) {
                    mma_bf16(acc[mi][nj], ah, bh[nj]);
                    mma_bf16(acc[mi][nj], ah, bl[nj]);
                    mma_bf16(acc[mi][nj], al, bh[nj]);
                }
            }
        }
    };

    if (DB) {
        prefA(0);
        cpB(0, 0);
        cp_commit();
        for (int kb = 0; kb < NB; kb++) {
            const int buf = kb & 1;
            convA(buf);
            if (kb + 1 < NB) {
                prefA(kb + 1);
                cpB(kb + 1, buf ^ 1);
                cp_commit();
                cp_wait<1>();
            } else {
                cp_wait<0>();
            }
            __syncthreads();
            compute(buf);
            __syncthreads();
        }
    } else {
        for (int kb = 0; kb < NB; kb++) {
            prefA(kb);
            convA(0);
            cpB(kb, 0);
            cp_commit();
            cp_wait<0>();
            __syncthreads();
            compute(0);
            __syncthreads();
        }
    }

    // ---- epilogue ----
    #pragma unroll
    for (int mi = 0; mi < 4; mi++) {
        #pragma unroll
        for (int half = 0; half < 2; half++) {
            const int r = wm * 64 + mi * 16 + (lane >> 2) + half * 8;
            const int t = t0 + r;
            if (t >= M) continue;
            #pragma unroll
            for (int nj = 0; nj < NF; nj++) {
                const int col = wn0 + nj * 8 + (lane & 3) * 2;
                float v0 = acc[mi][nj][half * 2 + 0];
                float v1 = acc[mi][nj][half * 2 + 1];
                float r0, r1;
                if (MODE == 0) {
                    r0 = v0 + e0[col]; r1 = v1 + e0[col + 1];
                } else if (MODE == 1) {
                    if (t < len) { r0 = fmaxf(v0 + e2[col], 0.f); r1 = fmaxf(v1 + e2[col + 1], 0.f); }
                    else         { r0 = 0.f; r1 = 0.f; }
                } else if (MODE == 2) {
                    float a0 = fmaxf(v0 + g_bias2[b * HDIM + col],     0.f);
                    float a1 = fmaxf(v1 + g_bias2[b * HDIM + col + 1], 0.f);
                    r0 = tanhf(a0 * e0[col]     + e1[col]);
                    r1 = tanhf(a1 * e0[col + 1] + e1[col + 1]);
                } else if (MODE == 3) {
                    r0 = v0 + e0[col]; r1 = v1 + e0[col + 1];
                } else {
                    const float* ares = A + ((size_t)b * M + t) * K + col;
                    const float* ev   = g_evec + ((size_t)arn_i * BDIM + b) * FDIM + col;
                    r0 = ares[0] + tanhf(v0 + ev[0] + e0[col]);
                    r1 = ares[1] + tanhf(v1 + ev[1] + e0[col + 1]);
                }
                *(float2*)(C + ((size_t)b * M + t) * N + col) = make_float2(r0, r1);
            }
        }
    }
}

// ---------------- GLN reduction ----------------
__global__ __launch_bounds__(256) void k_gln_reduce(const int* __restrict__ aux_len)
{
    const int b = blockIdx.x;
    const int len = aux_len[b];
    const int n = len * FDIM;
    const float* p = g_aux + (size_t)b * TA * FDIM;
    double s = 0.0, q = 0.0;
    for (int i = threadIdx.x; i < n; i += blockDim.x) {
        float v = p[i];
        s += (double)v; q += (double)v * (double)v;
    }
    __shared__ double ss[256], qq[256];
    ss[threadIdx.x] = s; qq[threadIdx.x] = q;
    __syncthreads();
    for (int st = 128; st > 0; st >>= 1) {
        if (threadIdx.x < st) { ss[threadIdx.x] += ss[threadIdx.x + st]; qq[threadIdx.x] += qq[threadIdx.x + st]; }
        __syncthreads();
    }
    if (threadIdx.x == 0) {
        double m = ss[0] / (double)n;
        double var = qq[0] / (double)n - m * m;
        g_mean[b] = (float)m;
        g_inv[b]  = (float)(1.0 / sqrt(var + 1e-5));
    }
}

// ---------------- h stats + attention time-constant bias (fused, block = batch) ----------------
__global__ __launch_bounds__(256) void k_hb(const int* __restrict__ aux_len,
                                            const float* __restrict__ att_w1,
                                            const float* __restrict__ att_b1)
{
    const int b = blockIdx.x, ch = threadIdx.x;
    const int len = aux_len[b];
    __shared__ float sm[256], sstd[256];
    {
        const float* p = g_h + (size_t)b * TA * HDIM + ch;
        float s = 0.f, q = 0.f;
        for (int t = 0; t < len; t++) { float v = p[(size_t)t * HDIM]; s += v; q += v * v; }
        const float n = (float)len;
        const float m = s / n;
        const float var = (q - n * m * m) / (n - 1.f);
        sm[ch] = m;
        sstd[ch] = sqrtf(fmaxf(var, 1e-4f));
    }
    __syncthreads();
    float acc = att_b1[ch];
    for (int k = 0; k < HDIM; k++) {
        acc += sm[k]   * att_w1[(size_t)(256 + k) * HDIM + ch]
             + sstd[k] * att_w1[(size_t)(512 + k) * HDIM + ch];
    }
    g_bias2[b * HDIM + ch] = acc;
}

// ---------------- softmax-pool + fc6/bn6/emb + classifier + ARN evec (fused, block = batch) ----------------
__global__ __launch_bounds__(256) void k_pev(const int* __restrict__ aux_len,
                                             const float* __restrict__ bn5g,
                                             const float* __restrict__ bn5b,
                                             const float* __restrict__ fc6_w,
                                             const float* __restrict__ fc6_b,
                                             const float* __restrict__ bn6g,
                                             const float* __restrict__ bn6b,
                                             const float* __restrict__ cls_w,
                                             const float* __restrict__ cls_b,
                                             const float* __restrict__ arn_w2,
                                             float* __restrict__ out_cls, int write_cls)
{
    const int b = blockIdx.x, j = threadIdx.x;
    const int len = aux_len[b];
    __shared__ float e[2 * HDIM];
    {
        const float* lp = g_logits + (size_t)b * TA * HDIM + j;
        const float* hp = g_h      + (size_t)b * TA * HDIM + j;
        float mx = -1e30f;
        for (int t = 0; t < len; t++) mx = fmaxf(mx, lp[(size_t)t * HDIM]);
        float se = 0.f, s1 = 0.f, s2 = 0.f;
        for (int t = 0; t < len; t++) {
            float ev = expf(lp[(size_t)t * HDIM] - mx);
            float hv = hp[(size_t)t * HDIM];
            se += ev; s1 += hv * ev; s2 += hv * hv * ev;
        }
        float mu = s1 / se;
        float sg = sqrtf(fmaxf(s2 / se - mu * mu, 1e-4f));
        e[j]        = mu * bn5g[j]        + bn5b[j];
        e[j + HDIM] = sg * bn5g[HDIM + j] + bn5b[HDIM + j];
    }
    __syncthreads();
    float acc = fc6_b[j];
    for (int k = 0; k < 2 * HDIM; k++) acc += e[k] * fc6_w[(size_t)k * FDIM + j];
    const float em = acc * bn6g[j] + bn6b[j];
    g_emb[b * FDIM + j] = em;

    __shared__ float red[256];
    red[j] = em * em;
    __syncthreads();
    for (int st = 128; st > 0; st >>= 1) { if (j < st) red[j] += red[j + st]; __syncthreads(); }
    const float nrmv = fmaxf(sqrtf(red[0]), 1e-12f);
    __shared__ float emv[256];
    emv[j] = em;
    __syncthreads();
    if (write_cls && j < NCLS) {
        float c = cls_b[j];
        for (int k = 0; k < FDIM; k++) c += (emv[k] / nrmv) * cls_w[(size_t)k * NCLS + j];
        out_cls[b * NCLS + j] = c;
    }
    // ARN embedding projections: evec[i,b,j] = emb[b] @ arn_w2[i][:,j]
    for (int i = 0; i < 4; i++) {
        const float* W = arn_w2 + (size_t)i * FDIM * FDIM;
        float a2 = 0.f;
        for (int k = 0; k < FDIM; k++) a2 += emv[k] * W[(size_t)k * FDIM + j];
        g_evec[((size_t)i * BDIM + b) * FDIM + j] = a2;
    }
}

__global__ __launch_bounds__(256) void k_ola(float* __restrict__ out)
{
    const int idx = blockIdx.x * blockDim.x + threadIdx.x;
    if (idx >= BDIM * LSIG) return;
    const int b = idx / LSIG;
    const int i = idx - b * LSIG;
    const int t = i / SHIFT;
    const int j = i - t * SHIFT;
    const float* yb = g_y + (size_t)b * TIN * FRAME;
    float v = yb[(size_t)t * FRAME + j];
    if (t > 0) { v += yb[(size_t)(t - 1) * FRAME + j + SHIFT]; v *= 0.5f; }
    out[idx] = v;
}

// ---------------- launch ----------------
extern "C" void kernel_launch(void* const* d_in, const int* in_sizes, int n_in,
                              void* d_out, int out_size)
{
    const float* input   = (const float*)d_in[0];
    const float* anchor  = (const float*)d_in[1];
    const int*   aux_len = (const int*)  d_in[2];
    const float* in_w    = (const float*)d_in[4];
    const float* in_b    = (const float*)d_in[5];
    const float* out_w   = (const float*)d_in[6];
    const float* out_b   = (const float*)d_in[7];
    const float* gln_g   = (const float*)d_in[8];
    const float* gln_b   = (const float*)d_in[9];
    const float* ecapa_w = (const float*)d_in[10];
    const float* ecapa_b = (const float*)d_in[11];
    const float* att_w1  = (const float*)d_in[12];
    const float* att_b1  = (const float*)d_in[13];
    const float* attbn_g = (const float*)d_in[14];
    const float* attbn_b = (const float*)d_in[15];
    const float* att_w2  = (const float*)d_in[16];
    const float* att_b2  = (const float*)d_in[17];
    const float* bn5_g   = (const float*)d_in[18];
    const float* bn5_b   = (const float*)d_in[19];
    const float* fc6_w   = (const float*)d_in[20];
    const float* fc6_b   = (const float*)d_in[21];
    const float* bn6_g   = (const float*)d_in[22];
    const float* bn6_b   = (const float*)d_in[23];
    const float* cls_w   = (const float*)d_in[24];
    const float* cls_b   = (const float*)d_in[25];
    const float* arn_w1  = (const float*)d_in[26];
    const float* arn_w2  = (const float*)d_in[27];
    const float* arn_b   = (const float*)d_in[28];

    float *p_out, *p_out2, *p_aux, *p_h, *p_a, *p_logits, *p_y;
    cudaGetSymbolAddress((void**)&p_out,    g_out);
    cudaGetSymbolAddress((void**)&p_out2,   g_out2);
    cudaGetSymbolAddress((void**)&p_aux,    g_aux);
    cudaGetSymbolAddress((void**)&p_h,      g_h);
    cudaGetSymbolAddress((void**)&p_a,      g_a);
    cudaGetSymbolAddress((void**)&p_logits, g_logits);
    cudaGetSymbolAddress((void**)&p_y,      g_y);

    __nv_bfloat16 *pw_in_h, *pw_in_l, *pw_ec_h, *pw_ec_l, *pw_a1_h, *pw_a1_l,
                  *pw_a2_h, *pw_a2_l, *pw_ar_h, *pw_ar_l, *pw_ou_h, *pw_ou_l;
    cudaGetSymbolAddress((void**)&pw_in_h, w_in_hi);  cudaGetSymbolAddress((void**)&pw_in_l, w_in_lo);
    cudaGetSymbolAddress((void**)&pw_ec_h, w_ec_hi);  cudaGetSymbolAddress((void**)&pw_ec_l, w_ec_lo);
    cudaGetSymbolAddress((void**)&pw_a1_h, w_a1_hi);  cudaGetSymbolAddress((void**)&pw_a1_l, w_a1_lo);
    cudaGetSymbolAddress((void**)&pw_a2_h, w_a2_hi);  cudaGetSymbolAddress((void**)&pw_a2_l, w_a2_lo);
    cudaGetSymbolAddress((void**)&pw_ar_h, w_arn_hi); cudaGetSymbolAddress((void**)&pw_ar_l, w_arn_lo);
    cudaGetSymbolAddress((void**)&pw_ou_h, w_out_hi); cudaGetSymbolAddress((void**)&pw_ou_l, w_out_lo);

    // ---- single fused weight-prep launch ----
    PrepArgs pa;
    int off = 0;
    auto reg = [&](int r, const float* s, __nv_bfloat16* h, __nv_bfloat16* l, int K, int elems) {
        pa.src[r] = s; pa.hi[r] = h; pa.lo[r] = l; pa.K[r] = K; pa.off[r] = off; off += elems;
    };
    reg(0, in_w,    pw_in_h, pw_in_l, 320, 320 * 256);
    reg(1, ecapa_w, pw_ec_h, pw_ec_l, 256, 256 * 256);
    reg(2, att_w1,  pw_a1_h, pw_a1_l, 256, 256 * 256);
    reg(3, att_w2,  pw_a2_h, pw_a2_l, 256, 256 * 256);
    for (int i = 0; i < 4; i++)
        reg(4 + i, arn_w1 + (size_t)i * 65536, pw_ar_h + (size_t)i * 65536,
            pw_ar_l + (size_t)i * 65536, 256, 256 * 256);
    reg(8, out_w, pw_ou_h, pw_ou_l, 256, 256 * 320);
    reg(9, out_w, pw_ou_h, pw_ou_l, 256, 0);   // pad (unused)
    pa.off[10] = off;
    k_prep_all<<<(off + 255) / 256, 256>>>(pa);

    // smem sizes
    constexpr int KS = 72;
    const int SM256 = 4 * (128 * KS * 2) + 4 * (256 * KS * 2);   // 221184
    const int SM320 = 4 * (64 * KS * 2) + 2 * (320 * KS * 2);    // 129024
    cudaFuncSetAttribute(k_tgemm<256,0,128,true>, cudaFuncAttributeMaxDynamicSharedMemorySize, SM256);
    cudaFuncSetAttribute(k_tgemm<256,1,128,true>, cudaFuncAttributeMaxDynamicSharedMemorySize, SM256);
    cudaFuncSetAttribute(k_tgemm<256,2,128,true>, cudaFuncAttributeMaxDynamicSharedMemorySize, SM256);
    cudaFuncSetAttribute(k_tgemm<256,3,128,true>, cudaFuncAttributeMaxDynamicSharedMemorySize, SM256);
    cudaFuncSetAttribute(k_tgemm<256,4,128,true>, cudaFuncAttributeMaxDynamicSharedMemorySize, SM256);
    cudaFuncSetAttribute(k_tgemm<320,3,64,false>, cudaFuncAttributeMaxDynamicSharedMemorySize, SM320);

    // 1-2. encoders
    k_tgemm<256,0,128,true><<<dim3(8, 32), 256, SM256>>>(input,  pw_in_h, pw_in_l, p_out, in_b,
                                                         nullptr, nullptr, nullptr, TIN, FRAME, LSIG, 0);
    k_tgemm<256,0,128,true><<<dim3(4, 32), 256, SM256>>>(anchor, pw_in_h, pw_in_l, p_aux, in_b,
                                                         nullptr, nullptr, nullptr, TA, FRAME, LAUX, 0);
    // 3. GLN stats
    k_gln_reduce<<<32, 256>>>(aux_len);
    // 4. GLN + ecapa + relu
    k_tgemm<256,1,128,true><<<dim3(4, 32), 256, SM256>>>(p_aux, pw_ec_h, pw_ec_l, p_h, gln_g, gln_b,
                                                         ecapa_b, aux_len, TA, FDIM, 0, 0);
    // 5. h stats + attention bias
    k_hb<<<32, 256>>>(aux_len, att_w1, att_b1);
    // 6. attention conv1(+relu+bn+tanh)
    k_tgemm<256,2,128,true><<<dim3(4, 32), 256, SM256>>>(p_h, pw_a1_h, pw_a1_l, p_a, attbn_g, attbn_b,
                                                         nullptr, nullptr, TA, HDIM, 0, 0);
    // 7. attention conv2
    k_tgemm<256,3,128,true><<<dim3(4, 32), 256, SM256>>>(p_a, pw_a2_h, pw_a2_l, p_logits, att_b2,
                                                         nullptr, nullptr, nullptr, TA, HDIM, 0, 0);
    // 8. pool + emb + classifier + evec
    const int write_cls = (out_size >= BDIM * LSIG + BDIM * NCLS) ? 1 : 0;
    k_pev<<<32, 256>>>(aux_len, bn5_g, bn5_b, fc6_w, fc6_b, bn6_g, bn6_b, cls_w, cls_b,
                       arn_w2, (float*)d_out + (size_t)BDIM * LSIG, write_cls);
    // 9-12. 4 ARN residual blocks (ping-pong)
    const float* src = p_out;
    float*       dst = p_out2;
    for (int i = 0; i < 4; i++) {
        k_tgemm<256,4,128,true><<<dim3(8, 32), 256, SM256>>>(src, pw_ar_h + (size_t)i * 65536,
                                                             pw_ar_l + (size_t)i * 65536, dst,
                                                             arn_b + i * FDIM, nullptr, nullptr,
                                                             nullptr, TIN, FDIM, 0, i);
        const float* tmp = dst; dst = (float*)src; src = tmp;
    }
    // 13. decoder
    k_tgemm<320,3,64,false><<<dim3(16, 32), 256, SM320>>>(src, pw_ou_h, pw_ou_l, p_y, out_b,
                                                          nullptr, nullptr, nullptr, TIN, FDIM, 0, 0);
    // 14. OLA
    k_ola<<<(BDIM * LSIG + 255) / 256, 256>>>((float*)d_out);
}

// round 5
// speedup vs baseline: 1.6293x; 1.0940x over previous
#include <cuda_runtime.h>
#include <cuda_bf16.h>
#include <math.h>
#include <stdint.h>

#define BDIM   32
#define TIN    1000
#define TA     400
#define FDIM   256
#define HDIM   256
#define FRAME  320
#define SHIFT  160
#define LSIG   160000
#define LAUX   64000
#define NCLS   101
#define NSLC   8     // time slices for partial reductions
#define SLC    (TA / NSLC)

// ---------------- scratch (static device globals; no allocation) ----------------
__device__ float g_out   [BDIM * TIN * FDIM];
__device__ float g_out2  [BDIM * TIN * FDIM];
__device__ float g_aux   [BDIM * TA  * FDIM];
__device__ float g_h     [BDIM * TA  * HDIM];
__device__ float g_a     [BDIM * TA  * HDIM];
__device__ float g_logits[BDIM * TA  * HDIM];
__device__ float g_y     [BDIM * TIN * FRAME];
__device__ float g_mean  [BDIM];
__device__ float g_inv   [BDIM];
__device__ float g_bias2 [BDIM * HDIM];
__device__ float g_emb   [BDIM * FDIM];
__device__ float g_evec  [4 * BDIM * FDIM];
__device__ float g_glnp  [BDIM * 16 * 2];
__device__ float g_hpart [BDIM * NSLC * HDIM * 2];
__device__ float g_ppart [BDIM * NSLC * HDIM * 4];

// bf16 split weight planes, layout [N][K] (K contiguous)
__device__ __nv_bfloat16 w_in_hi [256 * 320];
__device__ __nv_bfloat16 w_in_lo [256 * 320];
__device__ __nv_bfloat16 w_ec_hi [256 * 256];
__device__ __nv_bfloat16 w_ec_lo [256 * 256];
__device__ __nv_bfloat16 w_a1_hi [256 * 256];
__device__ __nv_bfloat16 w_a1_lo [256 * 256];
__device__ __nv_bfloat16 w_a2_hi [256 * 256];
__device__ __nv_bfloat16 w_a2_lo [256 * 256];
__device__ __nv_bfloat16 w_arn_hi[4 * 256 * 256];
__device__ __nv_bfloat16 w_arn_lo[4 * 256 * 256];
__device__ __nv_bfloat16 w_out_hi[320 * 256];
__device__ __nv_bfloat16 w_out_lo[320 * 256];

// ---------------- helpers ----------------
__device__ __forceinline__ uint32_t smem_u32(const void* p) {
    uint32_t a;
    asm("{ .reg .u64 t; cvta.to.shared.u64 t, %1; cvt.u32.u64 %0, t; }" : "=r"(a) : "l"(p));
    return a;
}
__device__ __forceinline__ void ldmx4(uint32_t* r, uint32_t addr) {
    asm volatile("ldmatrix.sync.aligned.m8n8.x4.shared.b16 {%0,%1,%2,%3}, [%4];"
                 : "=r"(r[0]), "=r"(r[1]), "=r"(r[2]), "=r"(r[3]) : "r"(addr));
}
__device__ __forceinline__ void ldmx2(uint32_t* r, uint32_t addr) {
    asm volatile("ldmatrix.sync.aligned.m8n8.x2.shared.b16 {%0,%1}, [%2];"
                 : "=r"(r[0]), "=r"(r[1]) : "r"(addr));
}
__device__ __forceinline__ void mma_bf16(float* c, const uint32_t* a, const uint32_t* b) {
    asm volatile("mma.sync.aligned.m16n8k16.row.col.f32.bf16.bf16.f32 "
                 "{%0,%1,%2,%3}, {%4,%5,%6,%7}, {%8,%9}, {%0,%1,%2,%3};"
                 : "+f"(c[0]), "+f"(c[1]), "+f"(c[2]), "+f"(c[3])
                 : "r"(a[0]), "r"(a[1]), "r"(a[2]), "r"(a[3]), "r"(b[0]), "r"(b[1]));
}
__device__ __forceinline__ void cp16(uint32_t saddr, const void* gaddr) {
    asm volatile("cp.async.ca.shared.global [%0], [%1], 16;" :: "r"(saddr), "l"(gaddr));
}
__device__ __forceinline__ void cp_commit() { asm volatile("cp.async.commit_group;" ::: "memory"); }
template<int W> __device__ __forceinline__ void cp_wait() {
    asm volatile("cp.async.wait_group %0;" :: "n"(W) : "memory");
}

// ---------------- fused weight prep ----------------
struct PrepArgs {
    const float* src[10];
    __nv_bfloat16* hi[10];
    __nv_bfloat16* lo[10];
    int K[10];
    int off[11];
};
__global__ __launch_bounds__(256) void k_prep_all(PrepArgs a)
{
    int gid = blockIdx.x * blockDim.x + threadIdx.x;
    if (gid >= a.off[10]) return;
    int r = 0;
    while (gid >= a.off[r + 1]) r++;
    int i = gid - a.off[r];
    int K = a.K[r];
    int N = (a.off[r + 1] - a.off[r]) / K;
    int n = i / K, k = i - n * K;
    float x = a.src[r][(size_t)k * N + n];
    __nv_bfloat16 h = __float2bfloat16(x);
    a.hi[r][i] = h;
    a.lo[r][i] = __float2bfloat16(x - __bfloat162float(h));
}

// ---------------- tensor-core GEMM (mma.sync bf16, 3-term split, cp.async pipelined) ----------------
template<int N, int MODE, int MT, bool DB>
__global__ void __launch_bounds__(256, 1) k_tgemm(
    const float* __restrict__ Ain,
    const __nv_bfloat16* __restrict__ Bhi, const __nv_bfloat16* __restrict__ Blo,
    float* __restrict__ Cin,
    const float* __restrict__ e0, const float* __restrict__ e1, const float* __restrict__ e2,
    const int* __restrict__ aux_len, int Min, int K, int Lin, int arn_i,
    const float* A2, float* C2, int M2, int L2, int split)
{
    constexpr int WARPS_M = MT / 64;
    constexpr int WARPS_N = 8 / WARPS_M;
    constexpr int WN   = N / WARPS_N;
    constexpr int NF   = WN / 8;
    constexpr int KS   = 72;
    constexpr int ASZ  = MT * KS * 2;
    constexpr int BSZ  = N  * KS * 2;
    constexpr int ABASE = 4 * ASZ;
    constexpr int TPR  = 256 / MT;
    constexpr int ACOLS = 64 / TPR;

    extern __shared__ char smem[];
    const uint32_t sb = smem_u32(smem);

    const int tid  = threadIdx.x;
    const int w    = tid >> 5;
    const int lane = tid & 31;
    const int b    = blockIdx.y;

    const float* A = Ain;
    float* C = Cin;
    int M = Min, L = Lin;
    int bx = blockIdx.x;
    if (MODE == 0 && split > 0 && bx >= split) {
        A = A2; C = C2; M = M2; L = L2; bx -= split;
    }
    const int t0 = bx * MT;
    const int NB = K / 64;
    const int wm = w / WARPS_N;
    const int wn = w % WARPS_N;
    const int wn0 = wn * WN;

    int   len  = 0;
    float mean = 0.f, inv = 0.f;
    if (MODE == 1) { len = aux_len[b]; mean = g_mean[b]; inv = g_inv[b]; }

    const int arow = tid / TPR;
    const int ac0  = (tid % TPR) * ACOLS;

    float acc[4][NF][4];
    #pragma unroll
    for (int mi = 0; mi < 4; mi++)
        #pragma unroll
        for (int nj = 0; nj < NF; nj++)
            #pragma unroll
            for (int q = 0; q < 4; q++) acc[mi][nj][q] = 0.f;

    float va[ACOLS];

    auto prefA = [&](int kb) {
        const int t = t0 + arow;
        if (MODE == 0) {
            if (t < M) {
                const float* src = A + (size_t)b * L;
                const int base = t * SHIFT + kb * 64 + ac0;
                #pragma unroll
                for (int q = 0; q < ACOLS / 4; q++) {
                    const int p = base + q * 4;
                    if (p + 3 < L) {
                        float4 f = *(const float4*)(src + p);
                        va[q*4+0]=f.x; va[q*4+1]=f.y; va[q*4+2]=f.z; va[q*4+3]=f.w;
                    } else {
                        #pragma unroll
                        for (int j = 0; j < 4; j++) va[q*4+j] = (p + j < L) ? src[p + j] : 0.f;
                    }
                }
            } else {
                #pragma unroll
                for (int j = 0; j < ACOLS; j++) va[j] = 0.f;
            }
        } else {
            const bool valid = (MODE == 1) ? (t < len) : (t < M);
            if (valid) {
                const float* src = A + ((size_t)b * M + t) * K + kb * 64 + ac0;
                #pragma unroll
                for (int q = 0; q < ACOLS / 4; q++) {
                    float4 f = *(const float4*)(src + q * 4);
                    va[q*4+0]=f.x; va[q*4+1]=f.y; va[q*4+2]=f.z; va[q*4+3]=f.w;
                }
                if (MODE == 1) {
                    const int c0 = kb * 64 + ac0;
                    #pragma unroll
                    for (int q = 0; q < ACOLS / 4; q++) {
                        float4 gg = *(const float4*)(e0 + c0 + q * 4);
                        float4 gb = *(const float4*)(e1 + c0 + q * 4);
                        va[q*4+0] = gg.x * inv * (va[q*4+0] - mean) + gb.x;
                        va[q*4+1] = gg.y * inv * (va[q*4+1] - mean) + gb.y;
                        va[q*4+2] = gg.z * inv * (va[q*4+2] - mean) + gb.z;
                        va[q*4+3] = gg.w * inv * (va[q*4+3] - mean) + gb.w;
                    }
                }
            } else {
                #pragma unroll
                for (int j = 0; j < ACOLS; j++) va[j] = 0.f;
            }
        }
    };
    auto convA = [&](int buf) {
        char* aH = smem + (size_t)(buf * 2 + 0) * ASZ;
        char* aL = smem + (size_t)(buf * 2 + 1) * ASZ;
        #pragma unroll
        for (int q = 0; q < ACOLS / 8; q++) {
            union { __nv_bfloat16 x[8]; uint4 v; } H, Lo;
            #pragma unroll
            for (int j = 0; j < 8; j++) {
                float f = va[q * 8 + j];
                __nv_bfloat16 hb = __float2bfloat16(f);
                H.x[j]  = hb;
                Lo.x[j] = __float2bfloat16(f - __bfloat162float(hb));
            }
            const uint32_t bo = (uint32_t)(arow * KS + ac0 + q * 8) * 2;
            *(uint4*)(aH + bo) = H.v;
            *(uint4*)(aL + bo) = Lo.v;
        }
    };
    auto cpB = [&](int kb, int buf) {
        const uint32_t bH = sb + ABASE + (uint32_t)(buf * 2 + 0) * BSZ;
        const uint32_t bL = sb + ABASE + (uint32_t)(buf * 2 + 1) * BSZ;
        for (int idx = tid; idx < N * 8; idx += 256) {
            const int n = idx >> 3, j = idx & 7;
            const uint32_t so = (uint32_t)(n * KS + j * 8) * 2;
            cp16(bH + so, Bhi + (size_t)n * K + kb * 64 + j * 8);
            cp16(bL + so, Blo + (size_t)n * K + kb * 64 + j * 8);
        }
    };
    auto compute = [&](int buf) {
        const uint32_t aH = sb + (uint32_t)(buf * 2 + 0) * ASZ;
        const uint32_t aL = sb + (uint32_t)(buf * 2 + 1) * ASZ;
        const uint32_t bH = sb + ABASE + (uint32_t)(buf * 2 + 0) * BSZ;
        const uint32_t bL = sb + ABASE + (uint32_t)(buf * 2 + 1) * BSZ;
        #pragma unroll
        for (int ki = 0; ki < 4; ki++) {
            uint32_t bh[NF][2], bl[NF][2];
            #pragma unroll
            for (int p = 0; p < NF / 2; p++) {
                const int g = lane >> 3;
                const int nrow = wn0 + p * 16 + ((g >> 1) << 3) + (lane & 7);
                const int kcol = ki * 16 + ((g & 1) << 3);
                const uint32_t off = (uint32_t)(nrow * KS + kcol) * 2;
                uint32_t r4[4];
                ldmx4(r4, bH + off);
                bh[2*p][0]=r4[0]; bh[2*p][1]=r4[1]; bh[2*p+1][0]=r4[2]; bh[2*p+1][1]=r4[3];
                ldmx4(r4, bL + off);
                bl[2*p][0]=r4[0]; bl[2*p][1]=r4[1]; bl[2*p+1][0]=r4[2]; bl[2*p+1][1]=r4[3];
            }
            if (NF & 1) {
                const int nj = NF - 1;
                const int nrow = wn0 + nj * 8 + (lane & 7);
                const int kcol = ki * 16 + (((lane & 15) >> 3) << 3);
                const uint32_t off = (uint32_t)(nrow * KS + kcol) * 2;
                ldmx2(bh[nj], bH + off);
                ldmx2(bl[nj], bL + off);
            }
            #pragma unroll
            for (int mi = 0; mi < 4; mi++) {
                uint32_t ah[4], al[4];
                const int row = wm * 64 + mi * 16 + (lane & 15);
                const int col = ki * 16 + ((lane >> 4) << 3);
                const uint32_t off = (uint32_t)(row * KS + col) * 2;
                ldmx4(ah, aH + off);
                ldmx4(al, aL + off);
                #pragma unroll
                for (int nj = 0; nj < NF; nj++) {
                    mma_bf16(acc[mi][nj], ah, bh[nj]);
                    mma_bf16(acc[mi][nj], ah, bl[nj]);
                    mma_bf16(acc[mi][nj], al, bh[nj]);
                }
            }
        }
    };

    if (DB) {
        prefA(0);
        cpB(0, 0);
        cp_commit();
        for (int kb = 0; kb < NB; kb++) {
            const int buf = kb & 1;
            convA(buf);
            if (kb + 1 < NB) {
                prefA(kb + 1);
                cpB(kb + 1, buf ^ 1);
                cp_commit();
                cp_wait<1>();
            } else {
                cp_wait<0>();
            }
            __syncthreads();
            compute(buf);
            __syncthreads();
        }
    } else {
        for (int kb = 0; kb < NB; kb++) {
            prefA(kb);
            convA(0);
            cpB(kb, 0);
            cp_commit();
            cp_wait<0>();
            __syncthreads();
            compute(0);
            __syncthreads();
        }
    }

    #pragma unroll
    for (int mi = 0; mi < 4; mi++) {
        #pragma unroll
        for (int half = 0; half < 2; half++) {
            const int r = wm * 64 + mi * 16 + (lane >> 2) + half * 8;
            const int t = t0 + r;
            if (t >= M) continue;
            #pragma unroll
            for (int nj = 0; nj < NF; nj++) {
                const int col = wn0 + nj * 8 + (lane & 3) * 2;
                float v0 = acc[mi][nj][half * 2 + 0];
                float v1 = acc[mi][nj][half * 2 + 1];
                float r0, r1;
                if (MODE == 0) {
                    r0 = v0 + e0[col]; r1 = v1 + e0[col + 1];
                } else if (MODE == 1) {
                    if (t < len) { r0 = fmaxf(v0 + e2[col], 0.f); r1 = fmaxf(v1 + e2[col + 1], 0.f); }
                    else         { r0 = 0.f; r1 = 0.f; }
                } else if (MODE == 2) {
                    float a0 = fmaxf(v0 + g_bias2[b * HDIM + col],     0.f);
                    float a1 = fmaxf(v1 + g_bias2[b * HDIM + col + 1], 0.f);
                    r0 = tanhf(a0 * e0[col]     + e1[col]);
                    r1 = tanhf(a1 * e0[col + 1] + e1[col + 1]);
                } else if (MODE == 3) {
                    r0 = v0 + e0[col]; r1 = v1 + e0[col + 1];
                } else {
                    const float* ares = A + ((size_t)b * M + t) * K + col;
                    const float* ev   = g_evec + ((size_t)arn_i * BDIM + b) * FDIM + col;
                    r0 = ares[0] + tanhf(v0 + ev[0] + e0[col]);
                    r1 = ares[1] + tanhf(v1 + ev[1] + e0[col + 1]);
                }
                *(float2*)(C + ((size_t)b * M + t) * N + col) = make_float2(r0, r1);
            }
        }
    }
}

// ---------------- GLN: phase A partials (grid 32x16), phase B combine ----------------
__global__ __launch_bounds__(256) void k_gln_part(const int* __restrict__ aux_len)
{
    const int b = blockIdx.x, s = blockIdx.y;
    const int len = aux_len[b];
    const int tA = s * (TA / 16);
    const int tB = min(len, tA + TA / 16);
    float sum = 0.f, sq = 0.f;
    if (tB > tA) {
        const float* p = g_aux + ((size_t)b * TA + tA) * FDIM;
        const int n = (tB - tA) * FDIM;
        for (int i = threadIdx.x; i < n; i += 256) {
            float v = p[i];
            sum += v; sq += v * v;
        }
    }
    __shared__ float ss[256], qq[256];
    ss[threadIdx.x] = sum; qq[threadIdx.x] = sq;
    __syncthreads();
    for (int st = 128; st > 0; st >>= 1) {
        if (threadIdx.x < st) { ss[threadIdx.x] += ss[threadIdx.x + st]; qq[threadIdx.x] += qq[threadIdx.x + st]; }
        __syncthreads();
    }
    if (threadIdx.x == 0) {
        g_glnp[(b * 16 + s) * 2 + 0] = ss[0];
        g_glnp[(b * 16 + s) * 2 + 1] = qq[0];
    }
}
__global__ __launch_bounds__(32) void k_gln_comb(const int* __restrict__ aux_len)
{
    const int b = blockIdx.x;
    const int t = threadIdx.x;
    double s = 0.0, q = 0.0;
    if (t < 16) {
        s = (double)g_glnp[(b * 16 + t) * 2 + 0];
        q = (double)g_glnp[(b * 16 + t) * 2 + 1];
    }
    #pragma unroll
    for (int o = 16; o > 0; o >>= 1) {
        s += __shfl_down_sync(0xffffffff, s, o);
        q += __shfl_down_sync(0xffffffff, q, o);
    }
    if (t == 0) {
        const double n = (double)aux_len[b] * FDIM;
        double m = s / n;
        double var = q / n - m * m;
        g_mean[b] = (float)m;
        g_inv[b]  = (float)(1.0 / sqrt(var + 1e-5));
    }
}

// ---------------- h stats: phase A partials (grid 32xNSLC), phase B combine + bias2 ----------------
__global__ __launch_bounds__(256) void k_hpart(const int* __restrict__ aux_len)
{
    const int b = blockIdx.x, s = blockIdx.y, ch = threadIdx.x;
    const int len = aux_len[b];
    const int tA = s * SLC;
    const int tB = min(len, tA + SLC);
    float sum = 0.f, sq = 0.f;
    const float* p = g_h + ((size_t)b * TA) * HDIM + ch;
    for (int t = tA; t < tB; t++) {
        float v = p[(size_t)t * HDIM];
        sum += v; sq += v * v;
    }
    float* o = g_hpart + (((size_t)b * NSLC + s) * HDIM + ch) * 2;
    o[0] = sum; o[1] = sq;
}
__global__ __launch_bounds__(256) void k_hcomb(const int* __restrict__ aux_len,
                                               const float* __restrict__ att_w1,
                                               const float* __restrict__ att_b1)
{
    const int b = blockIdx.x, ch = threadIdx.x;
    const int len = aux_len[b];
    __shared__ float sm[256], sstd[256];
    {
        float sum = 0.f, sq = 0.f;
        #pragma unroll
        for (int s = 0; s < NSLC; s++) {
            const float* o = g_hpart + (((size_t)b * NSLC + s) * HDIM + ch) * 2;
            sum += o[0]; sq += o[1];
        }
        const float n = (float)len;
        const float m = sum / n;
        const float var = (sq - n * m * m) / (n - 1.f);
        sm[ch] = m;
        sstd[ch] = sqrtf(fmaxf(var, 1e-4f));
    }
    __syncthreads();
    float acc = att_b1[ch];
    for (int k = 0; k < HDIM; k++) {
        acc += sm[k]   * att_w1[(size_t)(256 + k) * HDIM + ch]
             + sstd[k] * att_w1[(size_t)(512 + k) * HDIM + ch];
    }
    g_bias2[b * HDIM + ch] = acc;
}

// ---------------- pool: phase A online-softmax partials, phase B combine + emb + cls + evec ----------------
__global__ __launch_bounds__(256) void k_ppart(const int* __restrict__ aux_len)
{
    const int b = blockIdx.x, s = blockIdx.y, ch = threadIdx.x;
    const int len = aux_len[b];
    const int tA = s * SLC;
    const int tB = min(len, tA + SLC);
    const float* lp = g_logits + (size_t)b * TA * HDIM + ch;
    const float* hp = g_h      + (size_t)b * TA * HDIM + ch;
    float mx = -1e30f, se = 0.f, s1 = 0.f, s2 = 0.f;
    for (int t = tA; t < tB; t++) {
        float l  = lp[(size_t)t * HDIM];
        float hv = hp[(size_t)t * HDIM];
        if (l > mx) {
            float sc = expf(mx - l);
            se *= sc; s1 *= sc; s2 *= sc;
            mx = l;
        }
        float e = expf(l - mx);
        se += e; s1 += hv * e; s2 += hv * hv * e;
    }
    float* o = g_ppart + (((size_t)b * NSLC + s) * HDIM + ch) * 4;
    o[0] = mx; o[1] = se; o[2] = s1; o[3] = s2;
}
__global__ __launch_bounds__(256) void k_pcomb(const float* __restrict__ bn5g,
                                               const float* __restrict__ bn5b,
                                               const float* __restrict__ fc6_w,
                                               const float* __restrict__ fc6_b,
                                               const float* __restrict__ bn6g,
                                               const float* __restrict__ bn6b,
                                               const float* __restrict__ cls_w,
                                               const float* __restrict__ cls_b,
                                               const float* __restrict__ arn_w2,
                                               float* __restrict__ out_cls, int write_cls)
{
    const int b = blockIdx.x, j = threadIdx.x;
    __shared__ float e[2 * HDIM];
    {
        float mx = -1e30f;
        float pm[NSLC];
        #pragma unroll
        for (int s = 0; s < NSLC; s++) {
            pm[s] = g_ppart[(((size_t)b * NSLC + s) * HDIM + j) * 4];
            mx = fmaxf(mx, pm[s]);
        }
        float se = 0.f, s1 = 0.f, s2 = 0.f;
        #pragma unroll
        for (int s = 0; s < NSLC; s++) {
            const float* o = g_ppart + (((size_t)b * NSLC + s) * HDIM + j) * 4;
            float sc = expf(pm[s] - mx);
            se += o[1] * sc; s1 += o[2] * sc; s2 += o[3] * sc;
        }
        float mu = s1 / se;
        float sg = sqrtf(fmaxf(s2 / se - mu * mu, 1e-4f));
        e[j]        = mu * bn5g[j]        + bn5b[j];
        e[j + HDIM] = sg * bn5g[HDIM + j] + bn5b[HDIM + j];
    }
    __syncthreads();
    float acc = fc6_b[j];
    for (int k = 0; k < 2 * HDIM; k++) acc += e[k] * fc6_w[(size_t)k * FDIM + j];
    const float em = acc * bn6g[j] + bn6b[j];
    g_emb[b * FDIM + j] = em;

    __shared__ float red[256];
    red[j] = em * em;
    __syncthreads();
    for (int st = 128; st > 0; st >>= 1) { if (j < st) red[j] += red[j + st]; __syncthreads(); }
    const float nrmv = fmaxf(sqrtf(red[0]), 1e-12f);
    __shared__ float emv[256];
    emv[j] = em;
    __syncthreads();
    if (write_cls && j < NCLS) {
        float c = cls_b[j];
        for (int k = 0; k < FDIM; k++) c += (emv[k] / nrmv) * cls_w[(size_t)k * NCLS + j];
        out_cls[b * NCLS + j] = c;
    }
    for (int i = 0; i < 4; i++) {
        const float* W = arn_w2 + (size_t)i * FDIM * FDIM;
        float a2 = 0.f;
        for (int k = 0; k < FDIM; k++) a2 += emv[k] * W[(size_t)k * FDIM + j];
        g_evec[((size_t)i * BDIM + b) * FDIM + j] = a2;
    }
}

__global__ __launch_bounds__(256) void k_ola(float* __restrict__ out)
{
    const int idx = blockIdx.x * blockDim.x + threadIdx.x;
    if (idx >= BDIM * LSIG) return;
    const int b = idx / LSIG;
    const int i = idx - b * LSIG;
    const int t = i / SHIFT;
    const int j = i - t * SHIFT;
    const float* yb = g_y + (size_t)b * TIN * FRAME;
    float v = yb[(size_t)t * FRAME + j];
    if (t > 0) { v += yb[(size_t)(t - 1) * FRAME + j + SHIFT]; v *= 0.5f; }
    out[idx] = v;
}

// ---------------- launch ----------------
extern "C" void kernel_launch(void* const* d_in, const int* in_sizes, int n_in,
                              void* d_out, int out_size)
{
    const float* input   = (const float*)d_in[0];
    const float* anchor  = (const float*)d_in[1];
    const int*   aux_len = (const int*)  d_in[2];
    const float* in_w    = (const float*)d_in[4];
    const float* in_b    = (const float*)d_in[5];
    const float* out_w   = (const float*)d_in[6];
    const float* out_b   = (const float*)d_in[7];
    const float* gln_g   = (const float*)d_in[8];
    const float* gln_b   = (const float*)d_in[9];
    const float* ecapa_w = (const float*)d_in[10];
    const float* ecapa_b = (const float*)d_in[11];
    const float* att_w1  = (const float*)d_in[12];
    const float* att_b1  = (const float*)d_in[13];
    const float* attbn_g = (const float*)d_in[14];
    const float* attbn_b = (const float*)d_in[15];
    const float* att_w2  = (const float*)d_in[16];
    const float* att_b2  = (const float*)d_in[17];
    const float* bn5_g   = (const float*)d_in[18];
    const float* bn5_b   = (const float*)d_in[19];
    const float* fc6_w   = (const float*)d_in[20];
    const float* fc6_b   = (const float*)d_in[21];
    const float* bn6_g   = (const float*)d_in[22];
    const float* bn6_b   = (const float*)d_in[23];
    const float* cls_w   = (const float*)d_in[24];
    const float* cls_b   = (const float*)d_in[25];
    const float* arn_w1  = (const float*)d_in[26];
    const float* arn_w2  = (const float*)d_in[27];
    const float* arn_b   = (const float*)d_in[28];

    float *p_out, *p_out2, *p_aux, *p_h, *p_a, *p_logits, *p_y;
    cudaGetSymbolAddress((void**)&p_out,    g_out);
    cudaGetSymbolAddress((void**)&p_out2,   g_out2);
    cudaGetSymbolAddress((void**)&p_aux,    g_aux);
    cudaGetSymbolAddress((void**)&p_h,      g_h);
    cudaGetSymbolAddress((void**)&p_a,      g_a);
    cudaGetSymbolAddress((void**)&p_logits, g_logits);
    cudaGetSymbolAddress((void**)&p_y,      g_y);

    __nv_bfloat16 *pw_in_h, *pw_in_l, *pw_ec_h, *pw_ec_l, *pw_a1_h, *pw_a1_l,
                  *pw_a2_h, *pw_a2_l, *pw_ar_h, *pw_ar_l, *pw_ou_h, *pw_ou_l;
    cudaGetSymbolAddress((void**)&pw_in_h, w_in_hi);  cudaGetSymbolAddress((void**)&pw_in_l, w_in_lo);
    cudaGetSymbolAddress((void**)&pw_ec_h, w_ec_hi);  cudaGetSymbolAddress((void**)&pw_ec_l, w_ec_lo);
    cudaGetSymbolAddress((void**)&pw_a1_h, w_a1_hi);  cudaGetSymbolAddress((void**)&pw_a1_l, w_a1_lo);
    cudaGetSymbolAddress((void**)&pw_a2_h, w_a2_hi);  cudaGetSymbolAddress((void**)&pw_a2_l, w_a2_lo);
    cudaGetSymbolAddress((void**)&pw_ar_h, w_arn_hi); cudaGetSymbolAddress((void**)&pw_ar_l, w_arn_lo);
    cudaGetSymbolAddress((void**)&pw_ou_h, w_out_hi); cudaGetSymbolAddress((void**)&pw_ou_l, w_out_lo);

    // ---- single fused weight-prep launch ----
    PrepArgs pa;
    int off = 0;
    auto reg = [&](int r, const float* s, __nv_bfloat16* h, __nv_bfloat16* l, int K, int elems) {
        pa.src[r] = s; pa.hi[r] = h; pa.lo[r] = l; pa.K[r] = K; pa.off[r] = off; off += elems;
    };
    reg(0, in_w,    pw_in_h, pw_in_l, 320, 320 * 256);
    reg(1, ecapa_w, pw_ec_h, pw_ec_l, 256, 256 * 256);
    reg(2, att_w1,  pw_a1_h, pw_a1_l, 256, 256 * 256);
    reg(3, att_w2,  pw_a2_h, pw_a2_l, 256, 256 * 256);
    for (int i = 0; i < 4; i++)
        reg(4 + i, arn_w1 + (size_t)i * 65536, pw_ar_h + (size_t)i * 65536,
            pw_ar_l + (size_t)i * 65536, 256, 256 * 256);
    reg(8, out_w, pw_ou_h, pw_ou_l, 256, 256 * 320);
    reg(9, out_w, pw_ou_h, pw_ou_l, 256, 0);
    pa.off[10] = off;
    k_prep_all<<<(off + 255) / 256, 256>>>(pa);

    constexpr int KS = 72;
    const int SM256 = 4 * (128 * KS * 2) + 4 * (256 * KS * 2);
    const int SM320 = 4 * (64 * KS * 2) + 2 * (320 * KS * 2);
    cudaFuncSetAttribute(k_tgemm<256,0,128,true>, cudaFuncAttributeMaxDynamicSharedMemorySize, SM256);
    cudaFuncSetAttribute(k_tgemm<256,1,128,true>, cudaFuncAttributeMaxDynamicSharedMemorySize, SM256);
    cudaFuncSetAttribute(k_tgemm<256,2,128,true>, cudaFuncAttributeMaxDynamicSharedMemorySize, SM256);
    cudaFuncSetAttribute(k_tgemm<256,3,128,true>, cudaFuncAttributeMaxDynamicSharedMemorySize, SM256);
    cudaFuncSetAttribute(k_tgemm<256,4,128,true>, cudaFuncAttributeMaxDynamicSharedMemorySize, SM256);
    cudaFuncSetAttribute(k_tgemm<320,3,64,false>, cudaFuncAttributeMaxDynamicSharedMemorySize, SM320);

    // 1. merged encoders: blocks [0,8) -> input, [8,12) -> anchor
    k_tgemm<256,0,128,true><<<dim3(12, 32), 256, SM256>>>(input, pw_in_h, pw_in_l, p_out, in_b,
                                                          nullptr, nullptr, nullptr, TIN, FRAME, LSIG, 0,
                                                          anchor, p_aux, TA, LAUX, 8);
    // 2. GLN stats (two-phase)
    k_gln_part<<<dim3(32, 16), 256>>>(aux_len);
    k_gln_comb<<<32, 32>>>(aux_len);
    // 3. GLN + ecapa + relu
    k_tgemm<256,1,128,true><<<dim3(4, 32), 256, SM256>>>(p_aux, pw_ec_h, pw_ec_l, p_h, gln_g, gln_b,
                                                         ecapa_b, aux_len, TA, FDIM, 0, 0,
                                                         nullptr, nullptr, 0, 0, 0);
    // 4. h stats (two-phase) + attention bias
    k_hpart<<<dim3(32, NSLC), 256>>>(aux_len);
    k_hcomb<<<32, 256>>>(aux_len, att_w1, att_b1);
    // 5. attention conv1(+relu+bn+tanh)
    k_tgemm<256,2,128,true><<<dim3(4, 32), 256, SM256>>>(p_h, pw_a1_h, pw_a1_l, p_a, attbn_g, attbn_b,
                                                         nullptr, nullptr, TA, HDIM, 0, 0,
                                                         nullptr, nullptr, 0, 0, 0);
    // 6. attention conv2
    k_tgemm<256,3,128,true><<<dim3(4, 32), 256, SM256>>>(p_a, pw_a2_h, pw_a2_l, p_logits, att_b2,
                                                         nullptr, nullptr, nullptr, TA, HDIM, 0, 0,
                                                         nullptr, nullptr, 0, 0, 0);
    // 7. pool (two-phase) + emb + classifier + evec
    k_ppart<<<dim3(32, NSLC), 256>>>(aux_len);
    const int write_cls = (out_size >= BDIM * LSIG + BDIM * NCLS) ? 1 : 0;
    k_pcomb<<<32, 256>>>(bn5_g, bn5_b, fc6_w, fc6_b, bn6_g, bn6_b, cls_w, cls_b,
                         arn_w2, (float*)d_out + (size_t)BDIM * LSIG, write_cls);
    // 8-11. 4 ARN residual blocks (ping-pong)
    const float* src = p_out;
    float*       dst = p_out2;
    for (int i = 0; i < 4; i++) {
        k_tgemm<256,4,128,true><<<dim3(8, 32), 256, SM256>>>(src, pw_ar_h + (size_t)i * 65536,
                                                             pw_ar_l + (size_t)i * 65536, dst,
                                                             arn_b + i * FDIM, nullptr, nullptr,
                                                             nullptr, TIN, FDIM, 0, i,
                                                             nullptr, nullptr, 0, 0, 0);
        const float* tmp = dst; dst = (float*)src; src = tmp;
    }
    // 12. decoder
    k_tgemm<320,3,64,false><<<dim3(16, 32), 256, SM320>>>(src, pw_ou_h, pw_ou_l, p_y, out_b,
                                                          nullptr, nullptr, nullptr, TIN, FDIM, 0, 0,
                                                          nullptr, nullptr, 0, 0, 0);
    // 13. OLA
    k_ola<<<(BDIM * LSIG + 255) / 256, 256>>>((float*)d_out);
}

// round 6
// speedup vs baseline: 1.8203x; 1.1172x over previous
#include <cuda_runtime.h>
#include <cuda_bf16.h>
#include <math.h>
#include <stdint.h>

#define BDIM   32
#define TIN    1000
#define TA     400
#define FDIM   256
#define HDIM   256
#define FRAME  320
#define SHIFT  160
#define LSIG   160000
#define LAUX   64000
#define NCLS   101
#define NSLC   8
#define SLC    (TA / NSLC)

// ---------------- scratch ----------------
__device__ float g_out   [BDIM * TIN * FDIM];
__device__ float g_out2  [BDIM * TIN * FDIM];
__device__ float g_aux   [BDIM * TA  * FDIM];
__device__ float g_h     [BDIM * TA  * HDIM];
__device__ float g_a     [BDIM * TA  * HDIM];
__device__ float g_logits[BDIM * TA  * HDIM];
__device__ float g_y     [BDIM * TIN * FRAME];
__device__ float g_bias2 [BDIM * HDIM];
__device__ float g_emb   [BDIM * FDIM];
__device__ float g_evec  [4 * BDIM * FDIM];
__device__ float g_glnp  [BDIM * 16 * 2];
__device__ float g_hpart [BDIM * NSLC * HDIM * 2];
__device__ float g_ppart [BDIM * NSLC * HDIM * 4];

// bf16 split weight planes, layout [N][K]
__device__ __nv_bfloat16 w_in_hi [256 * 320];
__device__ __nv_bfloat16 w_in_lo [256 * 320];
__device__ __nv_bfloat16 w_ec_hi [256 * 256];
__device__ __nv_bfloat16 w_ec_lo [256 * 256];
__device__ __nv_bfloat16 w_a1_hi [256 * 256];
__device__ __nv_bfloat16 w_a1_lo [256 * 256];
__device__ __nv_bfloat16 w_a2_hi [256 * 256];
__device__ __nv_bfloat16 w_a2_lo [256 * 256];
__device__ __nv_bfloat16 w_arn_hi[4 * 256 * 256];
__device__ __nv_bfloat16 w_arn_lo[4 * 256 * 256];
__device__ __nv_bfloat16 w_out_hi[320 * 256];
__device__ __nv_bfloat16 w_out_lo[320 * 256];

// ---------------- helpers ----------------
__device__ __forceinline__ uint32_t smem_u32(const void* p) {
    uint32_t a;
    asm("{ .reg .u64 t; cvta.to.shared.u64 t, %1; cvt.u32.u64 %0, t; }" : "=r"(a) : "l"(p));
    return a;
}
__device__ __forceinline__ void ldmx4(uint32_t* r, uint32_t addr) {
    asm volatile("ldmatrix.sync.aligned.m8n8.x4.shared.b16 {%0,%1,%2,%3}, [%4];"
                 : "=r"(r[0]), "=r"(r[1]), "=r"(r[2]), "=r"(r[3]) : "r"(addr));
}
__device__ __forceinline__ void ldmx2(uint32_t* r, uint32_t addr) {
    asm volatile("ldmatrix.sync.aligned.m8n8.x2.shared.b16 {%0,%1}, [%2];"
                 : "=r"(r[0]), "=r"(r[1]) : "r"(addr));
}
__device__ __forceinline__ void mma_bf16(float* c, const uint32_t* a, const uint32_t* b) {
    asm volatile("mma.sync.aligned.m16n8k16.row.col.f32.bf16.bf16.f32 "
                 "{%0,%1,%2,%3}, {%4,%5,%6,%7}, {%8,%9}, {%0,%1,%2,%3};"
                 : "+f"(c[0]), "+f"(c[1]), "+f"(c[2]), "+f"(c[3])
                 : "r"(a[0]), "r"(a[1]), "r"(a[2]), "r"(a[3]), "r"(b[0]), "r"(b[1]));
}
__device__ __forceinline__ void cp16(uint32_t saddr, const void* gaddr) {
    asm volatile("cp.async.ca.shared.global [%0], [%1], 16;" :: "r"(saddr), "l"(gaddr));
}
__device__ __forceinline__ void cp_commit() { asm volatile("cp.async.commit_group;" ::: "memory"); }
template<int W> __device__ __forceinline__ void cp_wait() {
    asm volatile("cp.async.wait_group %0;" :: "n"(W) : "memory");
}

// ---------------- weight prep: tiled transpose + split, one launch ----------------
struct PrepArgs {
    const float* src[10];
    __nv_bfloat16* hi[10];
    __nv_bfloat16* lo[10];
    int K[10];       // source rows (k dim)
    int N[10];       // source cols (n dim)
    int toff[11];    // tile offsets
};
__global__ __launch_bounds__(256) void k_prep_all(PrepArgs a)
{
    __shared__ float tile[32][33];
    int tb = blockIdx.x;
    int r = 0;
    while (tb >= a.toff[r + 1]) r++;
    int ti = tb - a.toff[r];
    const int K = a.K[r], N = a.N[r];
    const int ntn = N / 32;
    const int tk = ti / ntn, tn = ti - tk * ntn;
    const int ty = threadIdx.x >> 5, tx = threadIdx.x & 31;
    // load W[k][n] tile coalesced in n
    #pragma unroll
    for (int q = 0; q < 4; q++) {
        const int k = tk * 32 + ty + q * 8;
        tile[ty + q * 8][tx] = a.src[r][(size_t)k * N + tn * 32 + tx];
    }
    __syncthreads();
    // write [n][k] coalesced in k
    #pragma unroll
    for (int q = 0; q < 4; q++) {
        const int n = tn * 32 + ty + q * 8;
        float x = tile[tx][ty + q * 8];
        __nv_bfloat16 h = __float2bfloat16(x);
        const size_t o = (size_t)n * K + tk * 32 + tx;
        a.hi[r][o] = h;
        a.lo[r][o] = __float2bfloat16(x - __bfloat162float(h));
    }
}

// ---------------- tensor-core GEMM: 512 threads, 16 warps ----------------
// MT=128: warps 4(m) x 4(n), each warp 32 rows x 64 cols (MI=2, NF=8)
// MT=64 : warps 2(m) x 8(n), each warp 32 rows x 40 cols (MI=2, NF=5)
template<int N, int MODE, int MT, bool DB>
__global__ void __launch_bounds__(512, 1) k_tgemm(
    const float* __restrict__ Ain,
    const __nv_bfloat16* __restrict__ Bhi, const __nv_bfloat16* __restrict__ Blo,
    float* __restrict__ Cin,
    const float* __restrict__ e0, const float* __restrict__ e1, const float* __restrict__ e2,
    const int* __restrict__ aux_len, int Min, int K, int Lin, int arn_i,
    const float* A2, float* C2, int M2, int L2, int split)
{
    constexpr int WM   = (MT == 128) ? 4 : 2;   // warp rows
    constexpr int WNW  = 16 / WM;               // warp cols
    constexpr int MI   = MT / (WM * 16);        // m-frags per warp (2)
    constexpr int WN   = N / WNW;               // cols per warp
    constexpr int NF   = WN / 8;
    constexpr int KS   = 72;
    constexpr int ASZ  = MT * KS * 2;
    constexpr int BSZ  = N  * KS * 2;
    constexpr int ABASE = 4 * ASZ;
    constexpr int TPR  = 512 / MT;
    constexpr int ACOLS = 64 / TPR;

    extern __shared__ char smem[];
    const uint32_t sb = smem_u32(smem);

    const int tid  = threadIdx.x;
    const int w    = tid >> 5;
    const int lane = tid & 31;
    const int b    = blockIdx.y;

    const float* A = Ain;
    float* C = Cin;
    int M = Min, L = Lin;
    int bx = blockIdx.x;
    if (MODE == 0 && split > 0 && bx >= split) {
        A = A2; C = C2; M = M2; L = L2; bx -= split;
    }
    const int t0 = bx * MT;
    const int NB = K / 64;
    const int wm = w / WNW;
    const int wn = w % WNW;
    const int wn0 = wn * WN;

    int   len  = 0;
    float mean = 0.f, inv = 0.f;
    if (MODE == 1) {
        len = aux_len[b];
        double s = 0.0, q = 0.0;
        #pragma unroll
        for (int i = 0; i < 16; i++) {
            s += (double)g_glnp[(b * 16 + i) * 2 + 0];
            q += (double)g_glnp[(b * 16 + i) * 2 + 1];
        }
        const double n = (double)len * FDIM;
        double m = s / n;
        double var = q / n - m * m;
        mean = (float)m;
        inv  = (float)(1.0 / sqrt(var + 1e-5));
    }

    const int arow = tid / TPR;
    const int ac0  = (tid % TPR) * ACOLS;

    float acc[MI][NF][4];
    #pragma unroll
    for (int mi = 0; mi < MI; mi++)
        #pragma unroll
        for (int nj = 0; nj < NF; nj++)
            #pragma unroll
            for (int q = 0; q < 4; q++) acc[mi][nj][q] = 0.f;

    float va[ACOLS];

    auto prefA = [&](int kb) {
        const int t = t0 + arow;
        if (MODE == 0) {
            if (t < M) {
                const float* src = A + (size_t)b * L;
                const int base = t * SHIFT + kb * 64 + ac0;
                #pragma unroll
                for (int q = 0; q < ACOLS / 4; q++) {
                    const int p = base + q * 4;
                    if (p + 3 < L) {
                        float4 f = *(const float4*)(src + p);
                        va[q*4+0]=f.x; va[q*4+1]=f.y; va[q*4+2]=f.z; va[q*4+3]=f.w;
                    } else {
                        #pragma unroll
                        for (int j = 0; j < 4; j++) va[q*4+j] = (p + j < L) ? src[p + j] : 0.f;
                    }
                }
            } else {
                #pragma unroll
                for (int j = 0; j < ACOLS; j++) va[j] = 0.f;
            }
        } else {
            const bool valid = (MODE == 1) ? (t < len) : (t < M);
            if (valid) {
                const float* src = A + ((size_t)b * M + t) * K + kb * 64 + ac0;
                #pragma unroll
                for (int q = 0; q < ACOLS / 4; q++) {
                    float4 f = *(const float4*)(src + q * 4);
                    va[q*4+0]=f.x; va[q*4+1]=f.y; va[q*4+2]=f.z; va[q*4+3]=f.w;
                }
                if (MODE == 1) {
                    const int c0 = kb * 64 + ac0;
                    #pragma unroll
                    for (int q = 0; q < ACOLS / 4; q++) {
                        float4 gg = *(const float4*)(e0 + c0 + q * 4);
                        float4 gb = *(const float4*)(e1 + c0 + q * 4);
                        va[q*4+0] = gg.x * inv * (va[q*4+0] - mean) + gb.x;
                        va[q*4+1] = gg.y * inv * (va[q*4+1] - mean) + gb.y;
                        va[q*4+2] = gg.z * inv * (va[q*4+2] - mean) + gb.z;
                        va[q*4+3] = gg.w * inv * (va[q*4+3] - mean) + gb.w;
                    }
                }
            } else {
                #pragma unroll
                for (int j = 0; j < ACOLS; j++) va[j] = 0.f;
            }
        }
    };
    auto convA = [&](int buf) {
        char* aH = smem + (size_t)(buf * 2 + 0) * ASZ;
        char* aL = smem + (size_t)(buf * 2 + 1) * ASZ;
        #pragma unroll
        for (int q = 0; q < ACOLS / 8; q++) {
            union { __nv_bfloat16 x[8]; uint4 v; } H, Lo;
            #pragma unroll
            for (int j = 0; j < 8; j++) {
                float f = va[q * 8 + j];
                __nv_bfloat16 hb = __float2bfloat16(f);
                H.x[j]  = hb;
                Lo.x[j] = __float2bfloat16(f - __bfloat162float(hb));
            }
            const uint32_t bo = (uint32_t)(arow * KS + ac0 + q * 8) * 2;
            *(uint4*)(aH + bo) = H.v;
            *(uint4*)(aL + bo) = Lo.v;
        }
    };
    auto cpB = [&](int kb, int buf) {
        const uint32_t bH = sb + ABASE + (uint32_t)(buf * 2 + 0) * BSZ;
        const uint32_t bL = sb + ABASE + (uint32_t)(buf * 2 + 1) * BSZ;
        for (int idx = tid; idx < N * 8; idx += 512) {
            const int n = idx >> 3, j = idx & 7;
            const uint32_t so = (uint32_t)(n * KS + j * 8) * 2;
            cp16(bH + so, Bhi + (size_t)n * K + kb * 64 + j * 8);
            cp16(bL + so, Blo + (size_t)n * K + kb * 64 + j * 8);
        }
    };
    auto compute = [&](int buf) {
        const uint32_t aH = sb + (uint32_t)(buf * 2 + 0) * ASZ;
        const uint32_t aL = sb + (uint32_t)(buf * 2 + 1) * ASZ;
        const uint32_t bH = sb + ABASE + (uint32_t)(buf * 2 + 0) * BSZ;
        const uint32_t bL = sb + ABASE + (uint32_t)(buf * 2 + 1) * BSZ;
        #pragma unroll
        for (int ki = 0; ki < 4; ki++) {
            uint32_t bh[NF][2], bl[NF][2];
            #pragma unroll
            for (int p = 0; p < NF / 2; p++) {
                const int g = lane >> 3;
                const int nrow = wn0 + p * 16 + ((g >> 1) << 3) + (lane & 7);
                const int kcol = ki * 16 + ((g & 1) << 3);
                const uint32_t off = (uint32_t)(nrow * KS + kcol) * 2;
                uint32_t r4[4];
                ldmx4(r4, bH + off);
                bh[2*p][0]=r4[0]; bh[2*p][1]=r4[1]; bh[2*p+1][0]=r4[2]; bh[2*p+1][1]=r4[3];
                ldmx4(r4, bL + off);
                bl[2*p][0]=r4[0]; bl[2*p][1]=r4[1]; bl[2*p+1][0]=r4[2]; bl[2*p+1][1]=r4[3];
            }
            if (NF & 1) {
                const int nj = NF - 1;
                const int nrow = wn0 + nj * 8 + (lane & 7);
                const int kcol = ki * 16 + (((lane & 15) >> 3) << 3);
                const uint32_t off = (uint32_t)(nrow * KS + kcol) * 2;
                ldmx2(bh[nj], bH + off);
                ldmx2(bl[nj], bL + off);
            }
            #pragma unroll
            for (int mi = 0; mi < MI; mi++) {
                uint32_t ah[4], al[4];
                const int row = wm * (MI * 16) + mi * 16 + (lane & 15);
                const int col = ki * 16 + ((lane >> 4) << 3);
                const uint32_t off = (uint32_t)(row * KS + col) * 2;
                ldmx4(ah, aH + off);
                ldmx4(al, aL + off);
                #pragma unroll
                for (int nj = 0; nj < NF; nj++) {
                    mma_bf16(acc[mi][nj], ah, bh[nj]);
                    mma_bf16(acc[mi][nj], ah, bl[nj]);
                    mma_bf16(acc[mi][nj], al, bh[nj]);
                }
            }
        }
    };

    if (DB) {
        prefA(0);
        cpB(0, 0);
        cp_commit();
        for (int kb = 0; kb < NB; kb++) {
            const int buf = kb & 1;
            convA(buf);
            if (kb + 1 < NB) {
                prefA(kb + 1);
                cpB(kb + 1, buf ^ 1);
                cp_commit();
                cp_wait<1>();
            } else {
                cp_wait<0>();
            }
            __syncthreads();
            compute(buf);
            __syncthreads();
        }
    } else {
        for (int kb = 0; kb < NB; kb++) {
            prefA(kb);
            convA(0);
            cpB(kb, 0);
            cp_commit();
            cp_wait<0>();
            __syncthreads();
            compute(0);
            __syncthreads();
        }
    }

    #pragma unroll
    for (int mi = 0; mi < MI; mi++) {
        #pragma unroll
        for (int half = 0; half < 2; half++) {
            const int r = wm * (MI * 16) + mi * 16 + (lane >> 2) + half * 8;
            const int t = t0 + r;
            if (t >= M) continue;
            #pragma unroll
            for (int nj = 0; nj < NF; nj++) {
                const int col = wn0 + nj * 8 + (lane & 3) * 2;
                float v0 = acc[mi][nj][half * 2 + 0];
                float v1 = acc[mi][nj][half * 2 + 1];
                float r0, r1;
                if (MODE == 0) {
                    r0 = v0 + e0[col]; r1 = v1 + e0[col + 1];
                } else if (MODE == 1) {
                    if (t < len) { r0 = fmaxf(v0 + e2[col], 0.f); r1 = fmaxf(v1 + e2[col + 1], 0.f); }
                    else         { r0 = 0.f; r1 = 0.f; }
                } else if (MODE == 2) {
                    float a0 = fmaxf(v0 + g_bias2[b * HDIM + col],     0.f);
                    float a1 = fmaxf(v1 + g_bias2[b * HDIM + col + 1], 0.f);
                    r0 = tanhf(a0 * e0[col]     + e1[col]);
                    r1 = tanhf(a1 * e0[col + 1] + e1[col + 1]);
                } else if (MODE == 3) {
                    r0 = v0 + e0[col]; r1 = v1 + e0[col + 1];
                } else {
                    const float* ares = A + ((size_t)b * M + t) * K + col;
                    const float* ev   = g_evec + ((size_t)arn_i * BDIM + b) * FDIM + col;
                    r0 = ares[0] + tanhf(v0 + ev[0] + e0[col]);
                    r1 = ares[1] + tanhf(v1 + ev[1] + e0[col + 1]);
                }
                *(float2*)(C + ((size_t)b * M + t) * N + col) = make_float2(r0, r1);
            }
        }
    }
}

// ---------------- GLN partials ----------------
__global__ __launch_bounds__(256) void k_gln_part(const int* __restrict__ aux_len)
{
    const int b = blockIdx.x, s = blockIdx.y;
    const int len = aux_len[b];
    const int tA = s * (TA / 16);
    const int tB = min(len, tA + TA / 16);
    float sum = 0.f, sq = 0.f;
    if (tB > tA) {
        const float* p = g_aux + ((size_t)b * TA + tA) * FDIM;
        const int n = (tB - tA) * FDIM;
        for (int i = threadIdx.x; i < n; i += 256) {
            float v = p[i];
            sum += v; sq += v * v;
        }
    }
    __shared__ float ss[256], qq[256];
    ss[threadIdx.x] = sum; qq[threadIdx.x] = sq;
    __syncthreads();
    for (int st = 128; st > 0; st >>= 1) {
        if (threadIdx.x < st) { ss[threadIdx.x] += ss[threadIdx.x + st]; qq[threadIdx.x] += qq[threadIdx.x + st]; }
        __syncthreads();
    }
    if (threadIdx.x == 0) {
        g_glnp[(b * 16 + s) * 2 + 0] = ss[0];
        g_glnp[(b * 16 + s) * 2 + 1] = qq[0];
    }
}

// ---------------- h stats partials + combine ----------------
__global__ __launch_bounds__(256) void k_hpart(const int* __restrict__ aux_len)
{
    const int b = blockIdx.x, s = blockIdx.y, ch = threadIdx.x;
    const int len = aux_len[b];
    const int tA = s * SLC;
    const int tB = min(len, tA + SLC);
    float sum = 0.f, sq = 0.f;
    const float* p = g_h + ((size_t)b * TA) * HDIM + ch;
    for (int t = tA; t < tB; t++) {
        float v = p[(size_t)t * HDIM];
        sum += v; sq += v * v;
    }
    float* o = g_hpart + (((size_t)b * NSLC + s) * HDIM + ch) * 2;
    o[0] = sum; o[1] = sq;
}
__global__ __launch_bounds__(256) void k_hcomb(const int* __restrict__ aux_len,
                                               const float* __restrict__ att_w1,
                                               const float* __restrict__ att_b1)
{
    const int b = blockIdx.x, ch = threadIdx.x;
    const int len = aux_len[b];
    __shared__ float sm[256], sstd[256];
    {
        float sum = 0.f, sq = 0.f;
        #pragma unroll
        for (int s = 0; s < NSLC; s++) {
            const float* o = g_hpart + (((size_t)b * NSLC + s) * HDIM + ch) * 2;
            sum += o[0]; sq += o[1];
        }
        const float n = (float)len;
        const float m = sum / n;
        const float var = (sq - n * m * m) / (n - 1.f);
        sm[ch] = m;
        sstd[ch] = sqrtf(fmaxf(var, 1e-4f));
    }
    __syncthreads();
    float acc = att_b1[ch];
    for (int k = 0; k < HDIM; k++) {
        acc += sm[k]   * att_w1[(size_t)(256 + k) * HDIM + ch]
             + sstd[k] * att_w1[(size_t)(512 + k) * HDIM + ch];
    }
    g_bias2[b * HDIM + ch] = acc;
}

// ---------------- pool partials + combine ----------------
__global__ __launch_bounds__(256) void k_ppart(const int* __restrict__ aux_len)
{
    const int b = blockIdx.x, s = blockIdx.y, ch = threadIdx.x;
    const int len = aux_len[b];
    const int tA = s * SLC;
    const int tB = min(len, tA + SLC);
    const float* lp = g_logits + (size_t)b * TA * HDIM + ch;
    const float* hp = g_h      + (size_t)b * TA * HDIM + ch;
    float mx = -1e30f, se = 0.f, s1 = 0.f, s2 = 0.f;
    for (int t = tA; t < tB; t++) {
        float l  = lp[(size_t)t * HDIM];
        float hv = hp[(size_t)t * HDIM];
        if (l > mx) {
            float sc = expf(mx - l);
            se *= sc; s1 *= sc; s2 *= sc;
            mx = l;
        }
        float e = expf(l - mx);
        se += e; s1 += hv * e; s2 += hv * hv * e;
    }
    float* o = g_ppart + (((size_t)b * NSLC + s) * HDIM + ch) * 4;
    o[0] = mx; o[1] = se; o[2] = s1; o[3] = s2;
}
__global__ __launch_bounds__(256) void k_pcomb(const float* __restrict__ bn5g,
                                               const float* __restrict__ bn5b,
                                               const float* __restrict__ fc6_w,
                                               const float* __restrict__ fc6_b,
                                               const float* __restrict__ bn6g,
                                               const float* __restrict__ bn6b,
                                               const float* __restrict__ cls_w,
                                               const float* __restrict__ cls_b,
                                               const float* __restrict__ arn_w2,
                                               float* __restrict__ out_cls, int write_cls)
{
    const int b = blockIdx.x, j = threadIdx.x;
    __shared__ float e[2 * HDIM];
    {
        float mx = -1e30f;
        float pm[NSLC];
        #pragma unroll
        for (int s = 0; s < NSLC; s++) {
            pm[s] = g_ppart[(((size_t)b * NSLC + s) * HDIM + j) * 4];
            mx = fmaxf(mx, pm[s]);
        }
        float se = 0.f, s1 = 0.f, s2 = 0.f;
        #pragma unroll
        for (int s = 0; s < NSLC; s++) {
            const float* o = g_ppart + (((size_t)b * NSLC + s) * HDIM + j) * 4;
            float sc = expf(pm[s] - mx);
            se += o[1] * sc; s1 += o[2] * sc; s2 += o[3] * sc;
        }
        float mu = s1 / se;
        float sg = sqrtf(fmaxf(s2 / se - mu * mu, 1e-4f));
        e[j]        = mu * bn5g[j]        + bn5b[j];
        e[j + HDIM] = sg * bn5g[HDIM + j] + bn5b[HDIM + j];
    }
    __syncthreads();
    float acc = fc6_b[j];
    for (int k = 0; k < 2 * HDIM; k++) acc += e[k] * fc6_w[(size_t)k * FDIM + j];
    const float em = acc * bn6g[j] + bn6b[j];
    g_emb[b * FDIM + j] = em;

    __shared__ float red[256];
    red[j] = em * em;
    __syncthreads();
    for (int st = 128; st > 0; st >>= 1) { if (j < st) red[j] += red[j + st]; __syncthreads(); }
    const float nrmv = fmaxf(sqrtf(red[0]), 1e-12f);
    __shared__ float emv[256];
    emv[j] = em;
    __syncthreads();
    if (write_cls && j < NCLS) {
        float c = cls_b[j];
        for (int k = 0; k < FDIM; k++) c += (emv[k] / nrmv) * cls_w[(size_t)k * NCLS + j];
        out_cls[b * NCLS + j] = c;
    }
    for (int i = 0; i < 4; i++) {
        const float* W = arn_w2 + (size_t)i * FDIM * FDIM;
        float a2 = 0.f;
        for (int k = 0; k < FDIM; k++) a2 += emv[k] * W[(size_t)k * FDIM + j];
        g_evec[((size_t)i * BDIM + b) * FDIM + j] = a2;
    }
}

__global__ __launch_bounds__(256) void k_ola(float* __restrict__ out)
{
    const int idx = blockIdx.x * blockDim.x + threadIdx.x;
    if (idx >= BDIM * LSIG) return;
    const int b = idx / LSIG;
    const int i = idx - b * LSIG;
    const int t = i / SHIFT;
    const int j = i - t * SHIFT;
    const float* yb = g_y + (size_t)b * TIN * FRAME;
    float v = yb[(size_t)t * FRAME + j];
    if (t > 0) { v += yb[(size_t)(t - 1) * FRAME + j + SHIFT]; v *= 0.5f; }
    out[idx] = v;
}

// ---------------- launch ----------------
extern "C" void kernel_launch(void* const* d_in, const int* in_sizes, int n_in,
                              void* d_out, int out_size)
{
    const float* input   = (const float*)d_in[0];
    const float* anchor  = (const float*)d_in[1];
    const int*   aux_len = (const int*)  d_in[2];
    const float* in_w    = (const float*)d_in[4];
    const float* in_b    = (const float*)d_in[5];
    const float* out_w   = (const float*)d_in[6];
    const float* out_b   = (const float*)d_in[7];
    const float* gln_g   = (const float*)d_in[8];
    const float* gln_b   = (const float*)d_in[9];
    const float* ecapa_w = (const float*)d_in[10];
    const float* ecapa_b = (const float*)d_in[11];
    const float* att_w1  = (const float*)d_in[12];
    const float* att_b1  = (const float*)d_in[13];
    const float* attbn_g = (const float*)d_in[14];
    const float* attbn_b = (const float*)d_in[15];
    const float* att_w2  = (const float*)d_in[16];
    const float* att_b2  = (const float*)d_in[17];
    const float* bn5_g   = (const float*)d_in[18];
    const float* bn5_b   = (const float*)d_in[19];
    const float* fc6_w   = (const float*)d_in[20];
    const float* fc6_b   = (const float*)d_in[21];
    const float* bn6_g   = (const float*)d_in[22];
    const float* bn6_b   = (const float*)d_in[23];
    const float* cls_w   = (const float*)d_in[24];
    const float* cls_b   = (const float*)d_in[25];
    const float* arn_w1  = (const float*)d_in[26];
    const float* arn_w2  = (const float*)d_in[27];
    const float* arn_b   = (const float*)d_in[28];

    float *p_out, *p_out2, *p_aux, *p_h, *p_a, *p_logits, *p_y;
    cudaGetSymbolAddress((void**)&p_out,    g_out);
    cudaGetSymbolAddress((void**)&p_out2,   g_out2);
    cudaGetSymbolAddress((void**)&p_aux,    g_aux);
    cudaGetSymbolAddress((void**)&p_h,      g_h);
    cudaGetSymbolAddress((void**)&p_a,      g_a);
    cudaGetSymbolAddress((void**)&p_logits, g_logits);
    cudaGetSymbolAddress((void**)&p_y,      g_y);

    __nv_bfloat16 *pw_in_h, *pw_in_l, *pw_ec_h, *pw_ec_l, *pw_a1_h, *pw_a1_l,
                  *pw_a2_h, *pw_a2_l, *pw_ar_h, *pw_ar_l, *pw_ou_h, *pw_ou_l;
    cudaGetSymbolAddress((void**)&pw_in_h, w_in_hi);  cudaGetSymbolAddress((void**)&pw_in_l, w_in_lo);
    cudaGetSymbolAddress((void**)&pw_ec_h, w_ec_hi);  cudaGetSymbolAddress((void**)&pw_ec_l, w_ec_lo);
    cudaGetSymbolAddress((void**)&pw_a1_h, w_a1_hi);  cudaGetSymbolAddress((void**)&pw_a1_l, w_a1_lo);
    cudaGetSymbolAddress((void**)&pw_a2_h, w_a2_hi);  cudaGetSymbolAddress((void**)&pw_a2_l, w_a2_lo);
    cudaGetSymbolAddress((void**)&pw_ar_h, w_arn_hi); cudaGetSymbolAddress((void**)&pw_ar_l, w_arn_lo);
    cudaGetSymbolAddress((void**)&pw_ou_h, w_out_hi); cudaGetSymbolAddress((void**)&pw_ou_l, w_out_lo);

    // ---- single fused weight-prep (tiled transpose) ----
    PrepArgs pa;
    int toff = 0;
    auto reg = [&](int r, const float* s, __nv_bfloat16* h, __nv_bfloat16* l, int K, int N) {
        pa.src[r] = s; pa.hi[r] = h; pa.lo[r] = l; pa.K[r] = K; pa.N[r] = N;
        pa.toff[r] = toff; toff += (K / 32) * (N / 32);
    };
    reg(0, in_w,    pw_in_h, pw_in_l, 320, 256);
    reg(1, ecapa_w, pw_ec_h, pw_ec_l, 256, 256);
    reg(2, att_w1,  pw_a1_h, pw_a1_l, 256, 256);
    reg(3, att_w2,  pw_a2_h, pw_a2_l, 256, 256);
    for (int i = 0; i < 4; i++)
        reg(4 + i, arn_w1 + (size_t)i * 65536, pw_ar_h + (size_t)i * 65536,
            pw_ar_l + (size_t)i * 65536, 256, 256);
    reg(8, out_w, pw_ou_h, pw_ou_l, 256, 320);
    pa.toff[9] = toff;       // layer 9 unused
    pa.src[9] = out_w; pa.hi[9] = pw_ou_h; pa.lo[9] = pw_ou_l; pa.K[9] = 256; pa.N[9] = 320;
    pa.toff[10] = toff;
    k_prep_all<<<toff, 256>>>(pa);

    constexpr int KS = 72;
    const int SM256 = 4 * (128 * KS * 2) + 4 * (256 * KS * 2);
    const int SM320 = 4 * (64 * KS * 2) + 2 * (320 * KS * 2);
    cudaFuncSetAttribute(k_tgemm<256,0,128,true>, cudaFuncAttributeMaxDynamicSharedMemorySize, SM256);
    cudaFuncSetAttribute(k_tgemm<256,1,128,true>, cudaFuncAttributeMaxDynamicSharedMemorySize, SM256);
    cudaFuncSetAttribute(k_tgemm<256,2,128,true>, cudaFuncAttributeMaxDynamicSharedMemorySize, SM256);
    cudaFuncSetAttribute(k_tgemm<256,3,128,true>, cudaFuncAttributeMaxDynamicSharedMemorySize, SM256);
    cudaFuncSetAttribute(k_tgemm<256,4,128,true>, cudaFuncAttributeMaxDynamicSharedMemorySize, SM256);
    cudaFuncSetAttribute(k_tgemm<320,3,64,false>, cudaFuncAttributeMaxDynamicSharedMemorySize, SM320);

    // 1. merged encoders: blocks [0,8) -> input, [8,12) -> anchor
    k_tgemm<256,0,128,true><<<dim3(12, 32), 512, SM256>>>(input, pw_in_h, pw_in_l, p_out, in_b,
                                                          nullptr, nullptr, nullptr, TIN, FRAME, LSIG, 0,
                                                          anchor, p_aux, TA, LAUX, 8);
    // 2. GLN partials (combine folded into next GEMM)
    k_gln_part<<<dim3(32, 16), 256>>>(aux_len);
    // 3. GLN + ecapa + relu
    k_tgemm<256,1,128,true><<<dim3(4, 32), 512, SM256>>>(p_aux, pw_ec_h, pw_ec_l, p_h, gln_g, gln_b,
                                                         ecapa_b, aux_len, TA, FDIM, 0, 0,
                                                         nullptr, nullptr, 0, 0, 0);
    // 4. h stats + attention bias
    k_hpart<<<dim3(32, NSLC), 256>>>(aux_len);
    k_hcomb<<<32, 256>>>(aux_len, att_w1, att_b1);
    // 5. attention conv1(+relu+bn+tanh)
    k_tgemm<256,2,128,true><<<dim3(4, 32), 512, SM256>>>(p_h, pw_a1_h, pw_a1_l, p_a, attbn_g, attbn_b,
                                                         nullptr, nullptr, TA, HDIM, 0, 0,
                                                         nullptr, nullptr, 0, 0, 0);
    // 6. attention conv2
    k_tgemm<256,3,128,true><<<dim3(4, 32), 512, SM256>>>(p_a, pw_a2_h, pw_a2_l, p_logits, att_b2,
                                                         nullptr, nullptr, nullptr, TA, HDIM, 0, 0,
                                                         nullptr, nullptr, 0, 0, 0);
    // 7. pool + emb + classifier + evec
    k_ppart<<<dim3(32, NSLC), 256>>>(aux_len);
    const int write_cls = (out_size >= BDIM * LSIG + BDIM * NCLS) ? 1 : 0;
    k_pcomb<<<32, 256>>>(bn5_g, bn5_b, fc6_w, fc6_b, bn6_g, bn6_b, cls_w, cls_b,
                         arn_w2, (float*)d_out + (size_t)BDIM * LSIG, write_cls);
    // 8-11. 4 ARN residual blocks (ping-pong)
    const float* src = p_out;
    float*       dst = p_out2;
    for (int i = 0; i < 4; i++) {
        k_tgemm<256,4,128,true><<<dim3(8, 32), 512, SM256>>>(src, pw_ar_h + (size_t)i * 65536,
                                                             pw_ar_l + (size_t)i * 65536, dst,
                                                             arn_b + i * FDIM, nullptr, nullptr,
                                                             nullptr, TIN, FDIM, 0, i,
                                                             nullptr, nullptr, 0, 0, 0);
        const float* tmp = dst; dst = (float*)src; src = tmp;
    }
    // 12. decoder
    k_tgemm<320,3,64,false><<<dim3(16, 32), 512, SM320>>>(src, pw_ou_h, pw_ou_l, p_y, out_b,
                                                          nullptr, nullptr, nullptr, TIN, FDIM, 0, 0,
                                                          nullptr, nullptr, 0, 0, 0);
    // 13. OLA
    k_ola<<<(BDIM * LSIG + 255) / 256, 256>>>((float*)d_out);
}

// round 7
// speedup vs baseline: 1.8929x; 1.0398x over previous
#include <cuda_runtime.h>
#include <cuda_bf16.h>
#include <math.h>
#include <stdint.h>

#define BDIM   32
#define TIN    1000
#define TA     400
#define FDIM   256
#define HDIM   256
#define FRAME  320
#define SHIFT  160
#define LSIG   160000
#define LAUX   64000
#define NCLS   101
#define NSLC   8
#define SLC    (TA / NSLC)

// ---------------- scratch ----------------
__device__ float g_out   [BDIM * TIN * FDIM];
__device__ float g_out2  [BDIM * TIN * FDIM];
__device__ float g_aux   [BDIM * TA  * FDIM];
__device__ float g_h     [BDIM * TA  * HDIM];
__device__ float g_a     [BDIM * TA  * HDIM];
__device__ float g_logits[BDIM * TA  * HDIM];
__device__ float g_y     [BDIM * TIN * FRAME];
__device__ float g_bias2 [BDIM * HDIM];
__device__ float g_emb   [BDIM * FDIM];
__device__ float g_evec  [4 * BDIM * FDIM];
__device__ float g_glnp  [BDIM * 16 * 2];
__device__ float g_hpart [BDIM * NSLC * HDIM * 2];
__device__ float g_ppart [BDIM * NSLC * HDIM * 4];

// bf16 split weight planes, layout [N][K]
__device__ __nv_bfloat16 w_in_hi [256 * 320];
__device__ __nv_bfloat16 w_in_lo [256 * 320];
__device__ __nv_bfloat16 w_ec_hi [256 * 256];
__device__ __nv_bfloat16 w_ec_lo [256 * 256];
__device__ __nv_bfloat16 w_a1_hi [256 * 256];
__device__ __nv_bfloat16 w_a1_lo [256 * 256];
__device__ __nv_bfloat16 w_a2_hi [256 * 256];
__device__ __nv_bfloat16 w_a2_lo [256 * 256];
__device__ __nv_bfloat16 w_arn_hi[4 * 256 * 256];
__device__ __nv_bfloat16 w_arn_lo[4 * 256 * 256];
__device__ __nv_bfloat16 w_out_hi[320 * 256];
__device__ __nv_bfloat16 w_out_lo[320 * 256];

// ---------------- helpers ----------------
__device__ __forceinline__ uint32_t smem_u32(const void* p) {
    uint32_t a;
    asm("{ .reg .u64 t; cvta.to.shared.u64 t, %1; cvt.u32.u64 %0, t; }" : "=r"(a) : "l"(p));
    return a;
}
__device__ __forceinline__ void ldmx4(uint32_t* r, uint32_t addr) {
    asm volatile("ldmatrix.sync.aligned.m8n8.x4.shared.b16 {%0,%1,%2,%3}, [%4];"
                 : "=r"(r[0]), "=r"(r[1]), "=r"(r[2]), "=r"(r[3]) : "r"(addr));
}
__device__ __forceinline__ void ldmx2(uint32_t* r, uint32_t addr) {
    asm volatile("ldmatrix.sync.aligned.m8n8.x2.shared.b16 {%0,%1}, [%2];"
                 : "=r"(r[0]), "=r"(r[1]) : "r"(addr));
}
__device__ __forceinline__ void mma_bf16(float* c, const uint32_t* a, const uint32_t* b) {
    asm volatile("mma.sync.aligned.m16n8k16.row.col.f32.bf16.bf16.f32 "
                 "{%0,%1,%2,%3}, {%4,%5,%6,%7}, {%8,%9}, {%0,%1,%2,%3};"
                 : "+f"(c[0]), "+f"(c[1]), "+f"(c[2]), "+f"(c[3])
                 : "r"(a[0]), "r"(a[1]), "r"(a[2]), "r"(a[3]), "r"(b[0]), "r"(b[1]));
}
__device__ __forceinline__ void cp16(uint32_t saddr, const void* gaddr) {
    asm volatile("cp.async.ca.shared.global [%0], [%1], 16;" :: "r"(saddr), "l"(gaddr));
}
__device__ __forceinline__ void cp_commit() { asm volatile("cp.async.commit_group;" ::: "memory"); }
template<int W> __device__ __forceinline__ void cp_wait() {
    asm volatile("cp.async.wait_group %0;" :: "n"(W) : "memory");
}

// ---------------- weight prep: tiled transpose + split ----------------
struct PrepArgs {
    const float* src[10];
    __nv_bfloat16* hi[10];
    __nv_bfloat16* lo[10];
    int K[10];
    int N[10];
    int toff[11];
};
__global__ __launch_bounds__(256) void k_prep_all(PrepArgs a)
{
    __shared__ float tile[32][33];
    int tb = blockIdx.x;
    int r = 0;
    while (tb >= a.toff[r + 1]) r++;
    int ti = tb - a.toff[r];
    const int K = a.K[r], N = a.N[r];
    const int ntn = N / 32;
    const int tk = ti / ntn, tn = ti - tk * ntn;
    const int ty = threadIdx.x >> 5, tx = threadIdx.x & 31;
    #pragma unroll
    for (int q = 0; q < 4; q++) {
        const int k = tk * 32 + ty + q * 8;
        tile[ty + q * 8][tx] = a.src[r][(size_t)k * N + tn * 32 + tx];
    }
    __syncthreads();
    #pragma unroll
    for (int q = 0; q < 4; q++) {
        const int n = tn * 32 + ty + q * 8;
        float x = tile[tx][ty + q * 8];
        __nv_bfloat16 h = __float2bfloat16(x);
        const size_t o = (size_t)n * K + tk * 32 + tx;
        a.hi[r][o] = h;
        a.lo[r][o] = __float2bfloat16(x - __bfloat162float(h));
    }
}

// ---------------- tensor-core GEMM: 256 threads, MT=64 tile, NT N-split, 2 CTAs/SM ----------------
// grid: (m-tiles [+split], batch, N/NT)
// warps: 2(m) x 4(n); per warp: MI=2 m-frags x NF n-frags
template<int NT, int MODE>
__global__ void __launch_bounds__(256, 2) k_tgemm(
    const float* __restrict__ Ain,
    const __nv_bfloat16* __restrict__ Bhi, const __nv_bfloat16* __restrict__ Blo,
    float* __restrict__ Cin,
    const float* __restrict__ e0, const float* __restrict__ e1, const float* __restrict__ e2,
    const int* __restrict__ aux_len, int Min, int K, int Nfull, int Lin, int arn_i,
    const float* A2, float* C2, int M2, int L2, int split)
{
    constexpr int MT   = 64;
    constexpr int WN   = NT / 4;     // 32 or 40
    constexpr int NF   = WN / 8;     // 4 or 5
    constexpr int MI   = 2;
    constexpr int KS   = 72;
    constexpr int ASZ  = MT * KS * 2;       // 9216 B per A plane
    constexpr int BSZ  = NT * KS * 2;       // B plane bytes
    constexpr int ABASE = 2 * ASZ;          // A single-buffered (hi,lo)
    constexpr int ACOLS = 16;               // 4 threads per A row

    extern __shared__ char smem[];
    const uint32_t sb = smem_u32(smem);

    const int tid  = threadIdx.x;
    const int w    = tid >> 5;
    const int lane = tid & 31;
    const int b    = blockIdx.y;
    const int nbase = blockIdx.z * NT;

    const float* A = Ain;
    float* C = Cin;
    int M = Min, L = Lin;
    int bx = blockIdx.x;
    if (MODE == 0 && split > 0 && bx >= split) {
        A = A2; C = C2; M = M2; L = L2; bx -= split;
    }
    const int t0 = bx * MT;
    const int NB = K / 64;
    const int wm = w >> 2;           // 0..1
    const int wn = w & 3;            // 0..3
    const int wn0 = wn * WN;

    int   len  = 0;
    float mean = 0.f, inv = 0.f;
    if (MODE == 1) {
        len = aux_len[b];
        double s = 0.0, q = 0.0;
        #pragma unroll
        for (int i = 0; i < 16; i++) {
            s += (double)g_glnp[(b * 16 + i) * 2 + 0];
            q += (double)g_glnp[(b * 16 + i) * 2 + 1];
        }
        const double n = (double)len * FDIM;
        double m = s / n;
        double var = q / n - m * m;
        mean = (float)m;
        inv  = (float)(1.0 / sqrt(var + 1e-5));
    }

    const int arow = tid >> 2;              // 0..63
    const int ac0  = (tid & 3) * ACOLS;     // 0,16,32,48

    float acc[MI][NF][4];
    #pragma unroll
    for (int mi = 0; mi < MI; mi++)
        #pragma unroll
        for (int nj = 0; nj < NF; nj++)
            #pragma unroll
            for (int q = 0; q < 4; q++) acc[mi][nj][q] = 0.f;

    float va[ACOLS];

    auto prefA = [&](int kb) {
        const int t = t0 + arow;
        if (MODE == 0) {
            if (t < M) {
                const float* src = A + (size_t)b * L;
                const int base = t * SHIFT + kb * 64 + ac0;
                #pragma unroll
                for (int q = 0; q < 4; q++) {
                    const int p = base + q * 4;
                    if (p + 3 < L) {
                        float4 f = *(const float4*)(src + p);
                        va[q*4+0]=f.x; va[q*4+1]=f.y; va[q*4+2]=f.z; va[q*4+3]=f.w;
                    } else {
                        #pragma unroll
                        for (int j = 0; j < 4; j++) va[q*4+j] = (p + j < L) ? src[p + j] : 0.f;
                    }
                }
            } else {
                #pragma unroll
                for (int j = 0; j < ACOLS; j++) va[j] = 0.f;
            }
        } else {
            const bool valid = (MODE == 1) ? (t < len) : (t < M);
            if (valid) {
                const float* src = A + ((size_t)b * M + t) * K + kb * 64 + ac0;
                #pragma unroll
                for (int q = 0; q < 4; q++) {
                    float4 f = *(const float4*)(src + q * 4);
                    va[q*4+0]=f.x; va[q*4+1]=f.y; va[q*4+2]=f.z; va[q*4+3]=f.w;
                }
                if (MODE == 1) {
                    const int c0 = kb * 64 + ac0;
                    #pragma unroll
                    for (int q = 0; q < 4; q++) {
                        float4 gg = *(const float4*)(e0 + c0 + q * 4);
                        float4 gb = *(const float4*)(e1 + c0 + q * 4);
                        va[q*4+0] = gg.x * inv * (va[q*4+0] - mean) + gb.x;
                        va[q*4+1] = gg.y * inv * (va[q*4+1] - mean) + gb.y;
                        va[q*4+2] = gg.z * inv * (va[q*4+2] - mean) + gb.z;
                        va[q*4+3] = gg.w * inv * (va[q*4+3] - mean) + gb.w;
                    }
                }
            } else {
                #pragma unroll
                for (int j = 0; j < ACOLS; j++) va[j] = 0.f;
            }
        }
    };
    auto convA = [&]() {
        char* aH = smem;
        char* aL = smem + ASZ;
        #pragma unroll
        for (int q = 0; q < 2; q++) {
            union { __nv_bfloat16 x[8]; uint4 v; } H, Lo;
            #pragma unroll
            for (int j = 0; j < 8; j++) {
                float f = va[q * 8 + j];
                __nv_bfloat16 hb = __float2bfloat16(f);
                H.x[j]  = hb;
                Lo.x[j] = __float2bfloat16(f - __bfloat162float(hb));
            }
            const uint32_t bo = (uint32_t)(arow * KS + ac0 + q * 8) * 2;
            *(uint4*)(aH + bo) = H.v;
            *(uint4*)(aL + bo) = Lo.v;
        }
    };
    auto cpB = [&](int kb, int buf) {
        const uint32_t bH = sb + ABASE + (uint32_t)(buf * 2 + 0) * BSZ;
        const uint32_t bL = sb + ABASE + (uint32_t)(buf * 2 + 1) * BSZ;
        for (int idx = tid; idx < NT * 8; idx += 256) {
            const int n = idx >> 3, j = idx & 7;
            const uint32_t so = (uint32_t)(n * KS + j * 8) * 2;
            cp16(bH + so, Bhi + (size_t)(nbase + n) * K + kb * 64 + j * 8);
            cp16(bL + so, Blo + (size_t)(nbase + n) * K + kb * 64 + j * 8);
        }
    };
    auto compute = [&](int buf) {
        const uint32_t aH = sb;
        const uint32_t aL = sb + ASZ;
        const uint32_t bH = sb + ABASE + (uint32_t)(buf * 2 + 0) * BSZ;
        const uint32_t bL = sb + ABASE + (uint32_t)(buf * 2 + 1) * BSZ;
        #pragma unroll
        for (int ki = 0; ki < 4; ki++) {
            uint32_t bh[NF][2], bl[NF][2];
            #pragma unroll
            for (int p = 0; p < NF / 2; p++) {
                const int g = lane >> 3;
                const int nrow = wn0 + p * 16 + ((g >> 1) << 3) + (lane & 7);
                const int kcol = ki * 16 + ((g & 1) << 3);
                const uint32_t off = (uint32_t)(nrow * KS + kcol) * 2;
                uint32_t r4[4];
                ldmx4(r4, bH + off);
                bh[2*p][0]=r4[0]; bh[2*p][1]=r4[1]; bh[2*p+1][0]=r4[2]; bh[2*p+1][1]=r4[3];
                ldmx4(r4, bL + off);
                bl[2*p][0]=r4[0]; bl[2*p][1]=r4[1]; bl[2*p+1][0]=r4[2]; bl[2*p+1][1]=r4[3];
            }
            if (NF & 1) {
                const int nj = NF - 1;
                const int nrow = wn0 + nj * 8 + (lane & 7);
                const int kcol = ki * 16 + (((lane & 15) >> 3) << 3);
                const uint32_t off = (uint32_t)(nrow * KS + kcol) * 2;
                ldmx2(bh[nj], bH + off);
                ldmx2(bl[nj], bL + off);
            }
            #pragma unroll
            for (int mi = 0; mi < MI; mi++) {
                uint32_t ah[4], al[4];
                const int row = wm * 32 + mi * 16 + (lane & 15);
                const int col = ki * 16 + ((lane >> 4) << 3);
                const uint32_t off = (uint32_t)(row * KS + col) * 2;
                ldmx4(ah, aH + off);
                ldmx4(al, aL + off);
                #pragma unroll
                for (int nj = 0; nj < NF; nj++) {
                    mma_bf16(acc[mi][nj], ah, bh[nj]);
                    mma_bf16(acc[mi][nj], ah, bl[nj]);
                    mma_bf16(acc[mi][nj], al, bh[nj]);
                }
            }
        }
    };

    prefA(0);
    cpB(0, 0);
    cp_commit();
    for (int kb = 0; kb < NB; kb++) {
        const int buf = kb & 1;
        convA();
        if (kb + 1 < NB) {
            prefA(kb + 1);
            cpB(kb + 1, buf ^ 1);
            cp_commit();
            cp_wait<1>();
        } else {
            cp_wait<0>();
        }
        __syncthreads();
        compute(buf);
        __syncthreads();
    }

    #pragma unroll
    for (int mi = 0; mi < MI; mi++) {
        #pragma unroll
        for (int half = 0; half < 2; half++) {
            const int r = wm * 32 + mi * 16 + (lane >> 2) + half * 8;
            const int t = t0 + r;
            if (t >= M) continue;
            #pragma unroll
            for (int nj = 0; nj < NF; nj++) {
                const int col = nbase + wn0 + nj * 8 + (lane & 3) * 2;
                float v0 = acc[mi][nj][half * 2 + 0];
                float v1 = acc[mi][nj][half * 2 + 1];
                float r0, r1;
                if (MODE == 0) {
                    r0 = v0 + e0[col]; r1 = v1 + e0[col + 1];
                } else if (MODE == 1) {
                    if (t < len) { r0 = fmaxf(v0 + e2[col], 0.f); r1 = fmaxf(v1 + e2[col + 1], 0.f); }
                    else         { r0 = 0.f; r1 = 0.f; }
                } else if (MODE == 2) {
                    float a0 = fmaxf(v0 + g_bias2[b * HDIM + col],     0.f);
                    float a1 = fmaxf(v1 + g_bias2[b * HDIM + col + 1], 0.f);
                    r0 = tanhf(a0 * e0[col]     + e1[col]);
                    r1 = tanhf(a1 * e0[col + 1] + e1[col + 1]);
                } else if (MODE == 3) {
                    r0 = v0 + e0[col]; r1 = v1 + e0[col + 1];
                } else {
                    const float* ares = A + ((size_t)b * M + t) * K + col;
                    const float* ev   = g_evec + ((size_t)arn_i * BDIM + b) * FDIM + col;
                    r0 = ares[0] + tanhf(v0 + ev[0] + e0[col]);
                    r1 = ares[1] + tanhf(v1 + ev[1] + e0[col + 1]);
                }
                *(float2*)(C + ((size_t)b * M + t) * Nfull + col) = make_float2(r0, r1);
            }
        }
    }
}

// ---------------- GLN partials ----------------
__global__ __launch_bounds__(256) void k_gln_part(const int* __restrict__ aux_len)
{
    const int b = blockIdx.x, s = blockIdx.y;
    const int len = aux_len[b];
    const int tA = s * (TA / 16);
    const int tB = min(len, tA + TA / 16);
    float sum = 0.f, sq = 0.f;
    if (tB > tA) {
        const float* p = g_aux + ((size_t)b * TA + tA) * FDIM;
        const int n = (tB - tA) * FDIM;
        for (int i = threadIdx.x; i < n; i += 256) {
            float v = p[i];
            sum += v; sq += v * v;
        }
    }
    __shared__ float ss[256], qq[256];
    ss[threadIdx.x] = sum; qq[threadIdx.x] = sq;
    __syncthreads();
    for (int st = 128; st > 0; st >>= 1) {
        if (threadIdx.x < st) { ss[threadIdx.x] += ss[threadIdx.x + st]; qq[threadIdx.x] += qq[threadIdx.x + st]; }
        __syncthreads();
    }
    if (threadIdx.x == 0) {
        g_glnp[(b * 16 + s) * 2 + 0] = ss[0];
        g_glnp[(b * 16 + s) * 2 + 1] = qq[0];
    }
}

// ---------------- h stats partials + combine ----------------
__global__ __launch_bounds__(256) void k_hpart(const int* __restrict__ aux_len)
{
    const int b = blockIdx.x, s = blockIdx.y, ch = threadIdx.x;
    const int len = aux_len[b];
    const int tA = s * SLC;
    const int tB = min(len, tA + SLC);
    float sum = 0.f, sq = 0.f;
    const float* p = g_h + ((size_t)b * TA) * HDIM + ch;
    for (int t = tA; t < tB; t++) {
        float v = p[(size_t)t * HDIM];
        sum += v; sq += v * v;
    }
    float* o = g_hpart + (((size_t)b * NSLC + s) * HDIM + ch) * 2;
    o[0] = sum; o[1] = sq;
}
__global__ __launch_bounds__(256) void k_hcomb(const int* __restrict__ aux_len,
                                               const float* __restrict__ att_w1,
                                               const float* __restrict__ att_b1)
{
    const int b = blockIdx.x, ch = threadIdx.x;
    const int len = aux_len[b];
    __shared__ float sm[256], sstd[256];
    {
        float sum = 0.f, sq = 0.f;
        #pragma unroll
        for (int s = 0; s < NSLC; s++) {
            const float* o = g_hpart + (((size_t)b * NSLC + s) * HDIM + ch) * 2;
            sum += o[0]; sq += o[1];
        }
        const float n = (float)len;
        const float m = sum / n;
        const float var = (sq - n * m * m) / (n - 1.f);
        sm[ch] = m;
        sstd[ch] = sqrtf(fmaxf(var, 1e-4f));
    }
    __syncthreads();
    float acc = att_b1[ch];
    for (int k = 0; k < HDIM; k++) {
        acc += sm[k]   * att_w1[(size_t)(256 + k) * HDIM + ch]
             + sstd[k] * att_w1[(size_t)(512 + k) * HDIM + ch];
    }
    g_bias2[b * HDIM + ch] = acc;
}

// ---------------- pool partials + combine ----------------
__global__ __launch_bounds__(256) void k_ppart(const int* __restrict__ aux_len)
{
    const int b = blockIdx.x, s = blockIdx.y, ch = threadIdx.x;
    const int len = aux_len[b];
    const int tA = s * SLC;
    const int tB = min(len, tA + SLC);
    const float* lp = g_logits + (size_t)b * TA * HDIM + ch;
    const float* hp = g_h      + (size_t)b * TA * HDIM + ch;
    float mx = -1e30f, se = 0.f, s1 = 0.f, s2 = 0.f;
    for (int t = tA; t < tB; t++) {
        float l  = lp[(size_t)t * HDIM];
        float hv = hp[(size_t)t * HDIM];
        if (l > mx) {
            float sc = expf(mx - l);
            se *= sc; s1 *= sc; s2 *= sc;
            mx = l;
        }
        float e = expf(l - mx);
        se += e; s1 += hv * e; s2 += hv * hv * e;
    }
    float* o = g_ppart + (((size_t)b * NSLC + s) * HDIM + ch) * 4;
    o[0] = mx; o[1] = se; o[2] = s1; o[3] = s2;
}
__global__ __launch_bounds__(256) void k_pcomb(const float* __restrict__ bn5g,
                                               const float* __restrict__ bn5b,
                                               const float* __restrict__ fc6_w,
                                               const float* __restrict__ fc6_b,
                                               const float* __restrict__ bn6g,
                                               const float* __restrict__ bn6b,
                                               const float* __restrict__ cls_w,
                                               const float* __restrict__ cls_b,
                                               const float* __restrict__ arn_w2,
                                               float* __restrict__ out_cls, int write_cls)
{
    const int b = blockIdx.x, j = threadIdx.x;
    __shared__ float e[2 * HDIM];
    {
        float mx = -1e30f;
        float pm[NSLC];
        #pragma unroll
        for (int s = 0; s < NSLC; s++) {
            pm[s] = g_ppart[(((size_t)b * NSLC + s) * HDIM + j) * 4];
            mx = fmaxf(mx, pm[s]);
        }
        float se = 0.f, s1 = 0.f, s2 = 0.f;
        #pragma unroll
        for (int s = 0; s < NSLC; s++) {
            const float* o = g_ppart + (((size_t)b * NSLC + s) * HDIM + j) * 4;
            float sc = expf(pm[s] - mx);
            se += o[1] * sc; s1 += o[2] * sc; s2 += o[3] * sc;
        }
        float mu = s1 / se;
        float sg = sqrtf(fmaxf(s2 / se - mu * mu, 1e-4f));
        e[j]        = mu * bn5g[j]        + bn5b[j];
        e[j + HDIM] = sg * bn5g[HDIM + j] + bn5b[HDIM + j];
    }
    __syncthreads();
    float acc = fc6_b[j];
    for (int k = 0; k < 2 * HDIM; k++) acc += e[k] * fc6_w[(size_t)k * FDIM + j];
    const float em = acc * bn6g[j] + bn6b[j];
    g_emb[b * FDIM + j] = em;

    __shared__ float red[256];
    red[j] = em * em;
    __syncthreads();
    for (int st = 128; st > 0; st >>= 1) { if (j < st) red[j] += red[j + st]; __syncthreads(); }
    const float nrmv = fmaxf(sqrtf(red[0]), 1e-12f);
    __shared__ float emv[256];
    emv[j] = em;
    __syncthreads();
    if (write_cls && j < NCLS) {
        float c = cls_b[j];
        for (int k = 0; k < FDIM; k++) c += (emv[k] / nrmv) * cls_w[(size_t)k * NCLS + j];
        out_cls[b * NCLS + j] = c;
    }
    for (int i = 0; i < 4; i++) {
        const float* W = arn_w2 + (size_t)i * FDIM * FDIM;
        float a2 = 0.f;
        for (int k = 0; k < FDIM; k++) a2 += emv[k] * W[(size_t)k * FDIM + j];
        g_evec[((size_t)i * BDIM + b) * FDIM + j] = a2;
    }
}

__global__ __launch_bounds__(256) void k_ola(float* __restrict__ out)
{
    const int idx = blockIdx.x * blockDim.x + threadIdx.x;
    if (idx >= BDIM * LSIG) return;
    const int b = idx / LSIG;
    const int i = idx - b * LSIG;
    const int t = i / SHIFT;
    const int j = i - t * SHIFT;
    const float* yb = g_y + (size_t)b * TIN * FRAME;
    float v = yb[(size_t)t * FRAME + j];
    if (t > 0) { v += yb[(size_t)(t - 1) * FRAME + j + SHIFT]; v *= 0.5f; }
    out[idx] = v;
}

// ---------------- launch ----------------
extern "C" void kernel_launch(void* const* d_in, const int* in_sizes, int n_in,
                              void* d_out, int out_size)
{
    const float* input   = (const float*)d_in[0];
    const float* anchor  = (const float*)d_in[1];
    const int*   aux_len = (const int*)  d_in[2];
    const float* in_w    = (const float*)d_in[4];
    const float* in_b    = (const float*)d_in[5];
    const float* out_w   = (const float*)d_in[6];
    const float* out_b   = (const float*)d_in[7];
    const float* gln_g   = (const float*)d_in[8];
    const float* gln_b   = (const float*)d_in[9];
    const float* ecapa_w = (const float*)d_in[10];
    const float* ecapa_b = (const float*)d_in[11];
    const float* att_w1  = (const float*)d_in[12];
    const float* att_b1  = (const float*)d_in[13];
    const float* attbn_g = (const float*)d_in[14];
    const float* attbn_b = (const float*)d_in[15];
    const float* att_w2  = (const float*)d_in[16];
    const float* att_b2  = (const float*)d_in[17];
    const float* bn5_g   = (const float*)d_in[18];
    const float* bn5_b   = (const float*)d_in[19];
    const float* fc6_w   = (const float*)d_in[20];
    const float* fc6_b   = (const float*)d_in[21];
    const float* bn6_g   = (const float*)d_in[22];
    const float* bn6_b   = (const float*)d_in[23];
    const float* cls_w   = (const float*)d_in[24];
    const float* cls_b   = (const float*)d_in[25];
    const float* arn_w1  = (const float*)d_in[26];
    const float* arn_w2  = (const float*)d_in[27];
    const float* arn_b   = (const float*)d_in[28];

    float *p_out, *p_out2, *p_aux, *p_h, *p_a, *p_logits, *p_y;
    cudaGetSymbolAddress((void**)&p_out,    g_out);
    cudaGetSymbolAddress((void**)&p_out2,   g_out2);
    cudaGetSymbolAddress((void**)&p_aux,    g_aux);
    cudaGetSymbolAddress((void**)&p_h,      g_h);
    cudaGetSymbolAddress((void**)&p_a,      g_a);
    cudaGetSymbolAddress((void**)&p_logits, g_logits);
    cudaGetSymbolAddress((void**)&p_y,      g_y);

    __nv_bfloat16 *pw_in_h, *pw_in_l, *pw_ec_h, *pw_ec_l, *pw_a1_h, *pw_a1_l,
                  *pw_a2_h, *pw_a2_l, *pw_ar_h, *pw_ar_l, *pw_ou_h, *pw_ou_l;
    cudaGetSymbolAddress((void**)&pw_in_h, w_in_hi);  cudaGetSymbolAddress((void**)&pw_in_l, w_in_lo);
    cudaGetSymbolAddress((void**)&pw_ec_h, w_ec_hi);  cudaGetSymbolAddress((void**)&pw_ec_l, w_ec_lo);
    cudaGetSymbolAddress((void**)&pw_a1_h, w_a1_hi);  cudaGetSymbolAddress((void**)&pw_a1_l, w_a1_lo);
    cudaGetSymbolAddress((void**)&pw_a2_h, w_a2_hi);  cudaGetSymbolAddress((void**)&pw_a2_l, w_a2_lo);
    cudaGetSymbolAddress((void**)&pw_ar_h, w_arn_hi); cudaGetSymbolAddress((void**)&pw_ar_l, w_arn_lo);
    cudaGetSymbolAddress((void**)&pw_ou_h, w_out_hi); cudaGetSymbolAddress((void**)&pw_ou_l, w_out_lo);

    // ---- single fused weight-prep (tiled transpose) ----
    PrepArgs pa;
    int toff = 0;
    auto reg = [&](int r, const float* s, __nv_bfloat16* h, __nv_bfloat16* l, int K, int N) {
        pa.src[r] = s; pa.hi[r] = h; pa.lo[r] = l; pa.K[r] = K; pa.N[r] = N;
        pa.toff[r] = toff; toff += (K / 32) * (N / 32);
    };
    reg(0, in_w,    pw_in_h, pw_in_l, 320, 256);
    reg(1, ecapa_w, pw_ec_h, pw_ec_l, 256, 256);
    reg(2, att_w1,  pw_a1_h, pw_a1_l, 256, 256);
    reg(3, att_w2,  pw_a2_h, pw_a2_l, 256, 256);
    for (int i = 0; i < 4; i++)
        reg(4 + i, arn_w1 + (size_t)i * 65536, pw_ar_h + (size_t)i * 65536,
            pw_ar_l + (size_t)i * 65536, 256, 256);
    reg(8, out_w, pw_ou_h, pw_ou_l, 256, 320);
    pa.toff[9] = toff;
    pa.src[9] = out_w; pa.hi[9] = pw_ou_h; pa.lo[9] = pw_ou_l; pa.K[9] = 256; pa.N[9] = 320;
    pa.toff[10] = toff;
    k_prep_all<<<toff, 256>>>(pa);

    constexpr int KS = 72;
    const int SM128 = 2 * (64 * KS * 2) + 4 * (128 * KS * 2);   // 92160
    const int SM160 = 2 * (64 * KS * 2) + 4 * (160 * KS * 2);   // 110592
    cudaFuncSetAttribute(k_tgemm<128,0>, cudaFuncAttributeMaxDynamicSharedMemorySize, SM128);
    cudaFuncSetAttribute(k_tgemm<128,1>, cudaFuncAttributeMaxDynamicSharedMemorySize, SM128);
    cudaFuncSetAttribute(k_tgemm<128,2>, cudaFuncAttributeMaxDynamicSharedMemorySize, SM128);
    cudaFuncSetAttribute(k_tgemm<128,3>, cudaFuncAttributeMaxDynamicSharedMemorySize, SM128);
    cudaFuncSetAttribute(k_tgemm<128,4>, cudaFuncAttributeMaxDynamicSharedMemorySize, SM128);
    cudaFuncSetAttribute(k_tgemm<160,3>, cudaFuncAttributeMaxDynamicSharedMemorySize, SM160);

    // 1. merged encoders: x blocks [0,16) -> input, [16,23) -> anchor; z = 2 N-halves
    k_tgemm<128,0><<<dim3(23, 32, 2), 256, SM128>>>(input, pw_in_h, pw_in_l, p_out, in_b,
                                                    nullptr, nullptr, nullptr, TIN, FRAME, FDIM, LSIG, 0,
                                                    anchor, p_aux, TA, LAUX, 16);
    // 2. GLN partials (combine folded into next GEMM)
    k_gln_part<<<dim3(32, 16), 256>>>(aux_len);
    // 3. GLN + ecapa + relu
    k_tgemm<128,1><<<dim3(7, 32, 2), 256, SM128>>>(p_aux, pw_ec_h, pw_ec_l, p_h, gln_g, gln_b,
                                                   ecapa_b, aux_len, TA, FDIM, HDIM, 0, 0,
                                                   nullptr, nullptr, 0, 0, 0);
    // 4. h stats + attention bias
    k_hpart<<<dim3(32, NSLC), 256>>>(aux_len);
    k_hcomb<<<32, 256>>>(aux_len, att_w1, att_b1);
    // 5. attention conv1(+relu+bn+tanh)
    k_tgemm<128,2><<<dim3(7, 32, 2), 256, SM128>>>(p_h, pw_a1_h, pw_a1_l, p_a, attbn_g, attbn_b,
                                                   nullptr, nullptr, TA, HDIM, HDIM, 0, 0,
                                                   nullptr, nullptr, 0, 0, 0);
    // 6. attention conv2
    k_tgemm<128,3><<<dim3(7, 32, 2), 256, SM128>>>(p_a, pw_a2_h, pw_a2_l, p_logits, att_b2,
                                                   nullptr, nullptr, nullptr, TA, HDIM, HDIM, 0, 0,
                                                   nullptr, nullptr, 0, 0, 0);
    // 7. pool + emb + classifier + evec
    k_ppart<<<dim3(32, NSLC), 256>>>(aux_len);
    const int write_cls = (out_size >= BDIM * LSIG + BDIM * NCLS) ? 1 : 0;
    k_pcomb<<<32, 256>>>(bn5_g, bn5_b, fc6_w, fc6_b, bn6_g, bn6_b, cls_w, cls_b,
                         arn_w2, (float*)d_out + (size_t)BDIM * LSIG, write_cls);
    // 8-11. 4 ARN residual blocks (ping-pong)
    const float* src = p_out;
    float*       dst = p_out2;
    for (int i = 0; i < 4; i++) {
        k_tgemm<128,4><<<dim3(16, 32, 2), 256, SM128>>>(src, pw_ar_h + (size_t)i * 65536,
                                                        pw_ar_l + (size_t)i * 65536, dst,
                                                        arn_b + i * FDIM, nullptr, nullptr,
                                                        nullptr, TIN, FDIM, FDIM, 0, i,
                                                        nullptr, nullptr, 0, 0, 0);
        const float* tmp = dst; dst = (float*)src; src = tmp;
    }
    // 12. decoder (N=320 in two 160-col halves)
    k_tgemm<160,3><<<dim3(16, 32, 2), 256, SM160>>>(src, pw_ou_h, pw_ou_l, p_y, out_b,
                                                    nullptr, nullptr, nullptr, TIN, FDIM, FRAME, 0, 0,
                                                    nullptr, nullptr, 0, 0, 0);
    // 13. OLA
    k_ola<<<(BDIM * LSIG + 255) / 256, 256>>>((float*)d_out);
}

// round 8
// speedup vs baseline: 2.0266x; 1.0706x over previous
#include <cuda_runtime.h>
#include <cuda_bf16.h>
#include <math.h>
#include <stdint.h>

#define BDIM   32
#define TIN    1000
#define TA     400
#define FDIM   256
#define HDIM   256
#define FRAME  320
#define SHIFT  160
#define LSIG   160000
#define LAUX   64000
#define NCLS   101
#define NSLC   8
#define SLC    (TA / NSLC)

// ---------------- scratch ----------------
__device__ float g_out   [BDIM * TIN * FDIM];
__device__ float g_out2  [BDIM * TIN * FDIM];
__device__ float g_aux   [BDIM * TA  * FDIM];
__device__ float g_h     [BDIM * TA  * HDIM];
__device__ float g_a     [BDIM * TA  * HDIM];
__device__ float g_logits[BDIM * TA  * HDIM];
__device__ float g_y     [BDIM * TIN * FRAME];
__device__ float g_bias2 [BDIM * HDIM];
__device__ float g_emb   [BDIM * FDIM];
__device__ float g_evec  [4 * BDIM * FDIM];
__device__ float g_glnp  [BDIM * 16 * 2];
__device__ float g_hpart [BDIM * NSLC * HDIM * 2];
__device__ float g_ppart [BDIM * NSLC * HDIM * 4];

// bf16 split weight planes, layout [N][K]
__device__ __nv_bfloat16 w_in_hi [256 * 320];
__device__ __nv_bfloat16 w_in_lo [256 * 320];
__device__ __nv_bfloat16 w_ec_hi [256 * 256];
__device__ __nv_bfloat16 w_ec_lo [256 * 256];
__device__ __nv_bfloat16 w_a1_hi [256 * 256];
__device__ __nv_bfloat16 w_a1_lo [256 * 256];
__device__ __nv_bfloat16 w_a2_hi [256 * 256];
__device__ __nv_bfloat16 w_a2_lo [256 * 256];
__device__ __nv_bfloat16 w_arn_hi[4 * 256 * 256];
__device__ __nv_bfloat16 w_arn_lo[4 * 256 * 256];
__device__ __nv_bfloat16 w_out_hi[320 * 256];
__device__ __nv_bfloat16 w_out_lo[320 * 256];

// ---------------- helpers ----------------
__device__ __forceinline__ uint32_t smem_u32(const void* p) {
    uint32_t a;
    asm("{ .reg .u64 t; cvta.to.shared.u64 t, %1; cvt.u32.u64 %0, t; }" : "=r"(a) : "l"(p));
    return a;
}
__device__ __forceinline__ void ldmx4(uint32_t* r, uint32_t addr) {
    asm volatile("ldmatrix.sync.aligned.m8n8.x4.shared.b16 {%0,%1,%2,%3}, [%4];"
                 : "=r"(r[0]), "=r"(r[1]), "=r"(r[2]), "=r"(r[3]) : "r"(addr));
}
__device__ __forceinline__ void ldmx2(uint32_t* r, uint32_t addr) {
    asm volatile("ldmatrix.sync.aligned.m8n8.x2.shared.b16 {%0,%1}, [%2];"
                 : "=r"(r[0]), "=r"(r[1]) : "r"(addr));
}
__device__ __forceinline__ void mma_bf16(float* c, const uint32_t* a, const uint32_t* b) {
    asm volatile("mma.sync.aligned.m16n8k16.row.col.f32.bf16.bf16.f32 "
                 "{%0,%1,%2,%3}, {%4,%5,%6,%7}, {%8,%9}, {%0,%1,%2,%3};"
                 : "+f"(c[0]), "+f"(c[1]), "+f"(c[2]), "+f"(c[3])
                 : "r"(a[0]), "r"(a[1]), "r"(a[2]), "r"(a[3]), "r"(b[0]), "r"(b[1]));
}
__device__ __forceinline__ void cp16(uint32_t saddr, const void* gaddr) {
    asm volatile("cp.async.ca.shared.global [%0], [%1], 16;" :: "r"(saddr), "l"(gaddr));
}
__device__ __forceinline__ void cp_commit() { asm volatile("cp.async.commit_group;" ::: "memory"); }
template<int W> __device__ __forceinline__ void cp_wait() {
    asm volatile("cp.async.wait_group %0;" :: "n"(W) : "memory");
}
// 128B rows, XOR swizzle on 16B chunks: byte offset of (row, chunk)
__device__ __forceinline__ uint32_t SWZ(int row, int chunk) {
    return ((uint32_t)row << 7) + ((uint32_t)((chunk ^ (row & 7)) & 7) << 4);
}

// ---------------- weight prep: tiled transpose + split ----------------
struct PrepArgs {
    const float* src[10];
    __nv_bfloat16* hi[10];
    __nv_bfloat16* lo[10];
    int K[10];
    int N[10];
    int toff[11];
};
__global__ __launch_bounds__(256) void k_prep_all(PrepArgs a)
{
    __shared__ float tile[32][33];
    int tb = blockIdx.x;
    int r = 0;
    while (tb >= a.toff[r + 1]) r++;
    int ti = tb - a.toff[r];
    const int K = a.K[r], N = a.N[r];
    const int ntn = N / 32;
    const int tk = ti / ntn, tn = ti - tk * ntn;
    const int ty = threadIdx.x >> 5, tx = threadIdx.x & 31;
    #pragma unroll
    for (int q = 0; q < 4; q++) {
        const int k = tk * 32 + ty + q * 8;
        tile[ty + q * 8][tx] = a.src[r][(size_t)k * N + tn * 32 + tx];
    }
    __syncthreads();
    #pragma unroll
    for (int q = 0; q < 4; q++) {
        const int n = tn * 32 + ty + q * 8;
        float x = tile[tx][ty + q * 8];
        __nv_bfloat16 h = __float2bfloat16(x);
        const size_t o = (size_t)n * K + tk * 32 + tx;
        a.hi[r][o] = h;
        a.lo[r][o] = __float2bfloat16(x - __bfloat162float(h));
    }
}

// ---------------- tensor-core GEMM: 256 threads, MT=64, swizzled 48KB smem, 3 CTAs/SM ----------------
template<int NT, int MODE>
__global__ void __launch_bounds__(256, 3) k_tgemm(
    const float* __restrict__ Ain,
    const __nv_bfloat16* __restrict__ Bhi, const __nv_bfloat16* __restrict__ Blo,
    float* __restrict__ Cin,
    const float* __restrict__ e0, const float* __restrict__ e1, const float* __restrict__ e2,
    const int* __restrict__ aux_len, int Min, int K, int Nfull, int Lin, int arn_i,
    const float* A2, float* C2, int M2, int L2, int split)
{
    constexpr int MT   = 64;
    constexpr int WN   = NT / 4;     // 32 or 40
    constexpr int NF   = WN / 8;     // 4 or 5
    constexpr int MI   = 2;
    constexpr int APL  = MT * 128;   // 8192 B per A plane
    constexpr int BPL  = NT * 128;   // B plane bytes

    extern __shared__ char smem[];
    const uint32_t sb = smem_u32(smem);
    const uint32_t aH = sb;
    const uint32_t aL = sb + APL;
    const uint32_t bH = sb + 2 * APL;
    const uint32_t bL = sb + 2 * APL + BPL;

    const int tid  = threadIdx.x;
    const int w    = tid >> 5;
    const int lane = tid & 31;
    const int b    = blockIdx.y;
    const int nbase = blockIdx.z * NT;

    const float* A = Ain;
    float* C = Cin;
    int M = Min, L = Lin;
    int bx = blockIdx.x;
    if (MODE == 0 && split > 0 && bx >= split) {
        A = A2; C = C2; M = M2; L = L2; bx -= split;
    }
    const int t0 = bx * MT;
    const int NB = K / 64;
    const int wm = w >> 2;
    const int wn = w & 3;
    const int wn0 = wn * WN;

    int   len  = 0;
    float mean = 0.f, inv = 0.f;
    if (MODE == 1) {
        len = aux_len[b];
        double s = 0.0, q = 0.0;
        #pragma unroll
        for (int i = 0; i < 16; i++) {
            s += (double)g_glnp[(b * 16 + i) * 2 + 0];
            q += (double)g_glnp[(b * 16 + i) * 2 + 1];
        }
        const double n = (double)len * FDIM;
        double m = s / n;
        double var = q / n - m * m;
        mean = (float)m;
        inv  = (float)(1.0 / sqrt(var + 1e-5));
    }

    const int arow = tid >> 2;              // 0..63
    const int achk = (tid & 3) * 2;         // first of 2 chunks this thread covers
    const int ac0  = achk * 8;              // fp32 col base (16 cols per thread)

    float acc[MI][NF][4];
    #pragma unroll
    for (int mi = 0; mi < MI; mi++)
        #pragma unroll
        for (int nj = 0; nj < NF; nj++)
            #pragma unroll
            for (int q = 0; q < 4; q++) acc[mi][nj][q] = 0.f;

    // ---- stage A: global load + GLN transform + bf16 split + swizzled STS ----
    auto stageA = [&](int kb) {
        const int t = t0 + arow;
        float va[16];
        if (MODE == 0) {
            if (t < M) {
                const float* src = A + (size_t)b * L;
                const int base = t * SHIFT + kb * 64 + ac0;
                #pragma unroll
                for (int q = 0; q < 4; q++) {
                    const int p = base + q * 4;
                    if (p + 3 < L) {
                        float4 f = *(const float4*)(src + p);
                        va[q*4+0]=f.x; va[q*4+1]=f.y; va[q*4+2]=f.z; va[q*4+3]=f.w;
                    } else {
                        #pragma unroll
                        for (int j = 0; j < 4; j++) va[q*4+j] = (p + j < L) ? src[p + j] : 0.f;
                    }
                }
            } else {
                #pragma unroll
                for (int j = 0; j < 16; j++) va[j] = 0.f;
            }
        } else {
            const bool valid = (MODE == 1) ? (t < len) : (t < M);
            if (valid) {
                const float* src = A + ((size_t)b * M + t) * K + kb * 64 + ac0;
                #pragma unroll
                for (int q = 0; q < 4; q++) {
                    float4 f = *(const float4*)(src + q * 4);
                    va[q*4+0]=f.x; va[q*4+1]=f.y; va[q*4+2]=f.z; va[q*4+3]=f.w;
                }
                if (MODE == 1) {
                    const int c0 = kb * 64 + ac0;
                    #pragma unroll
                    for (int q = 0; q < 4; q++) {
                        float4 gg = *(const float4*)(e0 + c0 + q * 4);
                        float4 gb = *(const float4*)(e1 + c0 + q * 4);
                        va[q*4+0] = gg.x * inv * (va[q*4+0] - mean) + gb.x;
                        va[q*4+1] = gg.y * inv * (va[q*4+1] - mean) + gb.y;
                        va[q*4+2] = gg.z * inv * (va[q*4+2] - mean) + gb.z;
                        va[q*4+3] = gg.w * inv * (va[q*4+3] - mean) + gb.w;
                    }
                }
            } else {
                #pragma unroll
                for (int j = 0; j < 16; j++) va[j] = 0.f;
            }
        }
        #pragma unroll
        for (int q = 0; q < 2; q++) {
            union { __nv_bfloat16 x[8]; uint4 v; } H, Lo;
            #pragma unroll
            for (int j = 0; j < 8; j++) {
                float f = va[q * 8 + j];
                __nv_bfloat16 hb = __float2bfloat16(f);
                H.x[j]  = hb;
                Lo.x[j] = __float2bfloat16(f - __bfloat162float(hb));
            }
            const uint32_t so = SWZ(arow, achk + q);
            *(uint4*)(smem + so)       = H.v;
            *(uint4*)(smem + APL + so) = Lo.v;
        }
    };
    auto cpB = [&](int kb) {
        for (int idx = tid; idx < NT * 8; idx += 256) {
            const int n = idx >> 3, c = idx & 7;
            const uint32_t so = SWZ(n, c);
            cp16(bH + so, Bhi + (size_t)(nbase + n) * K + kb * 64 + c * 8);
            cp16(bL + so, Blo + (size_t)(nbase + n) * K + kb * 64 + c * 8);
        }
    };
    auto compute = [&]() {
        #pragma unroll
        for (int ki = 0; ki < 4; ki++) {
            uint32_t bh[NF][2], bl[NF][2];
            #pragma unroll
            for (int p = 0; p < NF / 2; p++) {
                const int g = lane >> 3;
                const int nrow = wn0 + p * 16 + ((g >> 1) << 3) + (lane & 7);
                const int chunk = ki * 2 + (g & 1);
                const uint32_t off = SWZ(nrow, chunk);
                uint32_t r4[4];
                ldmx4(r4, bH + off);
                bh[2*p][0]=r4[0]; bh[2*p][1]=r4[1]; bh[2*p+1][0]=r4[2]; bh[2*p+1][1]=r4[3];
                ldmx4(r4, bL + off);
                bl[2*p][0]=r4[0]; bl[2*p][1]=r4[1]; bl[2*p+1][0]=r4[2]; bl[2*p+1][1]=r4[3];
            }
            if (NF & 1) {
                const int nj = NF - 1;
                const int nrow = wn0 + nj * 8 + (lane & 7);
                const int chunk = ki * 2 + ((lane & 15) >> 3);
                const uint32_t off = SWZ(nrow, chunk);
                ldmx2(bh[nj], bH + off);
                ldmx2(bl[nj], bL + off);
            }
            #pragma unroll
            for (int mi = 0; mi < MI; mi++) {
                uint32_t ah[4], al[4];
                const int row = wm * 32 + mi * 16 + (lane & 15);
                const int chunk = ki * 2 + (lane >> 4);
                const uint32_t off = SWZ(row, chunk);
                ldmx4(ah, aH + off);
                ldmx4(al, aL + off);
                #pragma unroll
                for (int nj = 0; nj < NF; nj++) {
                    mma_bf16(acc[mi][nj], ah, bh[nj]);
                    mma_bf16(acc[mi][nj], ah, bl[nj]);
                    mma_bf16(acc[mi][nj], al, bh[nj]);
                }
            }
        }
    };

    for (int kb = 0; kb < NB; kb++) {
        cpB(kb);
        cp_commit();
        stageA(kb);
        cp_wait<0>();
        __syncthreads();
        compute();
        __syncthreads();
    }

    #pragma unroll
    for (int mi = 0; mi < MI; mi++) {
        #pragma unroll
        for (int half = 0; half < 2; half++) {
            const int r = wm * 32 + mi * 16 + (lane >> 2) + half * 8;
            const int t = t0 + r;
            if (t >= M) continue;
            #pragma unroll
            for (int nj = 0; nj < NF; nj++) {
                const int col = nbase + wn0 + nj * 8 + (lane & 3) * 2;
                float v0 = acc[mi][nj][half * 2 + 0];
                float v1 = acc[mi][nj][half * 2 + 1];
                float r0, r1;
                if (MODE == 0) {
                    r0 = v0 + e0[col]; r1 = v1 + e0[col + 1];
                } else if (MODE == 1) {
                    if (t < len) { r0 = fmaxf(v0 + e2[col], 0.f); r1 = fmaxf(v1 + e2[col + 1], 0.f); }
                    else         { r0 = 0.f; r1 = 0.f; }
                } else if (MODE == 2) {
                    float a0 = fmaxf(v0 + g_bias2[b * HDIM + col],     0.f);
                    float a1 = fmaxf(v1 + g_bias2[b * HDIM + col + 1], 0.f);
                    r0 = tanhf(a0 * e0[col]     + e1[col]);
                    r1 = tanhf(a1 * e0[col + 1] + e1[col + 1]);
                } else if (MODE == 3) {
                    r0 = v0 + e0[col]; r1 = v1 + e0[col + 1];
                } else {
                    const float* ares = A + ((size_t)b * M + t) * K + col;
                    const float* ev   = g_evec + ((size_t)arn_i * BDIM + b) * FDIM + col;
                    r0 = ares[0] + tanhf(v0 + ev[0] + e0[col]);
                    r1 = ares[1] + tanhf(v1 + ev[1] + e0[col + 1]);
                }
                *(float2*)(C + ((size_t)b * M + t) * Nfull + col) = make_float2(r0, r1);
            }
        }
    }
}

// ---------------- GLN partials ----------------
__global__ __launch_bounds__(256) void k_gln_part(const int* __restrict__ aux_len)
{
    const int b = blockIdx.x, s = blockIdx.y;
    const int len = aux_len[b];
    const int tA = s * (TA / 16);
    const int tB = min(len, tA + TA / 16);
    float sum = 0.f, sq = 0.f;
    if (tB > tA) {
        const float* p = g_aux + ((size_t)b * TA + tA) * FDIM;
        const int n = (tB - tA) * FDIM;
        for (int i = threadIdx.x; i < n; i += 256) {
            float v = p[i];
            sum += v; sq += v * v;
        }
    }
    __shared__ float ss[256], qq[256];
    ss[threadIdx.x] = sum; qq[threadIdx.x] = sq;
    __syncthreads();
    for (int st = 128; st > 0; st >>= 1) {
        if (threadIdx.x < st) { ss[threadIdx.x] += ss[threadIdx.x + st]; qq[threadIdx.x] += qq[threadIdx.x + st]; }
        __syncthreads();
    }
    if (threadIdx.x == 0) {
        g_glnp[(b * 16 + s) * 2 + 0] = ss[0];
        g_glnp[(b * 16 + s) * 2 + 1] = qq[0];
    }
}

// ---------------- h stats partials + combine ----------------
__global__ __launch_bounds__(256) void k_hpart(const int* __restrict__ aux_len)
{
    const int b = blockIdx.x, s = blockIdx.y, ch = threadIdx.x;
    const int len = aux_len[b];
    const int tA = s * SLC;
    const int tB = min(len, tA + SLC);
    float sum = 0.f, sq = 0.f;
    const float* p = g_h + ((size_t)b * TA) * HDIM + ch;
    for (int t = tA; t < tB; t++) {
        float v = p[(size_t)t * HDIM];
        sum += v; sq += v * v;
    }
    float* o = g_hpart + (((size_t)b * NSLC + s) * HDIM + ch) * 2;
    o[0] = sum; o[1] = sq;
}
__global__ __launch_bounds__(256) void k_hcomb(const int* __restrict__ aux_len,
                                               const float* __restrict__ att_w1,
                                               const float* __restrict__ att_b1)
{
    const int b = blockIdx.x, ch = threadIdx.x;
    const int len = aux_len[b];
    __shared__ float sm[256], sstd[256];
    {
        float sum = 0.f, sq = 0.f;
        #pragma unroll
        for (int s = 0; s < NSLC; s++) {
            const float* o = g_hpart + (((size_t)b * NSLC + s) * HDIM + ch) * 2;
            sum += o[0]; sq += o[1];
        }
        const float n = (float)len;
        const float m = sum / n;
        const float var = (sq - n * m * m) / (n - 1.f);
        sm[ch] = m;
        sstd[ch] = sqrtf(fmaxf(var, 1e-4f));
    }
    __syncthreads();
    float acc = att_b1[ch];
    for (int k = 0; k < HDIM; k++) {
        acc += sm[k]   * att_w1[(size_t)(256 + k) * HDIM + ch]
             + sstd[k] * att_w1[(size_t)(512 + k) * HDIM + ch];
    }
    g_bias2[b * HDIM + ch] = acc;
}

// ---------------- pool partials + combine ----------------
__global__ __launch_bounds__(256) void k_ppart(const int* __restrict__ aux_len)
{
    const int b = blockIdx.x, s = blockIdx.y, ch = threadIdx.x;
    const int len = aux_len[b];
    const int tA = s * SLC;
    const int tB = min(len, tA + SLC);
    const float* lp = g_logits + (size_t)b * TA * HDIM + ch;
    const float* hp = g_h      + (size_t)b * TA * HDIM + ch;
    float mx = -1e30f, se = 0.f, s1 = 0.f, s2 = 0.f;
    for (int t = tA; t < tB; t++) {
        float l  = lp[(size_t)t * HDIM];
        float hv = hp[(size_t)t * HDIM];
        if (l > mx) {
            float sc = expf(mx - l);
            se *= sc; s1 *= sc; s2 *= sc;
            mx = l;
        }
        float e = expf(l - mx);
        se += e; s1 += hv * e; s2 += hv * hv * e;
    }
    float* o = g_ppart + (((size_t)b * NSLC + s) * HDIM + ch) * 4;
    o[0] = mx; o[1] = se; o[2] = s1; o[3] = s2;
}
__global__ __launch_bounds__(256) void k_pcomb(const float* __restrict__ bn5g,
                                               const float* __restrict__ bn5b,
                                               const float* __restrict__ fc6_w,
                                               const float* __restrict__ fc6_b,
                                               const float* __restrict__ bn6g,
                                               const float* __restrict__ bn6b,
                                               const float* __restrict__ cls_w,
                                               const float* __restrict__ cls_b,
                                               const float* __restrict__ arn_w2,
                                               float* __restrict__ out_cls, int write_cls)
{
    const int b = blockIdx.x, j = threadIdx.x;
    __shared__ float e[2 * HDIM];
    {
        float mx = -1e30f;
        float pm[NSLC];
        #pragma unroll
        for (int s = 0; s < NSLC; s++) {
            pm[s] = g_ppart[(((size_t)b * NSLC + s) * HDIM + j) * 4];
            mx = fmaxf(mx, pm[s]);
        }
        float se = 0.f, s1 = 0.f, s2 = 0.f;
        #pragma unroll
        for (int s = 0; s < NSLC; s++) {
            const float* o = g_ppart + (((size_t)b * NSLC + s) * HDIM + j) * 4;
            float sc = expf(pm[s] - mx);
            se += o[1] * sc; s1 += o[2] * sc; s2 += o[3] * sc;
        }
        float mu = s1 / se;
        float sg = sqrtf(fmaxf(s2 / se - mu * mu, 1e-4f));
        e[j]        = mu * bn5g[j]        + bn5b[j];
        e[j + HDIM] = sg * bn5g[HDIM + j] + bn5b[HDIM + j];
    }
    __syncthreads();
    float acc = fc6_b[j];
    for (int k = 0; k < 2 * HDIM; k++) acc += e[k] * fc6_w[(size_t)k * FDIM + j];
    const float em = acc * bn6g[j] + bn6b[j];
    g_emb[b * FDIM + j] = em;

    __shared__ float red[256];
    red[j] = em * em;
    __syncthreads();
    for (int st = 128; st > 0; st >>= 1) { if (j < st) red[j] += red[j + st]; __syncthreads(); }
    const float nrmv = fmaxf(sqrtf(red[0]), 1e-12f);
    __shared__ float emv[256];
    emv[j] = em;
    __syncthreads();
    if (write_cls && j < NCLS) {
        float c = cls_b[j];
        for (int k = 0; k < FDIM; k++) c += (emv[k] / nrmv) * cls_w[(size_t)k * NCLS + j];
        out_cls[b * NCLS + j] = c;
    }
    for (int i = 0; i < 4; i++) {
        const float* W = arn_w2 + (size_t)i * FDIM * FDIM;
        float a2 = 0.f;
        for (int k = 0; k < FDIM; k++) a2 += emv[k] * W[(size_t)k * FDIM + j];
        g_evec[((size_t)i * BDIM + b) * FDIM + j] = a2;
    }
}

__global__ __launch_bounds__(256) void k_ola(float* __restrict__ out)
{
    const int idx = blockIdx.x * blockDim.x + threadIdx.x;
    if (idx >= BDIM * LSIG) return;
    const int b = idx / LSIG;
    const int i = idx - b * LSIG;
    const int t = i / SHIFT;
    const int j = i - t * SHIFT;
    const float* yb = g_y + (size_t)b * TIN * FRAME;
    float v = yb[(size_t)t * FRAME + j];
    if (t > 0) { v += yb[(size_t)(t - 1) * FRAME + j + SHIFT]; v *= 0.5f; }
    out[idx] = v;
}

// ---------------- launch ----------------
extern "C" void kernel_launch(void* const* d_in, const int* in_sizes, int n_in,
                              void* d_out, int out_size)
{
    const float* input   = (const float*)d_in[0];
    const float* anchor  = (const float*)d_in[1];
    const int*   aux_len = (const int*)  d_in[2];
    const float* in_w    = (const float*)d_in[4];
    const float* in_b    = (const float*)d_in[5];
    const float* out_w   = (const float*)d_in[6];
    const float* out_b   = (const float*)d_in[7];
    const float* gln_g   = (const float*)d_in[8];
    const float* gln_b   = (const float*)d_in[9];
    const float* ecapa_w = (const float*)d_in[10];
    const float* ecapa_b = (const float*)d_in[11];
    const float* att_w1  = (const float*)d_in[12];
    const float* att_b1  = (const float*)d_in[13];
    const float* attbn_g = (const float*)d_in[14];
    const float* attbn_b = (const float*)d_in[15];
    const float* att_w2  = (const float*)d_in[16];
    const float* att_b2  = (const float*)d_in[17];
    const float* bn5_g   = (const float*)d_in[18];
    const float* bn5_b   = (const float*)d_in[19];
    const float* fc6_w   = (const float*)d_in[20];
    const float* fc6_b   = (const float*)d_in[21];
    const float* bn6_g   = (const float*)d_in[22];
    const float* bn6_b   = (const float*)d_in[23];
    const float* cls_w   = (const float*)d_in[24];
    const float* cls_b   = (const float*)d_in[25];
    const float* arn_w1  = (const float*)d_in[26];
    const float* arn_w2  = (const float*)d_in[27];
    const float* arn_b   = (const float*)d_in[28];

    float *p_out, *p_out2, *p_aux, *p_h, *p_a, *p_logits, *p_y;
    cudaGetSymbolAddress((void**)&p_out,    g_out);
    cudaGetSymbolAddress((void**)&p_out2,   g_out2);
    cudaGetSymbolAddress((void**)&p_aux,    g_aux);
    cudaGetSymbolAddress((void**)&p_h,      g_h);
    cudaGetSymbolAddress((void**)&p_a,      g_a);
    cudaGetSymbolAddress((void**)&p_logits, g_logits);
    cudaGetSymbolAddress((void**)&p_y,      g_y);

    __nv_bfloat16 *pw_in_h, *pw_in_l, *pw_ec_h, *pw_ec_l, *pw_a1_h, *pw_a1_l,
                  *pw_a2_h, *pw_a2_l, *pw_ar_h, *pw_ar_l, *pw_ou_h, *pw_ou_l;
    cudaGetSymbolAddress((void**)&pw_in_h, w_in_hi);  cudaGetSymbolAddress((void**)&pw_in_l, w_in_lo);
    cudaGetSymbolAddress((void**)&pw_ec_h, w_ec_hi);  cudaGetSymbolAddress((void**)&pw_ec_l, w_ec_lo);
    cudaGetSymbolAddress((void**)&pw_a1_h, w_a1_hi);  cudaGetSymbolAddress((void**)&pw_a1_l, w_a1_lo);
    cudaGetSymbolAddress((void**)&pw_a2_h, w_a2_hi);  cudaGetSymbolAddress((void**)&pw_a2_l, w_a2_lo);
    cudaGetSymbolAddress((void**)&pw_ar_h, w_arn_hi); cudaGetSymbolAddress((void**)&pw_ar_l, w_arn_lo);
    cudaGetSymbolAddress((void**)&pw_ou_h, w_out_hi); cudaGetSymbolAddress((void**)&pw_ou_l, w_out_lo);

    // ---- single fused weight-prep (tiled transpose) ----
    PrepArgs pa;
    int toff = 0;
    auto reg = [&](int r, const float* s, __nv_bfloat16* h, __nv_bfloat16* l, int K, int N) {
        pa.src[r] = s; pa.hi[r] = h; pa.lo[r] = l; pa.K[r] = K; pa.N[r] = N;
        pa.toff[r] = toff; toff += (K / 32) * (N / 32);
    };
    reg(0, in_w,    pw_in_h, pw_in_l, 320, 256);
    reg(1, ecapa_w, pw_ec_h, pw_ec_l, 256, 256);
    reg(2, att_w1,  pw_a1_h, pw_a1_l, 256, 256);
    reg(3, att_w2,  pw_a2_h, pw_a2_l, 256, 256);
    for (int i = 0; i < 4; i++)
        reg(4 + i, arn_w1 + (size_t)i * 65536, pw_ar_h + (size_t)i * 65536,
            pw_ar_l + (size_t)i * 65536, 256, 256);
    reg(8, out_w, pw_ou_h, pw_ou_l, 256, 320);
    pa.toff[9] = toff;
    pa.src[9] = out_w; pa.hi[9] = pw_ou_h; pa.lo[9] = pw_ou_l; pa.K[9] = 256; pa.N[9] = 320;
    pa.toff[10] = toff;
    k_prep_all<<<toff, 256>>>(pa);

    const int SM128 = 2 * (64 * 128) + 2 * (128 * 128);   // 49152
    const int SM160 = 2 * (64 * 128) + 2 * (160 * 128);   // 57344
    cudaFuncSetAttribute(k_tgemm<128,0>, cudaFuncAttributeMaxDynamicSharedMemorySize, SM128);
    cudaFuncSetAttribute(k_tgemm<128,1>, cudaFuncAttributeMaxDynamicSharedMemorySize, SM128);
    cudaFuncSetAttribute(k_tgemm<128,2>, cudaFuncAttributeMaxDynamicSharedMemorySize, SM128);
    cudaFuncSetAttribute(k_tgemm<128,3>, cudaFuncAttributeMaxDynamicSharedMemorySize, SM128);
    cudaFuncSetAttribute(k_tgemm<128,4>, cudaFuncAttributeMaxDynamicSharedMemorySize, SM128);
    cudaFuncSetAttribute(k_tgemm<160,3>, cudaFuncAttributeMaxDynamicSharedMemorySize, SM160);

    // 1. merged encoders: x blocks [0,16) -> input, [16,23) -> anchor; z = 2 N-halves
    k_tgemm<128,0><<<dim3(23, 32, 2), 256, SM128>>>(input, pw_in_h, pw_in_l, p_out, in_b,
                                                    nullptr, nullptr, nullptr, TIN, FRAME, FDIM, LSIG, 0,
                                                    anchor, p_aux, TA, LAUX, 16);
    // 2. GLN partials (combine folded into next GEMM)
    k_gln_part<<<dim3(32, 16), 256>>>(aux_len);
    // 3. GLN + ecapa + relu
    k_tgemm<128,1><<<dim3(7, 32, 2), 256, SM128>>>(p_aux, pw_ec_h, pw_ec_l, p_h, gln_g, gln_b,
                                                   ecapa_b, aux_len, TA, FDIM, HDIM, 0, 0,
                                                   nullptr, nullptr, 0, 0, 0);
    // 4. h stats + attention bias
    k_hpart<<<dim3(32, NSLC), 256>>>(aux_len);
    k_hcomb<<<32, 256>>>(aux_len, att_w1, att_b1);
    // 5. attention conv1(+relu+bn+tanh)
    k_tgemm<128,2><<<dim3(7, 32, 2), 256, SM128>>>(p_h, pw_a1_h, pw_a1_l, p_a, attbn_g, attbn_b,
                                                   nullptr, nullptr, TA, HDIM, HDIM, 0, 0,
                                                   nullptr, nullptr, 0, 0, 0);
    // 6. attention conv2
    k_tgemm<128,3><<<dim3(7, 32, 2), 256, SM128>>>(p_a, pw_a2_h, pw_a2_l, p_logits, att_b2,
                                                   nullptr, nullptr, nullptr, TA, HDIM, HDIM, 0, 0,
                                                   nullptr, nullptr, 0, 0, 0);
    // 7. pool + emb + classifier + evec
    k_ppart<<<dim3(32, NSLC), 256>>>(aux_len);
    const int write_cls = (out_size >= BDIM * LSIG + BDIM * NCLS) ? 1 : 0;
    k_pcomb<<<32, 256>>>(bn5_g, bn5_b, fc6_w, fc6_b, bn6_g, bn6_b, cls_w, cls_b,
                         arn_w2, (float*)d_out + (size_t)BDIM * LSIG, write_cls);
    // 8-11. 4 ARN residual blocks (ping-pong)
    const float* src = p_out;
    float*       dst = p_out2;
    for (int i = 0; i < 4; i++) {
        k_tgemm<128,4><<<dim3(16, 32, 2), 256, SM128>>>(src, pw_ar_h + (size_t)i * 65536,
                                                        pw_ar_l + (size_t)i * 65536, dst,
                                                        arn_b + i * FDIM, nullptr, nullptr,
                                                        nullptr, TIN, FDIM, FDIM, 0, i,
                                                        nullptr, nullptr, 0, 0, 0);
        const float* tmp = dst; dst = (float*)src; src = tmp;
    }
    // 12. decoder (N=320 in two 160-col halves)
    k_tgemm<160,3><<<dim3(16, 32, 2), 256, SM160>>>(src, pw_ou_h, pw_ou_l, p_y, out_b,
                                                    nullptr, nullptr, nullptr, TIN, FDIM, FRAME, 0, 0,
                                                    nullptr, nullptr, 0, 0, 0);
    // 13. OLA
    k_ola<<<(BDIM * LSIG + 255) / 256, 256>>>((float*)d_out);
}